// round 14
// baseline (speedup 1.0000x reference)
#include <cuda_runtime.h>
#include <cuda_bf16.h>
#include <math.h>
#include <stdint.h>

#define BQ   1024
#define NT   50000
#define NTP  50048
#define NL   8
#define KNN  75
#define HD   128
#define NC   10000
#define NTILES 391          // NTP/128

typedef unsigned long long u64;

// ---------------- device scratch ----------------
__device__ float g_h1[BQ * HD];
__device__ float g_h2[BQ * HD];
__device__ float g_h3[BQ * HD];
__device__ float g_q4[BQ * NL];
__device__ float g_t3[(size_t)NT * HD];
__device__ float g_t4[(size_t)NT * NL];
__device__ float g_d2[(size_t)BQ * NT];
__device__ float g_min[(size_t)BQ * NTILES];
__device__ float g_qn[BQ];
__device__ float g_tn[NT];
__device__ float g_tot[BQ * NL];
__device__ __nv_bfloat16 g_qhi[(size_t)BQ * 128];
__device__ __nv_bfloat16 g_qlo[(size_t)BQ * 128];
__device__ __nv_bfloat16 g_thi[(size_t)NTP * 128];    // bank A
__device__ __nv_bfloat16 g_tlo[(size_t)NTP * 128];
__device__ __nv_bfloat16 g_thi2[(size_t)NTP * 128];   // bank B
__device__ __nv_bfloat16 g_tlo2[(size_t)NTP * 128];
__device__ __nv_bfloat16 g_w1th[128 * 128], g_w1tl[128 * 128];
__device__ __nv_bfloat16 g_w2th[128 * 128], g_w2tl[128 * 128];
__device__ __nv_bfloat16 g_w3th[128 * 128], g_w3tl[128 * 128];

// ---------------------------------------------------------------------------
__device__ __forceinline__ void mma_bf16(float* d, const uint32_t* a, const uint32_t* b)
{
    asm volatile(
        "mma.sync.aligned.m16n8k16.row.col.f32.bf16.bf16.f32 "
        "{%0,%1,%2,%3}, {%4,%5,%6,%7}, {%8,%9}, {%0,%1,%2,%3};"
        : "+f"(d[0]), "+f"(d[1]), "+f"(d[2]), "+f"(d[3])
        : "r"(a[0]), "r"(a[1]), "r"(a[2]), "r"(a[3]), "r"(b[0]), "r"(b[1]));
}

#define SLICE_ELEMS (128 * 24)

__device__ __forceinline__ void slice_load_async(
    const __nv_bfloat16* __restrict__ Gp, __nv_bfloat16* Ss,
    int row0, int k0, int lr, int lh)
{
    uint32_t sa = (uint32_t)__cvta_generic_to_shared(Ss + lr * 24 + lh * 8);
    const void* ga = Gp + (size_t)(row0 + lr) * 128 + k0 + lh * 8;
    asm volatile("cp.async.cg.shared.global [%0], [%1], 16;\n" :: "r"(sa), "l"(ga));
}

// ---------------------------------------------------------------------------
// Layer-4 exact d2 helpers: fixed-order __fmaf_rn chains so min4_kernel and
// select4_kernel produce bit-identical values for the same (query, row).
// ---------------------------------------------------------------------------
__device__ __forceinline__ float l4_qq(const float* q)
{
    float s = __fmul_rn(q[0], q[0]);
    s = __fmaf_rn(q[1], q[1], s); s = __fmaf_rn(q[2], q[2], s);
    s = __fmaf_rn(q[3], q[3], s); s = __fmaf_rn(q[4], q[4], s);
    s = __fmaf_rn(q[5], q[5], s); s = __fmaf_rn(q[6], q[6], s);
    s = __fmaf_rn(q[7], q[7], s);
    return s;
}
__device__ __forceinline__ float l4_d2f(const float* __restrict__ tr,
                                        const float* q, float qq)
{
    float tt = __fmul_rn(tr[0], tr[0]);
    tt = __fmaf_rn(tr[1], tr[1], tt); tt = __fmaf_rn(tr[2], tr[2], tt);
    tt = __fmaf_rn(tr[3], tr[3], tt); tt = __fmaf_rn(tr[4], tr[4], tt);
    tt = __fmaf_rn(tr[5], tr[5], tt); tt = __fmaf_rn(tr[6], tr[6], tt);
    tt = __fmaf_rn(tr[7], tr[7], tt);
    float dt = __fmul_rn(q[0], tr[0]);
    dt = __fmaf_rn(q[1], tr[1], dt); dt = __fmaf_rn(q[2], tr[2], dt);
    dt = __fmaf_rn(q[3], tr[3], dt); dt = __fmaf_rn(q[4], tr[4], dt);
    dt = __fmaf_rn(q[5], tr[5], dt); dt = __fmaf_rn(q[6], tr[6], dt);
    dt = __fmaf_rn(q[7], tr[7], dt);
    return fmaxf(__fmaf_rn(-2.f, dt, __fadd_rn(qq, tt)), 0.f);
}

// ---------------------------------------------------------------------------
__global__ void __launch_bounds__(256)
conv_norm_kernel(const float* __restrict__ A, __nv_bfloat16* __restrict__ hi,
                 __nv_bfloat16* __restrict__ lo, float* __restrict__ nrm,
                 int Mreal, int D)
{
    int warp = threadIdx.x >> 5, lane = threadIdx.x & 31;
    int row = blockIdx.x * 8 + warp;
    int base = lane * 4;

    float ss = 0.f;
    __nv_bfloat16 hb[4], lb[4];
#pragma unroll
    for (int j = 0; j < 4; j++) {
        int col = base + j;
        float v = (row < Mreal && col < D) ? A[(size_t)row * D + col] : 0.f;
        ss += v * v;
        hb[j] = __float2bfloat16_rn(v);
        lb[j] = __float2bfloat16_rn(v - __bfloat162float(hb[j]));
    }
    __nv_bfloat162 h01, h23, l01, l23;
    h01.x = hb[0]; h01.y = hb[1]; h23.x = hb[2]; h23.y = hb[3];
    l01.x = lb[0]; l01.y = lb[1]; l23.x = lb[2]; l23.y = lb[3];
    *(__nv_bfloat162*)&hi[(size_t)row * 128 + base]     = h01;
    *(__nv_bfloat162*)&hi[(size_t)row * 128 + base + 2] = h23;
    *(__nv_bfloat162*)&lo[(size_t)row * 128 + base]     = l01;
    *(__nv_bfloat162*)&lo[(size_t)row * 128 + base + 2] = l23;

#pragma unroll
    for (int off = 16; off > 0; off >>= 1) ss += __shfl_down_sync(0xFFFFFFFFu, ss, off);
    if (lane == 0 && row < Mreal) nrm[row] = ss;
}

// ---------------------------------------------------------------------------
__global__ void __launch_bounds__(256)
wt_convert_kernel(const float* __restrict__ W1, const float* __restrict__ W2,
                  const float* __restrict__ W3)
{
    int idx = blockIdx.x * 256 + threadIdx.x;
    if (idx >= 3 * 128 * 128) return;
    int which = idx >> 14;
    int e = idx & 16383;
    int n = e & 127, k = e >> 7;
    const float* W = (which == 0) ? W1 : (which == 1) ? W2 : W3;
    int K = (which == 0) ? 83 : 128;
    float v = (k < K) ? W[(size_t)k * 128 + n] : 0.f;
    __nv_bfloat16 h = __float2bfloat16_rn(v);
    __nv_bfloat16 l = __float2bfloat16_rn(v - __bfloat162float(h));
    __nv_bfloat16* dh = (which == 0) ? g_w1th : (which == 1) ? g_w2th : g_w3th;
    __nv_bfloat16* dl = (which == 0) ? g_w1tl : (which == 1) ? g_w2tl : g_w3tl;
    dh[e] = h;
    dl[e] = l;
}

// ---------------------------------------------------------------------------
// bf16x3 GEMM mainloop (128-row tiles, 2-buffer) - used by mma_linear_kernel.
// 3-pass MMA schedule (hh, lh, hl) -> per-acc order fixed, bit-identical.
// ---------------------------------------------------------------------------
__device__ __forceinline__ void gemm3_mainloop(
    const __nv_bfloat16* Ahi, const __nv_bfloat16* Alo,
    const __nv_bfloat16* Bhi, const __nv_bfloat16* Blo,
    __nv_bfloat16* smem, int m0, int n0, int nCh,
    int wm, int wn, int fr, int fc, int lr, int lh,
    float acc[2][8][4])
{
    __nv_bfloat16* AhiS[2] = {smem,                   smem + 4 * SLICE_ELEMS};
    __nv_bfloat16* AloS[2] = {smem + 1 * SLICE_ELEMS, smem + 5 * SLICE_ELEMS};
    __nv_bfloat16* BhiS[2] = {smem + 2 * SLICE_ELEMS, smem + 6 * SLICE_ELEMS};
    __nv_bfloat16* BloS[2] = {smem + 3 * SLICE_ELEMS, smem + 7 * SLICE_ELEMS};

    slice_load_async(Ahi, AhiS[0], m0, 0, lr, lh);
    slice_load_async(Alo, AloS[0], m0, 0, lr, lh);
    slice_load_async(Bhi, BhiS[0], n0, 0, lr, lh);
    slice_load_async(Blo, BloS[0], n0, 0, lr, lh);
    asm volatile("cp.async.commit_group;\n" ::: "memory");

    for (int c = 0; c < nCh; c++) {
        int buf = c & 1;
        if (c + 1 < nCh) {
            int k0 = (c + 1) * 16;
            slice_load_async(Ahi, AhiS[buf ^ 1], m0, k0, lr, lh);
            slice_load_async(Alo, AloS[buf ^ 1], m0, k0, lr, lh);
            slice_load_async(Bhi, BhiS[buf ^ 1], n0, k0, lr, lh);
            slice_load_async(Blo, BloS[buf ^ 1], n0, k0, lr, lh);
            asm volatile("cp.async.commit_group;\n" ::: "memory");
            asm volatile("cp.async.wait_group 1;" ::: "memory");
        } else {
            asm volatile("cp.async.wait_group 0;" ::: "memory");
        }
        __syncthreads();

        const __nv_bfloat16* Ah = AhiS[buf];
        const __nv_bfloat16* Al = AloS[buf];
        const __nv_bfloat16* Bh = BhiS[buf];
        const __nv_bfloat16* Bl = BloS[buf];

        uint32_t ah[2][4];
#pragma unroll
        for (int mt = 0; mt < 2; mt++) {
            int bm = wm + mt * 16;
            ah[mt][0] = *(const uint32_t*)&Ah[(bm + fr) * 24 + fc];
            ah[mt][1] = *(const uint32_t*)&Ah[(bm + fr + 8) * 24 + fc];
            ah[mt][2] = *(const uint32_t*)&Ah[(bm + fr) * 24 + fc + 8];
            ah[mt][3] = *(const uint32_t*)&Ah[(bm + fr + 8) * 24 + fc + 8];
        }
        uint32_t bh8[8][2];
#pragma unroll
        for (int nt = 0; nt < 8; nt++) {
            int nb = wn + nt * 8;
            bh8[nt][0] = *(const uint32_t*)&Bh[(nb + fr) * 24 + fc];
            bh8[nt][1] = *(const uint32_t*)&Bh[(nb + fr) * 24 + fc + 8];
        }
#pragma unroll
        for (int nt = 0; nt < 8; nt++) {
            mma_bf16(acc[0][nt], ah[0], bh8[nt]);
            mma_bf16(acc[1][nt], ah[1], bh8[nt]);
        }
        uint32_t al[2][4];
#pragma unroll
        for (int mt = 0; mt < 2; mt++) {
            int bm = wm + mt * 16;
            al[mt][0] = *(const uint32_t*)&Al[(bm + fr) * 24 + fc];
            al[mt][1] = *(const uint32_t*)&Al[(bm + fr + 8) * 24 + fc];
            al[mt][2] = *(const uint32_t*)&Al[(bm + fr) * 24 + fc + 8];
            al[mt][3] = *(const uint32_t*)&Al[(bm + fr + 8) * 24 + fc + 8];
        }
#pragma unroll
        for (int nt = 0; nt < 8; nt++) {
            mma_bf16(acc[0][nt], al[0], bh8[nt]);
            mma_bf16(acc[1][nt], al[1], bh8[nt]);
        }
#pragma unroll
        for (int nt = 0; nt < 8; nt++) {
            int nb = wn + nt * 8;
            uint32_t bl[2];
            bl[0] = *(const uint32_t*)&Bl[(nb + fr) * 24 + fc];
            bl[1] = *(const uint32_t*)&Bl[(nb + fr) * 24 + fc + 8];
            mma_bf16(acc[0][nt], ah[0], bl);
            mma_bf16(acc[1][nt], ah[1], bl);
        }
        __syncthreads();
    }
}

// ---------------------------------------------------------------------------
// 256x128 distance GEMM, 512 threads, 3-stage pipeline, 1 sync per chunk.
// ---------------------------------------------------------------------------
#define ASL (256 * 24)
#define BSL (128 * 24)
#define STAGE_ELEMS (2 * ASL + 2 * BSL)
#define MD_SMEM (3 * STAGE_ELEMS * 2)

__global__ void __launch_bounds__(512, 1)
mma_dist_kernel(const __nv_bfloat16* __restrict__ Qhi, const __nv_bfloat16* __restrict__ Qlo,
                const __nv_bfloat16* __restrict__ Thi, const __nv_bfloat16* __restrict__ Tlo,
                const float* __restrict__ qn, const float* __restrict__ tn,
                float* __restrict__ out, float* __restrict__ gmin, int nCh)
{
    extern __shared__ __align__(16) __nv_bfloat16 dsm[];
    __shared__ float sMin[256][2];
    const int tid = threadIdx.x;
    const int wid = tid >> 5, lane = tid & 31;
    const int n0 = blockIdx.x * 128;
    const int m0 = blockIdx.y * 256;
    const int wm = (wid & 7) * 32;
    const int wn = (wid >> 3) * 64;
    const int fr = lane >> 2, fc = (lane & 3) * 2;
    const int ar = tid >> 1, ah2 = tid & 1;
    const int br = (tid & 255) >> 1, bh2 = tid & 1;

    float acc[2][8][4];
#pragma unroll
    for (int mt = 0; mt < 2; mt++)
#pragma unroll
        for (int nt = 0; nt < 8; nt++)
#pragma unroll
            for (int j = 0; j < 4; j++) acc[mt][nt][j] = 0.f;

#define LOAD_STAGE(s, k0) do {                                                  \
        __nv_bfloat16* sb_ = dsm + (s) * STAGE_ELEMS;                           \
        slice_load_async(Qhi, sb_,            m0, (k0), ar, ah2);               \
        slice_load_async(Qlo, sb_ + ASL,      m0, (k0), ar, ah2);               \
        if (tid < 256) slice_load_async(Thi, sb_ + 2 * ASL,      n0, (k0), br, bh2); \
        else           slice_load_async(Tlo, sb_ + 2 * ASL + BSL, n0, (k0), br, bh2); \
        asm volatile("cp.async.commit_group;\n" ::: "memory");                  \
    } while (0)

    LOAD_STAGE(0, 0);
    if (nCh > 1) LOAD_STAGE(1, 16);

    for (int c = 0; c < nCh; c++) {
        if (c + 1 < nCh) asm volatile("cp.async.wait_group 1;" ::: "memory");
        else             asm volatile("cp.async.wait_group 0;" ::: "memory");
        __syncthreads();
        if (c + 2 < nCh) LOAD_STAGE((c + 2) % 3, (c + 2) * 16);

        const __nv_bfloat16* sb = dsm + (c % 3) * STAGE_ELEMS;
        const __nv_bfloat16* Ah = sb;
        const __nv_bfloat16* Al = sb + ASL;
        const __nv_bfloat16* Bh = sb + 2 * ASL;
        const __nv_bfloat16* Bl = sb + 2 * ASL + BSL;

        uint32_t ah[2][4];
#pragma unroll
        for (int mt = 0; mt < 2; mt++) {
            int bm = wm + mt * 16;
            ah[mt][0] = *(const uint32_t*)&Ah[(bm + fr) * 24 + fc];
            ah[mt][1] = *(const uint32_t*)&Ah[(bm + fr + 8) * 24 + fc];
            ah[mt][2] = *(const uint32_t*)&Ah[(bm + fr) * 24 + fc + 8];
            ah[mt][3] = *(const uint32_t*)&Ah[(bm + fr + 8) * 24 + fc + 8];
        }
        uint32_t bh8[8][2];
#pragma unroll
        for (int nt = 0; nt < 8; nt++) {
            int nb = wn + nt * 8;
            bh8[nt][0] = *(const uint32_t*)&Bh[(nb + fr) * 24 + fc];
            bh8[nt][1] = *(const uint32_t*)&Bh[(nb + fr) * 24 + fc + 8];
        }
#pragma unroll
        for (int nt = 0; nt < 8; nt++) {
            mma_bf16(acc[0][nt], ah[0], bh8[nt]);
            mma_bf16(acc[1][nt], ah[1], bh8[nt]);
        }
        uint32_t al[2][4];
#pragma unroll
        for (int mt = 0; mt < 2; mt++) {
            int bm = wm + mt * 16;
            al[mt][0] = *(const uint32_t*)&Al[(bm + fr) * 24 + fc];
            al[mt][1] = *(const uint32_t*)&Al[(bm + fr + 8) * 24 + fc];
            al[mt][2] = *(const uint32_t*)&Al[(bm + fr) * 24 + fc + 8];
            al[mt][3] = *(const uint32_t*)&Al[(bm + fr + 8) * 24 + fc + 8];
        }
#pragma unroll
        for (int nt = 0; nt < 8; nt++) {
            mma_bf16(acc[0][nt], al[0], bh8[nt]);
            mma_bf16(acc[1][nt], al[1], bh8[nt]);
        }
#pragma unroll
        for (int nt = 0; nt < 8; nt++) {
            int nb = wn + nt * 8;
            uint32_t bl[2];
            bl[0] = *(const uint32_t*)&Bl[(nb + fr) * 24 + fc];
            bl[1] = *(const uint32_t*)&Bl[(nb + fr) * 24 + fc + 8];
            mma_bf16(acc[0][nt], ah[0], bl);
            mma_bf16(acc[1][nt], ah[1], bl);
        }
    }
#undef LOAD_STAGE

    const float FINF = __int_as_float(0x7F800000);
    float rmin[2][2] = {{FINF, FINF}, {FINF, FINF}};
#pragma unroll
    for (int mt = 0; mt < 2; mt++) {
        int mrow = m0 + wm + mt * 16 + fr;
        float q0 = qn[mrow], q1 = qn[mrow + 8];
#pragma unroll
        for (int nt = 0; nt < 8; nt++) {
            int n = n0 + wn + nt * 8 + fc;
            if (n < NT) {
                float t0 = tn[n], t1 = tn[n + 1];
                float2 o;
                o.x = fmaxf(q0 + t0 - 2.f * acc[mt][nt][0], 0.f);
                o.y = fmaxf(q0 + t1 - 2.f * acc[mt][nt][1], 0.f);
                *(float2*)&out[(size_t)mrow * NT + n] = o;
                rmin[mt][0] = fminf(rmin[mt][0], fminf(o.x, o.y));
                o.x = fmaxf(q1 + t0 - 2.f * acc[mt][nt][2], 0.f);
                o.y = fmaxf(q1 + t1 - 2.f * acc[mt][nt][3], 0.f);
                *(float2*)&out[(size_t)(mrow + 8) * NT + n] = o;
                rmin[mt][1] = fminf(rmin[mt][1], fminf(o.x, o.y));
            }
        }
    }
    __syncthreads();
#pragma unroll
    for (int mt = 0; mt < 2; mt++)
#pragma unroll
        for (int rr = 0; rr < 2; rr++) {
            float m = rmin[mt][rr];
            m = fminf(m, __shfl_xor_sync(0xFFFFFFFFu, m, 1));
            m = fminf(m, __shfl_xor_sync(0xFFFFFFFFu, m, 2));
            if ((lane & 3) == 0)
                sMin[wm + mt * 16 + rr * 8 + fr][wn >> 6] = m;
        }
    __syncthreads();
    if (tid < 256)
        gmin[(size_t)(m0 + tid) * NTILES + blockIdx.x] =
            fminf(sMin[tid][0], sMin[tid][1]);
}

// ---------------------------------------------------------------------------
__global__ void __launch_bounds__(256, 2)
mma_linear_kernel(const __nv_bfloat16* __restrict__ Ahi, const __nv_bfloat16* __restrict__ Alo,
                  const __nv_bfloat16* __restrict__ Wth, const __nv_bfloat16* __restrict__ Wtl,
                  const float* __restrict__ bias,
                  __nv_bfloat16* __restrict__ Ohi, __nv_bfloat16* __restrict__ Olo,
                  float* __restrict__ nrm, float* __restrict__ Ofp, int nCh)
{
    __shared__ __align__(16) __nv_bfloat16 smem[8 * SLICE_ELEMS];
    __shared__ float snorm[128];
    __shared__ float sbias[128];
    const int tid = threadIdx.x;
    const int wid = tid >> 5, lane = tid & 31;
    const int m0 = blockIdx.x * 128;
    const int wm = (wid & 3) * 32;
    const int wn = (wid >> 2) * 64;
    const int lr = tid >> 1, lh = tid & 1;
    const int fr = lane >> 2, fc = (lane & 3) * 2;

    if (tid < 128) { sbias[tid] = bias[tid]; snorm[tid] = 0.f; }

    float acc[2][8][4];
#pragma unroll
    for (int mt = 0; mt < 2; mt++)
#pragma unroll
        for (int nt = 0; nt < 8; nt++)
#pragma unroll
            for (int j = 0; j < 4; j++) acc[mt][nt][j] = 0.f;

    gemm3_mainloop(Ahi, Alo, Wth, Wtl, smem, m0, 0, nCh,
                   wm, wn, fr, fc, lr, lh, acc);

#pragma unroll
    for (int mt = 0; mt < 2; mt++) {
        int r0 = wm + mt * 16 + fr;
        int r1 = r0 + 8;
        size_t g0 = (size_t)(m0 + r0) * 128;
        size_t g1 = (size_t)(m0 + r1) * 128;
        float ns0 = 0.f, ns1 = 0.f;
#pragma unroll
        for (int nt = 0; nt < 8; nt++) {
            int n = wn + nt * 8 + fc;
            float b0 = sbias[n], b1 = sbias[n + 1];
            float v00 = fmaxf(acc[mt][nt][0] + b0, 0.f);
            float v01 = fmaxf(acc[mt][nt][1] + b1, 0.f);
            float v10 = fmaxf(acc[mt][nt][2] + b0, 0.f);
            float v11 = fmaxf(acc[mt][nt][3] + b1, 0.f);
            ns0 += v00 * v00 + v01 * v01;
            ns1 += v10 * v10 + v11 * v11;
            __nv_bfloat162 h, l;
            h.x = __float2bfloat16_rn(v00);
            h.y = __float2bfloat16_rn(v01);
            l.x = __float2bfloat16_rn(v00 - __bfloat162float(h.x));
            l.y = __float2bfloat16_rn(v01 - __bfloat162float(h.y));
            *(__nv_bfloat162*)&Ohi[g0 + n] = h;
            *(__nv_bfloat162*)&Olo[g0 + n] = l;
            h.x = __float2bfloat16_rn(v10);
            h.y = __float2bfloat16_rn(v11);
            l.x = __float2bfloat16_rn(v10 - __bfloat162float(h.x));
            l.y = __float2bfloat16_rn(v11 - __bfloat162float(h.y));
            *(__nv_bfloat162*)&Ohi[g1 + n] = h;
            *(__nv_bfloat162*)&Olo[g1 + n] = l;
            if (Ofp) {
                *(float2*)&Ofp[g0 + n] = make_float2(v00, v01);
                *(float2*)&Ofp[g1 + n] = make_float2(v10, v11);
            }
        }
        atomicAdd(&snorm[r0], ns0);
        atomicAdd(&snorm[r1], ns1);
    }
    __syncthreads();
    if (tid < 128 && m0 + tid < NT) nrm[m0 + tid] = snorm[tid];
}

// ---------------------------------------------------------------------------
__global__ void __launch_bounds__(256)
linear_relu_kernel(const float* __restrict__ A, const float* __restrict__ W,
                   const float* __restrict__ bias, float* __restrict__ out,
                   int M, int K)
{
    __shared__ __align__(16) float As[16 * 68];
    __shared__ __align__(16) float Bs[16 * 136];
    const int tx = threadIdx.x, ty = threadIdx.y;
    const int tid = ty * 16 + tx;
    const int m0 = blockIdx.x * 64;

    float acc[4][8];
#pragma unroll
    for (int r = 0; r < 4; r++)
#pragma unroll
        for (int c = 0; c < 8; c++) acc[r][c] = 0.f;

    const int nChunks = (K + 15) / 16;
    for (int ch = 0; ch < nChunks; ch++) {
        const int k0 = ch * 16;
#pragma unroll
        for (int i = 0; i < 4; i++) {
            int e = tid + i * 256;
            int k = e & 15, m = e >> 4;
            float v = 0.f;
            if (k0 + k < K && m0 + m < M) v = A[(size_t)(m0 + m) * K + k0 + k];
            As[k * 68 + m] = v;
        }
#pragma unroll
        for (int i = 0; i < 8; i++) {
            int e = tid + i * 256;
            int h = e & 127, k = e >> 7;
            float v = 0.f;
            if (k0 + k < K) v = W[(size_t)(k0 + k) * HD + h];
            Bs[k * 136 + h] = v;
        }
        __syncthreads();
#pragma unroll
        for (int k = 0; k < 16; k++) {
            float4 a  = *(const float4*)&As[k * 68 + ty * 4];
            float4 b0 = *(const float4*)&Bs[k * 136 + tx * 4];
            float4 b1 = *(const float4*)&Bs[k * 136 + 64 + tx * 4];
            float av[4] = {a.x, a.y, a.z, a.w};
            float bv[8] = {b0.x, b0.y, b0.z, b0.w, b1.x, b1.y, b1.z, b1.w};
#pragma unroll
            for (int r = 0; r < 4; r++)
#pragma unroll
                for (int c = 0; c < 8; c++) acc[r][c] += av[r] * bv[c];
        }
        __syncthreads();
    }
#pragma unroll
    for (int r = 0; r < 4; r++) {
        int m = m0 + ty * 4 + r;
        if (m >= M) continue;
#pragma unroll
        for (int half = 0; half < 2; half++) {
#pragma unroll
            for (int c = 0; c < 4; c++) {
                int h = half * 64 + tx * 4 + c;
                float v = acc[r][half * 4 + c] + bias[h];
                out[(size_t)m * HD + h] = fmaxf(v, 0.f);
            }
        }
    }
}

// ---------------------------------------------------------------------------
__global__ void __launch_bounds__(256)
linear_softmax_kernel(const float* __restrict__ A, const float* __restrict__ W,
                      const float* __restrict__ bias, float* __restrict__ out, int M)
{
    __shared__ float Ws[HD * NL];
    __shared__ float bs[NL];
    int tid = threadIdx.x;
    for (int i = tid; i < HD * NL; i += 256) Ws[i] = W[i];
    if (tid < NL) bs[tid] = bias[tid];
    __syncthreads();

    int warp = tid >> 5, lane = tid & 31;
    int m = blockIdx.x * 8 + warp;
    if (m >= M) return;

    float acc[NL];
#pragma unroll
    for (int h = 0; h < NL; h++) acc[h] = 0.f;
    for (int k = lane; k < HD; k += 32) {
        float x = A[(size_t)m * HD + k];
#pragma unroll
        for (int h = 0; h < NL; h++) acc[h] += x * Ws[k * NL + h];
    }
#pragma unroll
    for (int h = 0; h < NL; h++)
#pragma unroll
        for (int off = 16; off > 0; off >>= 1)
            acc[h] += __shfl_down_sync(0xFFFFFFFFu, acc[h], off);

    if (lane == 0) {
        float v[NL], mx = -1e30f;
#pragma unroll
        for (int h = 0; h < NL; h++) { v[h] = acc[h] + bs[h]; mx = fmaxf(mx, v[h]); }
        float s = 0.f;
#pragma unroll
        for (int h = 0; h < NL; h++) { v[h] = expf(v[h] - mx); s += v[h]; }
        float inv = 1.0f / s;
#pragma unroll
        for (int h = 0; h < NL; h++) out[(size_t)m * NL + h] = v[h] * inv;
    }
}

// ---------------------------------------------------------------------------
// Layer-4 tile minima WITHOUT materializing d2.  Block = (tile, 128 queries).
// ---------------------------------------------------------------------------
__global__ void __launch_bounds__(256)
min4_kernel(const float* __restrict__ q4, const float* __restrict__ t4,
            float* __restrict__ gmin)
{
    __shared__ float st[128 * 8];
    __shared__ float sq[128 * 8];
    const int t = blockIdx.x;
    const int q0 = blockIdx.y * 128;
    const int tid = threadIdx.x;
    const float FINF = __int_as_float(0x7F800000);

    for (int i = tid; i < 1024; i += 256) {
        int row = t * 128 + (i >> 3);
        st[i] = (row < NT) ? t4[(size_t)row * 8 + (i & 7)] : 0.f;
        sq[i] = q4[(size_t)(q0 + (i >> 3)) * 8 + (i & 7)];
    }
    __syncthreads();

    const int qi = tid >> 1, half = tid & 1;
    float q[8];
#pragma unroll
    for (int j = 0; j < 8; j++) q[j] = sq[qi * 8 + j];
    const float qq = l4_qq(q);

    float m = FINF;
    const int rbase = half * 64;
    for (int r = 0; r < 64; r++) {
        int row = t * 128 + rbase + r;
        if (row < NT)
            m = fminf(m, l4_d2f(&st[(rbase + r) * 8], q, qq));
    }
    m = fminf(m, __shfl_xor_sync(0xFFFFFFFFu, m, 1));
    if (half == 0)
        gmin[(size_t)(q0 + qi) * NTILES + t] = m;
}

// ---------------------------------------------------------------------------
__device__ __forceinline__ void find_kth(const unsigned* hist, int NB, unsigned kth,
                                         int tid, unsigned* s_bin, unsigned* s_kthr)
{
    if (tid < 32) {
        unsigned running = 0;
        for (int base = 0; base < NB; base += 32) {
            unsigned v = hist[base + tid];
            unsigned sc = v;
#pragma unroll
            for (int off = 1; off < 32; off <<= 1) {
                unsigned t = __shfl_up_sync(0xFFFFFFFFu, sc, off);
                if (tid >= off) sc += t;
            }
            unsigned tot = __shfl_sync(0xFFFFFFFFu, sc, 31);
            if (running + tot >= kth) {
                unsigned mask = __ballot_sync(0xFFFFFFFFu, running + sc >= kth);
                int l = __ffs(mask) - 1;
                if (tid == l) { *s_bin = (unsigned)(base + l); *s_kthr = kth - running - (sc - v); }
                break;
            }
            running += tot;
        }
    }
}

// ---------------------------------------------------------------------------
// Exact top-K select (layers 0-3): tile-min threshold + tile-subset d2 scan.
// ---------------------------------------------------------------------------
#define SEL_THREADS 512
#define SEL_CAP 2048
#define OFF_CAND  16384
#define OFF_SEL   (OFF_CAND + SEL_CAP * 8)
#define OFF_TIES  (OFF_SEL + 1024)
#define OFF_TLAB  (OFF_TIES + 1024)
#define OFF_MINS  (OFF_TLAB + 512)
#define OFF_TLIST (OFF_MINS + 392 * 4)
#define SEL_SMEM  (OFF_TLIST + 392 * 4)

__global__ void __launch_bounds__(SEL_THREADS)
select_kernel(const float* __restrict__ d2mat, const float* __restrict__ gmin,
              const int* __restrict__ labels, float* __restrict__ total, int init)
{
    extern __shared__ __align__(16) char sms[];
    unsigned* hist = (unsigned*)sms;
    u64* cand  = (u64*)(sms + OFF_CAND);
    u64* sel   = (u64*)(sms + OFF_SEL);
    u64* ties  = (u64*)(sms + OFF_TIES);
    int* tlab  = (int*)(sms + OFF_TLAB);
    float* mins = (float*)(sms + OFF_MINS);
    int* tlist = (int*)(sms + OFF_TLIST);

    __shared__ unsigned s_M75, s_bin, s_kthr, s_candcnt, s_selcnt, s_tiecnt, s_ntiles;
    __shared__ float s_w[80];
    __shared__ int s_lab[80];

    const int b = blockIdx.x, tid = threadIdx.x, lane = tid & 31;
    const uint4* usrc = (const uint4*)(d2mat + (size_t)b * NT);
    const int NH = NT / 4;

    for (int i = tid; i < NTILES; i += SEL_THREADS)
        mins[i] = gmin[(size_t)b * NTILES + i];
    if (tid == 0) { s_candcnt = 0; s_selcnt = 0; s_tiecnt = 0; s_ntiles = 0; }
    __syncthreads();

    if (tid < NTILES) {
        unsigned key = __float_as_uint(mins[tid]);
        int c = 0;
        for (int j = 0; j < NTILES; j++) {
            unsigned kj = __float_as_uint(mins[j]);
            c += (kj < key) || (kj == key && j < tid);
        }
        if (c == KNN - 1) s_M75 = key;
    }
    __syncthreads();
    const unsigned Mkey = s_M75;

    if (tid < NTILES) {
        if (__float_as_uint(mins[tid]) <= Mkey) {
            unsigned s = atomicAdd(&s_ntiles, 1u);
            tlist[s] = tid;
        }
    }
    __syncthreads();
    const int ntl = (int)s_ntiles;

    for (int w = tid; w < ntl * 32; w += SEL_THREADS) {
        int t = tlist[w >> 5];
        int i4 = t * 32 + (w & 31);
        if (i4 < NH) {
            uint4 a = usrc[i4];
            unsigned k[4] = {a.x, a.y, a.z, a.w};
#pragma unroll
            for (int j = 0; j < 4; j++) {
                if (k[j] <= Mkey) {
                    unsigned s = atomicAdd(&s_candcnt, 1u);
                    if (s < SEL_CAP) cand[s] = ((u64)k[j] << 32) | (unsigned)(i4 * 4 + j);
                }
            }
        }
    }
    __syncthreads();

    unsigned Tkey;
    const unsigned candTotal = s_candcnt;

    if (candTotal <= SEL_CAP) {
        const int cc = (int)candTotal;
        for (int i = tid; i < 4096; i += SEL_THREADS) hist[i] = 0;
        __syncthreads();
        for (int i = tid; i < cc; i += SEL_THREADS)
            atomicAdd(&hist[(unsigned)(cand[i] >> 52)], 1u);
        __syncthreads();
        find_kth(hist, 4096, KNN, tid, &s_bin, &s_kthr);
        __syncthreads();
        const unsigned pfx = s_bin;
        const unsigned k1v = s_kthr;
        for (int i = tid; i < 4096; i += SEL_THREADS) hist[i] = 0;
        __syncthreads();
        for (int i = tid; i < cc; i += SEL_THREADS) {
            unsigned key = (unsigned)(cand[i] >> 32);
            if ((key >> 20) == pfx) atomicAdd(&hist[(key >> 8) & 0xFFFu], 1u);
        }
        __syncthreads();
        find_kth(hist, 4096, k1v, tid, &s_bin, &s_kthr);
        __syncthreads();
        const unsigned pfx20 = (pfx << 12) | s_bin;
        const unsigned k2v = s_kthr;
        for (int i = tid; i < 256; i += SEL_THREADS) hist[i] = 0;
        __syncthreads();
        for (int i = tid; i < cc; i += SEL_THREADS) {
            unsigned key = (unsigned)(cand[i] >> 32);
            if ((key >> 8) == pfx20) atomicAdd(&hist[key & 0xFFu], 1u);
        }
        __syncthreads();
        find_kth(hist, 256, k2v, tid, &s_bin, &s_kthr);
        __syncthreads();
        Tkey = (pfx20 << 8) | s_bin;
        for (int i = tid; i < cc; i += SEL_THREADS) {
            u64 cv = cand[i];
            unsigned key = (unsigned)(cv >> 32);
            if (key < Tkey) {
                unsigned s = atomicAdd(&s_selcnt, 1u);
                if (s < 128) sel[s] = cv;
            } else if (key == Tkey) {
                unsigned s = atomicAdd(&s_tiecnt, 1u);
                if (s < 128) ties[s] = cv;
            }
        }
        __syncthreads();
    } else {
        for (int i = tid; i < 4096; i += SEL_THREADS) hist[i] = 0;
        __syncthreads();
        for (int w = tid; w < ntl * 32; w += SEL_THREADS) {
            int t = tlist[w >> 5];
            int i4 = t * 32 + (w & 31);
            uint4 a = (i4 < NH) ? usrc[i4] : make_uint4(~0u, ~0u, ~0u, ~0u);
            unsigned k[4] = {a.x, a.y, a.z, a.w};
#pragma unroll
            for (int j = 0; j < 4; j++) {
                unsigned bin = (k[j] <= Mkey) ? (k[j] >> 20) : 0xFFFFFFFFu;
                unsigned grp = __match_any_sync(0xFFFFFFFFu, bin);
                if (bin != 0xFFFFFFFFu && lane == __ffs(grp) - 1)
                    atomicAdd(&hist[bin], (unsigned)__popc(grp));
            }
        }
        __syncthreads();
        find_kth(hist, 4096, KNN, tid, &s_bin, &s_kthr);
        __syncthreads();
        const unsigned pfx = s_bin;
        const unsigned k1v = s_kthr;

        for (int i = tid; i < 4096; i += SEL_THREADS) hist[i] = 0;
        __syncthreads();
        for (int w = tid; w < ntl * 32; w += SEL_THREADS) {
            int t = tlist[w >> 5];
            int i4 = t * 32 + (w & 31);
            uint4 a = (i4 < NH) ? usrc[i4] : make_uint4(~0u, ~0u, ~0u, ~0u);
            unsigned k[4] = {a.x, a.y, a.z, a.w};
#pragma unroll
            for (int j = 0; j < 4; j++) {
                unsigned bin = (k[j] <= Mkey && (k[j] >> 20) == pfx)
                               ? ((k[j] >> 8) & 0xFFFu) : 0xFFFFFFFFu;
                unsigned grp = __match_any_sync(0xFFFFFFFFu, bin);
                if (bin != 0xFFFFFFFFu && lane == __ffs(grp) - 1)
                    atomicAdd(&hist[bin], (unsigned)__popc(grp));
            }
        }
        __syncthreads();
        find_kth(hist, 4096, k1v, tid, &s_bin, &s_kthr);
        __syncthreads();
        const unsigned pfx20 = (pfx << 12) | s_bin;
        const unsigned k2v = s_kthr;

        for (int i = tid; i < 256; i += SEL_THREADS) hist[i] = 0;
        __syncthreads();
        for (int w = tid; w < ntl * 32; w += SEL_THREADS) {
            int t = tlist[w >> 5];
            int i4 = t * 32 + (w & 31);
            uint4 a = (i4 < NH) ? usrc[i4] : make_uint4(~0u, ~0u, ~0u, ~0u);
            unsigned k[4] = {a.x, a.y, a.z, a.w};
#pragma unroll
            for (int j = 0; j < 4; j++) {
                unsigned bin = (k[j] <= Mkey && (k[j] >> 8) == pfx20)
                               ? (k[j] & 0xFFu) : 0xFFFFFFFFu;
                unsigned grp = __match_any_sync(0xFFFFFFFFu, bin);
                if (bin != 0xFFFFFFFFu && lane == __ffs(grp) - 1)
                    atomicAdd(&hist[bin], (unsigned)__popc(grp));
            }
        }
        __syncthreads();
        find_kth(hist, 256, k2v, tid, &s_bin, &s_kthr);
        __syncthreads();
        Tkey = (pfx20 << 8) | s_bin;

        for (int w = tid; w < ntl * 32; w += SEL_THREADS) {
            int t = tlist[w >> 5];
            int i4 = t * 32 + (w & 31);
            if (i4 < NH) {
                uint4 a = usrc[i4];
                unsigned k[4] = {a.x, a.y, a.z, a.w};
#pragma unroll
                for (int j = 0; j < 4; j++) {
                    if (k[j] < Tkey) {
                        unsigned s = atomicAdd(&s_selcnt, 1u);
                        if (s < 128) sel[s] = ((u64)k[j] << 32) | (unsigned)(i4 * 4 + j);
                    } else if (k[j] == Tkey) {
                        unsigned s = atomicAdd(&s_tiecnt, 1u);
                        if (s < 128) ties[s] = ((u64)k[j] << 32) | (unsigned)(i4 * 4 + j);
                    }
                }
            }
        }
        __syncthreads();
    }

    const int ns = min((int)s_selcnt, 128);
    const int ne = min((int)s_tiecnt, 128);

    if (tid < ns) {
        u64 mine = sel[tid];
        unsigned my_idx = (unsigned)(mine & 0xFFFFFFFFu);
        int rank = 0;
        for (int j = 0; j < ns; j++) rank += ((unsigned)(sel[j] & 0xFFFFFFFFu) < my_idx);
        float d2 = __uint_as_float((unsigned)(mine >> 32));
        s_w[rank] = (d2 > 0.f) ? __fdiv_rn(1.0f, __fsqrt_rn(d2)) : 0.f;
        s_lab[rank] = labels[my_idx];
    }
    if (tid >= 128 && tid - 128 < ne) {
        int t = tid - 128;
        unsigned my_idx = (unsigned)(ties[t] & 0xFFFFFFFFu);
        int rank = 0;
        for (int j = 0; j < ne; j++) rank += ((unsigned)(ties[j] & 0xFFFFFFFFu) < my_idx);
        tlab[rank] = labels[my_idx];
    }
    __syncthreads();

    if (tid == 0) {
        float cls[NL];
#pragma unroll
        for (int l = 0; l < NL; l++) cls[l] = 0.f;
        float stot = 0.f;
        for (int j = 0; j < ns; j++) { stot += s_w[j]; cls[s_lab[j]] += s_w[j]; }
        int need = KNN - ns;
        float d2T = __uint_as_float(Tkey);
        float wT = (d2T > 0.f) ? __fdiv_rn(1.0f, __fsqrt_rn(d2T)) : 0.f;
        int m = (need < ne) ? need : ne;
        for (int j = 0; j < m; j++) { stot += wT; cls[tlab[j]] += wT; }
#pragma unroll
        for (int l = 0; l < NL; l++) {
            float val = stot - cls[l];
            size_t o = (size_t)b * NL + l;
            if (init) total[o] = val; else total[o] += val;
        }
    }
}

// ---------------------------------------------------------------------------
// Layer-4 select: same structure but d2 recomputed inline from t4 (no d2 mat).
// ---------------------------------------------------------------------------
__global__ void __launch_bounds__(SEL_THREADS)
select4_kernel(const float* __restrict__ q4, const float* __restrict__ t4,
               const float* __restrict__ gmin, const int* __restrict__ labels,
               float* __restrict__ total)
{
    extern __shared__ __align__(16) char sms[];
    unsigned* hist = (unsigned*)sms;
    u64* cand  = (u64*)(sms + OFF_CAND);
    u64* sel   = (u64*)(sms + OFF_SEL);
    u64* ties  = (u64*)(sms + OFF_TIES);
    int* tlab  = (int*)(sms + OFF_TLAB);
    float* mins = (float*)(sms + OFF_MINS);
    int* tlist = (int*)(sms + OFF_TLIST);

    __shared__ unsigned s_M75, s_bin, s_kthr, s_candcnt, s_selcnt, s_tiecnt, s_ntiles;
    __shared__ float s_w[80];
    __shared__ int s_lab[80];
    __shared__ float s_q[8];

    const int b = blockIdx.x, tid = threadIdx.x, lane = tid & 31;

    if (tid < 8) s_q[tid] = q4[(size_t)b * 8 + tid];
    for (int i = tid; i < NTILES; i += SEL_THREADS)
        mins[i] = gmin[(size_t)b * NTILES + i];
    if (tid == 0) { s_candcnt = 0; s_selcnt = 0; s_tiecnt = 0; s_ntiles = 0; }
    __syncthreads();

    float q[8];
#pragma unroll
    for (int j = 0; j < 8; j++) q[j] = s_q[j];
    const float qq = l4_qq(q);

    if (tid < NTILES) {
        unsigned key = __float_as_uint(mins[tid]);
        int c = 0;
        for (int j = 0; j < NTILES; j++) {
            unsigned kj = __float_as_uint(mins[j]);
            c += (kj < key) || (kj == key && j < tid);
        }
        if (c == KNN - 1) s_M75 = key;
    }
    __syncthreads();
    unsigned Mkey = s_M75;

    if (tid < NTILES) {
        if (__float_as_uint(mins[tid]) <= Mkey) {
            unsigned s = atomicAdd(&s_ntiles, 1u);
            tlist[s] = tid;
        }
    }
    __syncthreads();
    int ntl = (int)s_ntiles;

    for (int w = tid; w < ntl * 128; w += SEL_THREADS) {
        int row = tlist[w >> 7] * 128 + (w & 127);
        if (row < NT) {
            unsigned key = __float_as_uint(l4_d2f(t4 + (size_t)row * 8, q, qq));
            if (key <= Mkey) {
                unsigned s = atomicAdd(&s_candcnt, 1u);
                if (s < SEL_CAP) cand[s] = ((u64)key << 32) | (unsigned)row;
            }
        }
    }
    __syncthreads();

    unsigned candTotal = s_candcnt;
    // safety net (should never fire; guards cross-kernel fp mismatch)
    if (candTotal < KNN) {
        __syncthreads();
        if (tid < NTILES) tlist[tid] = tid;
        if (tid == 0) s_ntiles = NTILES;
        __syncthreads();
        ntl = NTILES;
        Mkey = 0xFFFFFFFFu;
        candTotal = SEL_CAP + 1;   // force fallback radix below
    }

    unsigned Tkey;
    if (candTotal <= SEL_CAP) {
        const int cc = (int)candTotal;
        for (int i = tid; i < 4096; i += SEL_THREADS) hist[i] = 0;
        __syncthreads();
        for (int i = tid; i < cc; i += SEL_THREADS)
            atomicAdd(&hist[(unsigned)(cand[i] >> 52)], 1u);
        __syncthreads();
        find_kth(hist, 4096, KNN, tid, &s_bin, &s_kthr);
        __syncthreads();
        const unsigned pfx = s_bin;
        const unsigned k1v = s_kthr;
        for (int i = tid; i < 4096; i += SEL_THREADS) hist[i] = 0;
        __syncthreads();
        for (int i = tid; i < cc; i += SEL_THREADS) {
            unsigned key = (unsigned)(cand[i] >> 32);
            if ((key >> 20) == pfx) atomicAdd(&hist[(key >> 8) & 0xFFFu], 1u);
        }
        __syncthreads();
        find_kth(hist, 4096, k1v, tid, &s_bin, &s_kthr);
        __syncthreads();
        const unsigned pfx20 = (pfx << 12) | s_bin;
        const unsigned k2v = s_kthr;
        for (int i = tid; i < 256; i += SEL_THREADS) hist[i] = 0;
        __syncthreads();
        for (int i = tid; i < cc; i += SEL_THREADS) {
            unsigned key = (unsigned)(cand[i] >> 32);
            if ((key >> 8) == pfx20) atomicAdd(&hist[key & 0xFFu], 1u);
        }
        __syncthreads();
        find_kth(hist, 256, k2v, tid, &s_bin, &s_kthr);
        __syncthreads();
        Tkey = (pfx20 << 8) | s_bin;
        for (int i = tid; i < cc; i += SEL_THREADS) {
            u64 cv = cand[i];
            unsigned key = (unsigned)(cv >> 32);
            if (key < Tkey) {
                unsigned s = atomicAdd(&s_selcnt, 1u);
                if (s < 128) sel[s] = cv;
            } else if (key == Tkey) {
                unsigned s = atomicAdd(&s_tiecnt, 1u);
                if (s < 128) ties[s] = cv;
            }
        }
        __syncthreads();
    } else {
        // fallback radix with inline d2 over listed tiles
        for (int i = tid; i < 4096; i += SEL_THREADS) hist[i] = 0;
        __syncthreads();
        for (int w = tid; w < ntl * 128; w += SEL_THREADS) {
            int row = tlist[w >> 7] * 128 + (w & 127);
            unsigned bin = 0xFFFFFFFFu;
            if (row < NT) {
                unsigned key = __float_as_uint(l4_d2f(t4 + (size_t)row * 8, q, qq));
                if (key <= Mkey) bin = key >> 20;
            }
            unsigned grp = __match_any_sync(0xFFFFFFFFu, bin);
            if (bin != 0xFFFFFFFFu && lane == __ffs(grp) - 1)
                atomicAdd(&hist[bin], (unsigned)__popc(grp));
        }
        __syncthreads();
        find_kth(hist, 4096, KNN, tid, &s_bin, &s_kthr);
        __syncthreads();
        const unsigned pfx = s_bin;
        const unsigned k1v = s_kthr;

        for (int i = tid; i < 4096; i += SEL_THREADS) hist[i] = 0;
        __syncthreads();
        for (int w = tid; w < ntl * 128; w += SEL_THREADS) {
            int row = tlist[w >> 7] * 128 + (w & 127);
            unsigned bin = 0xFFFFFFFFu;
            if (row < NT) {
                unsigned key = __float_as_uint(l4_d2f(t4 + (size_t)row * 8, q, qq));
                if (key <= Mkey && (key >> 20) == pfx) bin = (key >> 8) & 0xFFFu;
            }
            unsigned grp = __match_any_sync(0xFFFFFFFFu, bin);
            if (bin != 0xFFFFFFFFu && lane == __ffs(grp) - 1)
                atomicAdd(&hist[bin], (unsigned)__popc(grp));
        }
        __syncthreads();
        find_kth(hist, 4096, k1v, tid, &s_bin, &s_kthr);
        __syncthreads();
        const unsigned pfx20 = (pfx << 12) | s_bin;
        const unsigned k2v = s_kthr;

        for (int i = tid; i < 256; i += SEL_THREADS) hist[i] = 0;
        __syncthreads();
        for (int w = tid; w < ntl * 128; w += SEL_THREADS) {
            int row = tlist[w >> 7] * 128 + (w & 127);
            unsigned bin = 0xFFFFFFFFu;
            if (row < NT) {
                unsigned key = __float_as_uint(l4_d2f(t4 + (size_t)row * 8, q, qq));
                if (key <= Mkey && (key >> 8) == pfx20) bin = key & 0xFFu;
            }
            unsigned grp = __match_any_sync(0xFFFFFFFFu, bin);
            if (bin != 0xFFFFFFFFu && lane == __ffs(grp) - 1)
                atomicAdd(&hist[bin], (unsigned)__popc(grp));
        }
        __syncthreads();
        find_kth(hist, 256, k2v, tid, &s_bin, &s_kthr);
        __syncthreads();
        Tkey = (pfx20 << 8) | s_bin;

        for (int w = tid; w < ntl * 128; w += SEL_THREADS) {
            int row = tlist[w >> 7] * 128 + (w & 127);
            if (row < NT) {
                unsigned key = __float_as_uint(l4_d2f(t4 + (size_t)row * 8, q, qq));
                if (key < Tkey) {
                    unsigned s = atomicAdd(&s_selcnt, 1u);
                    if (s < 128) sel[s] = ((u64)key << 32) | (unsigned)row;
                } else if (key == Tkey) {
                    unsigned s = atomicAdd(&s_tiecnt, 1u);
                    if (s < 128) ties[s] = ((u64)key << 32) | (unsigned)row;
                }
            }
        }
        __syncthreads();
    }

    const int ns = min((int)s_selcnt, 128);
    const int ne = min((int)s_tiecnt, 128);

    if (tid < ns) {
        u64 mine = sel[tid];
        unsigned my_idx = (unsigned)(mine & 0xFFFFFFFFu);
        int rank = 0;
        for (int j = 0; j < ns; j++) rank += ((unsigned)(sel[j] & 0xFFFFFFFFu) < my_idx);
        float d2 = __uint_as_float((unsigned)(mine >> 32));
        s_w[rank] = (d2 > 0.f) ? __fdiv_rn(1.0f, __fsqrt_rn(d2)) : 0.f;
        s_lab[rank] = labels[my_idx];
    }
    if (tid >= 128 && tid - 128 < ne) {
        int t = tid - 128;
        unsigned my_idx = (unsigned)(ties[t] & 0xFFFFFFFFu);
        int rank = 0;
        for (int j = 0; j < ne; j++) rank += ((unsigned)(ties[j] & 0xFFFFFFFFu) < my_idx);
        tlab[rank] = labels[my_idx];
    }
    __syncthreads();

    if (tid == 0) {
        float cls[NL];
#pragma unroll
        for (int l = 0; l < NL; l++) cls[l] = 0.f;
        float stot = 0.f;
        for (int j = 0; j < ns; j++) { stot += s_w[j]; cls[s_lab[j]] += s_w[j]; }
        int need = KNN - ns;
        float d2T = __uint_as_float(Tkey);
        float wT = (d2T > 0.f) ? __fdiv_rn(1.0f, __fsqrt_rn(d2T)) : 0.f;
        int m = (need < ne) ? need : ne;
        for (int j = 0; j < m; j++) { stot += wT; cls[tlab[j]] += wT; }
#pragma unroll
        for (int l = 0; l < NL; l++)
            total[(size_t)b * NL + l] += stot - cls[l];
    }
}

// ---------------------------------------------------------------------------
__global__ void __launch_bounds__(256)
pvalue_kernel(const float* __restrict__ total, const float* __restrict__ cali,
              float* __restrict__ out)
{
    const int b = blockIdx.x, tid = threadIdx.x;
    float t[NL];
#pragma unroll
    for (int l = 0; l < NL; l++) t[l] = total[(size_t)b * NL + l];
    int cnt[NL];
#pragma unroll
    for (int l = 0; l < NL; l++) cnt[l] = 0;
    for (int i = tid; i < NC; i += 256) {
        float c = cali[i];
#pragma unroll
        for (int l = 0; l < NL; l++) cnt[l] += (c >= t[l]) ? 1 : 0;
    }
    __shared__ int sc[NL];
    if (tid < NL) sc[tid] = 0;
    __syncthreads();
#pragma unroll
    for (int l = 0; l < NL; l++) atomicAdd(&sc[l], cnt[l]);
    __syncthreads();
    if (tid < NL) out[(size_t)b * NL + tid] = (float)sc[tid] * (1.0f / NC);
}

// ---------------------------------------------------------------------------
extern "C" void kernel_launch(void* const* d_in, const int* in_sizes, int n_in,
                              void* d_out, int out_size)
{
    const float* x        = (const float*)d_in[0];
    const float* train_x  = (const float*)d_in[1];
    const int*   lab      = (const int*)  d_in[2];
    const float* cali     = (const float*)d_in[3];
    const float* W1 = (const float*)d_in[4];  const float* b1 = (const float*)d_in[5];
    const float* W2 = (const float*)d_in[6];  const float* b2 = (const float*)d_in[7];
    const float* W3 = (const float*)d_in[8];  const float* b3 = (const float*)d_in[9];
    const float* W4 = (const float*)d_in[10]; const float* b4 = (const float*)d_in[11];
    float* out = (float*)d_out;

    float *h1p, *h2p, *h3p, *q4p, *t3p, *t4p, *d2p, *qnp, *tnp, *totp, *minp;
    __nv_bfloat16 *qhip, *qlop, *thip, *tlop, *thi2p, *tlo2p;
    __nv_bfloat16 *w1th, *w1tl, *w2th, *w2tl, *w3th, *w3tl;
    cudaGetSymbolAddress((void**)&h1p, g_h1);
    cudaGetSymbolAddress((void**)&h2p, g_h2);
    cudaGetSymbolAddress((void**)&h3p, g_h3);
    cudaGetSymbolAddress((void**)&q4p, g_q4);
    cudaGetSymbolAddress((void**)&t3p, g_t3);
    cudaGetSymbolAddress((void**)&t4p, g_t4);
    cudaGetSymbolAddress((void**)&d2p, g_d2);
    cudaGetSymbolAddress((void**)&minp, g_min);
    cudaGetSymbolAddress((void**)&qnp, g_qn);
    cudaGetSymbolAddress((void**)&tnp, g_tn);
    cudaGetSymbolAddress((void**)&totp, g_tot);
    cudaGetSymbolAddress((void**)&qhip, g_qhi);
    cudaGetSymbolAddress((void**)&qlop, g_qlo);
    cudaGetSymbolAddress((void**)&thip, g_thi);
    cudaGetSymbolAddress((void**)&tlop, g_tlo);
    cudaGetSymbolAddress((void**)&thi2p, g_thi2);
    cudaGetSymbolAddress((void**)&tlo2p, g_tlo2);
    cudaGetSymbolAddress((void**)&w1th, g_w1th);
    cudaGetSymbolAddress((void**)&w1tl, g_w1tl);
    cudaGetSymbolAddress((void**)&w2th, g_w2th);
    cudaGetSymbolAddress((void**)&w2tl, g_w2tl);
    cudaGetSymbolAddress((void**)&w3th, g_w3th);
    cudaGetSymbolAddress((void**)&w3tl, g_w3tl);

    cudaFuncSetAttribute(select_kernel,
                         cudaFuncAttributeMaxDynamicSharedMemorySize, SEL_SMEM);
    cudaFuncSetAttribute(select4_kernel,
                         cudaFuncAttributeMaxDynamicSharedMemorySize, SEL_SMEM);
    cudaFuncSetAttribute(mma_dist_kernel,
                         cudaFuncAttributeMaxDynamicSharedMemorySize, MD_SMEM);

    dim3 tb(16, 16);
    const int D0 = 83;
    const dim3 mgrid(NTILES, BQ / 256);

    conv_norm_kernel<<<BQ / 8, 256>>>(x, qhip, qlop, qnp, BQ, D0);
    conv_norm_kernel<<<NTP / 8, 256>>>(train_x, thip, tlop, tnp, NT, D0);
    wt_convert_kernel<<<(3 * 128 * 128 + 255) / 256, 256>>>(W1, W2, W3);

    // layer 0 (mma_dist = launch #4 -> profiled)
    mma_dist_kernel<<<mgrid, 512, MD_SMEM>>>(qhip, qlop, thip, tlop, qnp, tnp, d2p, minp, 6);
    select_kernel<<<BQ, SEL_THREADS, SEL_SMEM>>>(d2p, minp, lab, totp, 1);

    // query-side MLP (tiny SIMT)
    linear_relu_kernel<<<BQ / 64, tb>>>(x,   W1, b1, h1p, BQ, D0);
    linear_relu_kernel<<<BQ / 64, tb>>>(h1p, W2, b2, h2p, BQ, HD);
    linear_relu_kernel<<<BQ / 64, tb>>>(h2p, W3, b3, h3p, BQ, HD);
    linear_softmax_kernel<<<(BQ + 7) / 8, 256>>>(h3p, W4, b4, q4p, BQ);

    // layer 1
    mma_linear_kernel<<<NTILES, 256>>>(thip, tlop, w1th, w1tl, b1,
                                       thi2p, tlo2p, tnp, (float*)0, 6);
    conv_norm_kernel<<<BQ / 8, 256>>>(h1p, qhip, qlop, qnp, BQ, HD);
    mma_dist_kernel<<<mgrid, 512, MD_SMEM>>>(qhip, qlop, thi2p, tlo2p, qnp, tnp, d2p, minp, 8);
    select_kernel<<<BQ, SEL_THREADS, SEL_SMEM>>>(d2p, minp, lab, totp, 0);

    // layer 2
    mma_linear_kernel<<<NTILES, 256>>>(thi2p, tlo2p, w2th, w2tl, b2,
                                       thip, tlop, tnp, (float*)0, 8);
    conv_norm_kernel<<<BQ / 8, 256>>>(h2p, qhip, qlop, qnp, BQ, HD);
    mma_dist_kernel<<<mgrid, 512, MD_SMEM>>>(qhip, qlop, thip, tlop, qnp, tnp, d2p, minp, 8);
    select_kernel<<<BQ, SEL_THREADS, SEL_SMEM>>>(d2p, minp, lab, totp, 0);

    // layer 3 (+ fp32 t3 for softmax)
    mma_linear_kernel<<<NTILES, 256>>>(thip, tlop, w3th, w3tl, b3,
                                       thi2p, tlo2p, tnp, t3p, 8);
    conv_norm_kernel<<<BQ / 8, 256>>>(h3p, qhip, qlop, qnp, BQ, HD);
    mma_dist_kernel<<<mgrid, 512, MD_SMEM>>>(qhip, qlop, thi2p, tlo2p, qnp, tnp, d2p, minp, 8);
    select_kernel<<<BQ, SEL_THREADS, SEL_SMEM>>>(d2p, minp, lab, totp, 0);

    // layer 4 (softmax features, D=8): d2-free exact path
    linear_softmax_kernel<<<(NT + 7) / 8, 256>>>(t3p, W4, b4, t4p, NT);
    min4_kernel<<<dim3(NTILES, BQ / 128), 256>>>(q4p, t4p, minp);
    select4_kernel<<<BQ, SEL_THREADS, SEL_SMEM>>>(q4p, t4p, minp, lab, totp);

    pvalue_kernel<<<BQ, 256>>>(totp, cali, out);
}

// round 15
// speedup vs baseline: 1.0985x; 1.0985x over previous
#include <cuda_runtime.h>
#include <cuda_bf16.h>
#include <math.h>
#include <stdint.h>

#define BQ   1024
#define NT   50000
#define NTP  50048
#define NL   8
#define KNN  75
#define HD   128
#define NC   10000
#define NTILES 391          // NTP/128

typedef unsigned long long u64;

// ---------------- device scratch ----------------
__device__ float g_h1[BQ * HD];
__device__ float g_h2[BQ * HD];
__device__ float g_h3[BQ * HD];
__device__ float g_q4[BQ * NL];
__device__ float g_t3[(size_t)NT * HD];
__device__ float g_t4[(size_t)NT * NL];
__device__ float g_d2a[(size_t)BQ * NT];
__device__ float g_d2b[(size_t)BQ * NT];
__device__ float g_minall[(size_t)5 * BQ * NTILES];   // per-layer min buffers
__device__ float g_qn[BQ];
__device__ float g_tn[NT];
__device__ float g_tot[BQ * NL];
__device__ __nv_bfloat16 g_qhi[(size_t)BQ * 128];
__device__ __nv_bfloat16 g_qlo[(size_t)BQ * 128];
__device__ __nv_bfloat16 g_thi[(size_t)NTP * 128];    // bank A
__device__ __nv_bfloat16 g_tlo[(size_t)NTP * 128];
__device__ __nv_bfloat16 g_thi2[(size_t)NTP * 128];   // bank B
__device__ __nv_bfloat16 g_tlo2[(size_t)NTP * 128];
__device__ __nv_bfloat16 g_w1th[128 * 128], g_w1tl[128 * 128];
__device__ __nv_bfloat16 g_w2th[128 * 128], g_w2tl[128 * 128];
__device__ __nv_bfloat16 g_w3th[128 * 128], g_w3tl[128 * 128];

// ---------------- overlap machinery (created once at load; no device mem) ----
static cudaStream_t g_s2 = 0;
static cudaEvent_t g_evF[5], g_evJ[5];
static bool g_ok = false;
namespace {
struct StreamInit {
    StreamInit() {
        if (cudaStreamCreateWithFlags(&g_s2, cudaStreamNonBlocking) != cudaSuccess) return;
        bool ok = true;
        for (int i = 0; i < 5; i++) {
            ok = ok && (cudaEventCreateWithFlags(&g_evF[i], cudaEventDisableTiming) == cudaSuccess);
            ok = ok && (cudaEventCreateWithFlags(&g_evJ[i], cudaEventDisableTiming) == cudaSuccess);
        }
        g_ok = ok;
    }
};
StreamInit g_si;
}

// ---------------------------------------------------------------------------
__device__ __forceinline__ void mma_bf16(float* d, const uint32_t* a, const uint32_t* b)
{
    asm volatile(
        "mma.sync.aligned.m16n8k16.row.col.f32.bf16.bf16.f32 "
        "{%0,%1,%2,%3}, {%4,%5,%6,%7}, {%8,%9}, {%0,%1,%2,%3};"
        : "+f"(d[0]), "+f"(d[1]), "+f"(d[2]), "+f"(d[3])
        : "r"(a[0]), "r"(a[1]), "r"(a[2]), "r"(a[3]), "r"(b[0]), "r"(b[1]));
}

#define SLICE_ELEMS (128 * 24)

__device__ __forceinline__ void slice_load_async(
    const __nv_bfloat16* __restrict__ Gp, __nv_bfloat16* Ss,
    int row0, int k0, int lr, int lh)
{
    uint32_t sa = (uint32_t)__cvta_generic_to_shared(Ss + lr * 24 + lh * 8);
    const void* ga = Gp + (size_t)(row0 + lr) * 128 + k0 + lh * 8;
    asm volatile("cp.async.cg.shared.global [%0], [%1], 16;\n" :: "r"(sa), "l"(ga));
}

// ---------------------------------------------------------------------------
// Layer-4 exact d2 helpers (fixed op order, shared by min4 / select4).
// ---------------------------------------------------------------------------
__device__ __forceinline__ float l4_qq(const float* q)
{
    float s = __fmul_rn(q[0], q[0]);
    s = __fmaf_rn(q[1], q[1], s); s = __fmaf_rn(q[2], q[2], s);
    s = __fmaf_rn(q[3], q[3], s); s = __fmaf_rn(q[4], q[4], s);
    s = __fmaf_rn(q[5], q[5], s); s = __fmaf_rn(q[6], q[6], s);
    s = __fmaf_rn(q[7], q[7], s);
    return s;
}
__device__ __forceinline__ float l4_d2f(const float* __restrict__ tr,
                                        const float* q, float qq)
{
    float tt = __fmul_rn(tr[0], tr[0]);
    tt = __fmaf_rn(tr[1], tr[1], tt); tt = __fmaf_rn(tr[2], tr[2], tt);
    tt = __fmaf_rn(tr[3], tr[3], tt); tt = __fmaf_rn(tr[4], tr[4], tt);
    tt = __fmaf_rn(tr[5], tr[5], tt); tt = __fmaf_rn(tr[6], tr[6], tt);
    tt = __fmaf_rn(tr[7], tr[7], tt);
    float dt = __fmul_rn(q[0], tr[0]);
    dt = __fmaf_rn(q[1], tr[1], dt); dt = __fmaf_rn(q[2], tr[2], dt);
    dt = __fmaf_rn(q[3], tr[3], dt); dt = __fmaf_rn(q[4], tr[4], dt);
    dt = __fmaf_rn(q[5], tr[5], dt); dt = __fmaf_rn(q[6], tr[6], dt);
    dt = __fmaf_rn(q[7], tr[7], dt);
    return fmaxf(__fmaf_rn(-2.f, dt, __fadd_rn(qq, tt)), 0.f);
}

// ---------------------------------------------------------------------------
__global__ void __launch_bounds__(256)
conv_norm_kernel(const float* __restrict__ A, __nv_bfloat16* __restrict__ hi,
                 __nv_bfloat16* __restrict__ lo, float* __restrict__ nrm,
                 int Mreal, int D)
{
    int warp = threadIdx.x >> 5, lane = threadIdx.x & 31;
    int row = blockIdx.x * 8 + warp;
    int base = lane * 4;

    float ss = 0.f;
    __nv_bfloat16 hb[4], lb[4];
#pragma unroll
    for (int j = 0; j < 4; j++) {
        int col = base + j;
        float v = (row < Mreal && col < D) ? A[(size_t)row * D + col] : 0.f;
        ss += v * v;
        hb[j] = __float2bfloat16_rn(v);
        lb[j] = __float2bfloat16_rn(v - __bfloat162float(hb[j]));
    }
    __nv_bfloat162 h01, h23, l01, l23;
    h01.x = hb[0]; h01.y = hb[1]; h23.x = hb[2]; h23.y = hb[3];
    l01.x = lb[0]; l01.y = lb[1]; l23.x = lb[2]; l23.y = lb[3];
    *(__nv_bfloat162*)&hi[(size_t)row * 128 + base]     = h01;
    *(__nv_bfloat162*)&hi[(size_t)row * 128 + base + 2] = h23;
    *(__nv_bfloat162*)&lo[(size_t)row * 128 + base]     = l01;
    *(__nv_bfloat162*)&lo[(size_t)row * 128 + base + 2] = l23;

#pragma unroll
    for (int off = 16; off > 0; off >>= 1) ss += __shfl_down_sync(0xFFFFFFFFu, ss, off);
    if (lane == 0 && row < Mreal) nrm[row] = ss;
}

// ---------------------------------------------------------------------------
__global__ void __launch_bounds__(256)
wt_convert_kernel(const float* __restrict__ W1, const float* __restrict__ W2,
                  const float* __restrict__ W3)
{
    int idx = blockIdx.x * 256 + threadIdx.x;
    if (idx >= 3 * 128 * 128) return;
    int which = idx >> 14;
    int e = idx & 16383;
    int n = e & 127, k = e >> 7;
    const float* W = (which == 0) ? W1 : (which == 1) ? W2 : W3;
    int K = (which == 0) ? 83 : 128;
    float v = (k < K) ? W[(size_t)k * 128 + n] : 0.f;
    __nv_bfloat16 h = __float2bfloat16_rn(v);
    __nv_bfloat16 l = __float2bfloat16_rn(v - __bfloat162float(h));
    __nv_bfloat16* dh = (which == 0) ? g_w1th : (which == 1) ? g_w2th : g_w3th;
    __nv_bfloat16* dl = (which == 0) ? g_w1tl : (which == 1) ? g_w2tl : g_w3tl;
    dh[e] = h;
    dl[e] = l;
}

// ---------------------------------------------------------------------------
// bf16x3 GEMM mainloop (128-row tiles) - used by mma_linear_kernel.
// ---------------------------------------------------------------------------
__device__ __forceinline__ void gemm3_mainloop(
    const __nv_bfloat16* Ahi, const __nv_bfloat16* Alo,
    const __nv_bfloat16* Bhi, const __nv_bfloat16* Blo,
    __nv_bfloat16* smem, int m0, int n0, int nCh,
    int wm, int wn, int fr, int fc, int lr, int lh,
    float acc[2][8][4])
{
    __nv_bfloat16* AhiS[2] = {smem,                   smem + 4 * SLICE_ELEMS};
    __nv_bfloat16* AloS[2] = {smem + 1 * SLICE_ELEMS, smem + 5 * SLICE_ELEMS};
    __nv_bfloat16* BhiS[2] = {smem + 2 * SLICE_ELEMS, smem + 6 * SLICE_ELEMS};
    __nv_bfloat16* BloS[2] = {smem + 3 * SLICE_ELEMS, smem + 7 * SLICE_ELEMS};

    slice_load_async(Ahi, AhiS[0], m0, 0, lr, lh);
    slice_load_async(Alo, AloS[0], m0, 0, lr, lh);
    slice_load_async(Bhi, BhiS[0], n0, 0, lr, lh);
    slice_load_async(Blo, BloS[0], n0, 0, lr, lh);
    asm volatile("cp.async.commit_group;\n" ::: "memory");

    for (int c = 0; c < nCh; c++) {
        int buf = c & 1;
        if (c + 1 < nCh) {
            int k0 = (c + 1) * 16;
            slice_load_async(Ahi, AhiS[buf ^ 1], m0, k0, lr, lh);
            slice_load_async(Alo, AloS[buf ^ 1], m0, k0, lr, lh);
            slice_load_async(Bhi, BhiS[buf ^ 1], n0, k0, lr, lh);
            slice_load_async(Blo, BloS[buf ^ 1], n0, k0, lr, lh);
            asm volatile("cp.async.commit_group;\n" ::: "memory");
            asm volatile("cp.async.wait_group 1;" ::: "memory");
        } else {
            asm volatile("cp.async.wait_group 0;" ::: "memory");
        }
        __syncthreads();

        const __nv_bfloat16* Ah = AhiS[buf];
        const __nv_bfloat16* Al = AloS[buf];
        const __nv_bfloat16* Bh = BhiS[buf];
        const __nv_bfloat16* Bl = BloS[buf];

        uint32_t ah[2][4];
#pragma unroll
        for (int mt = 0; mt < 2; mt++) {
            int bm = wm + mt * 16;
            ah[mt][0] = *(const uint32_t*)&Ah[(bm + fr) * 24 + fc];
            ah[mt][1] = *(const uint32_t*)&Ah[(bm + fr + 8) * 24 + fc];
            ah[mt][2] = *(const uint32_t*)&Ah[(bm + fr) * 24 + fc + 8];
            ah[mt][3] = *(const uint32_t*)&Ah[(bm + fr + 8) * 24 + fc + 8];
        }
        uint32_t bh8[8][2];
#pragma unroll
        for (int nt = 0; nt < 8; nt++) {
            int nb = wn + nt * 8;
            bh8[nt][0] = *(const uint32_t*)&Bh[(nb + fr) * 24 + fc];
            bh8[nt][1] = *(const uint32_t*)&Bh[(nb + fr) * 24 + fc + 8];
        }
#pragma unroll
        for (int nt = 0; nt < 8; nt++) {
            mma_bf16(acc[0][nt], ah[0], bh8[nt]);
            mma_bf16(acc[1][nt], ah[1], bh8[nt]);
        }
        uint32_t al[2][4];
#pragma unroll
        for (int mt = 0; mt < 2; mt++) {
            int bm = wm + mt * 16;
            al[mt][0] = *(const uint32_t*)&Al[(bm + fr) * 24 + fc];
            al[mt][1] = *(const uint32_t*)&Al[(bm + fr + 8) * 24 + fc];
            al[mt][2] = *(const uint32_t*)&Al[(bm + fr) * 24 + fc + 8];
            al[mt][3] = *(const uint32_t*)&Al[(bm + fr + 8) * 24 + fc + 8];
        }
#pragma unroll
        for (int nt = 0; nt < 8; nt++) {
            mma_bf16(acc[0][nt], al[0], bh8[nt]);
            mma_bf16(acc[1][nt], al[1], bh8[nt]);
        }
#pragma unroll
        for (int nt = 0; nt < 8; nt++) {
            int nb = wn + nt * 8;
            uint32_t bl[2];
            bl[0] = *(const uint32_t*)&Bl[(nb + fr) * 24 + fc];
            bl[1] = *(const uint32_t*)&Bl[(nb + fr) * 24 + fc + 8];
            mma_bf16(acc[0][nt], ah[0], bl);
            mma_bf16(acc[1][nt], ah[1], bl);
        }
        __syncthreads();
    }
}

// ---------------------------------------------------------------------------
// 256x128 distance GEMM, 512 threads, 3-stage pipeline, 1 sync per chunk.
// ---------------------------------------------------------------------------
#define ASL (256 * 24)
#define BSL (128 * 24)
#define STAGE_ELEMS (2 * ASL + 2 * BSL)
#define MD_SMEM (3 * STAGE_ELEMS * 2)

__global__ void __launch_bounds__(512, 1)
mma_dist_kernel(const __nv_bfloat16* __restrict__ Qhi, const __nv_bfloat16* __restrict__ Qlo,
                const __nv_bfloat16* __restrict__ Thi, const __nv_bfloat16* __restrict__ Tlo,
                const float* __restrict__ qn, const float* __restrict__ tn,
                float* __restrict__ out, float* __restrict__ gmin, int nCh)
{
    extern __shared__ __align__(16) __nv_bfloat16 dsm[];
    __shared__ float sMin[256][2];
    const int tid = threadIdx.x;
    const int wid = tid >> 5, lane = tid & 31;
    const int n0 = blockIdx.x * 128;
    const int m0 = blockIdx.y * 256;
    const int wm = (wid & 7) * 32;
    const int wn = (wid >> 3) * 64;
    const int fr = lane >> 2, fc = (lane & 3) * 2;
    const int ar = tid >> 1, ah2 = tid & 1;
    const int br = (tid & 255) >> 1, bh2 = tid & 1;

    float acc[2][8][4];
#pragma unroll
    for (int mt = 0; mt < 2; mt++)
#pragma unroll
        for (int nt = 0; nt < 8; nt++)
#pragma unroll
            for (int j = 0; j < 4; j++) acc[mt][nt][j] = 0.f;

#define LOAD_STAGE(s, k0) do {                                                  \
        __nv_bfloat16* sb_ = dsm + (s) * STAGE_ELEMS;                           \
        slice_load_async(Qhi, sb_,            m0, (k0), ar, ah2);               \
        slice_load_async(Qlo, sb_ + ASL,      m0, (k0), ar, ah2);               \
        if (tid < 256) slice_load_async(Thi, sb_ + 2 * ASL,      n0, (k0), br, bh2); \
        else           slice_load_async(Tlo, sb_ + 2 * ASL + BSL, n0, (k0), br, bh2); \
        asm volatile("cp.async.commit_group;\n" ::: "memory");                  \
    } while (0)

    LOAD_STAGE(0, 0);
    if (nCh > 1) LOAD_STAGE(1, 16);

    for (int c = 0; c < nCh; c++) {
        if (c + 1 < nCh) asm volatile("cp.async.wait_group 1;" ::: "memory");
        else             asm volatile("cp.async.wait_group 0;" ::: "memory");
        __syncthreads();
        if (c + 2 < nCh) LOAD_STAGE((c + 2) % 3, (c + 2) * 16);

        const __nv_bfloat16* sb = dsm + (c % 3) * STAGE_ELEMS;
        const __nv_bfloat16* Ah = sb;
        const __nv_bfloat16* Al = sb + ASL;
        const __nv_bfloat16* Bh = sb + 2 * ASL;
        const __nv_bfloat16* Bl = sb + 2 * ASL + BSL;

        uint32_t ah[2][4];
#pragma unroll
        for (int mt = 0; mt < 2; mt++) {
            int bm = wm + mt * 16;
            ah[mt][0] = *(const uint32_t*)&Ah[(bm + fr) * 24 + fc];
            ah[mt][1] = *(const uint32_t*)&Ah[(bm + fr + 8) * 24 + fc];
            ah[mt][2] = *(const uint32_t*)&Ah[(bm + fr) * 24 + fc + 8];
            ah[mt][3] = *(const uint32_t*)&Ah[(bm + fr + 8) * 24 + fc + 8];
        }
        uint32_t bh8[8][2];
#pragma unroll
        for (int nt = 0; nt < 8; nt++) {
            int nb = wn + nt * 8;
            bh8[nt][0] = *(const uint32_t*)&Bh[(nb + fr) * 24 + fc];
            bh8[nt][1] = *(const uint32_t*)&Bh[(nb + fr) * 24 + fc + 8];
        }
#pragma unroll
        for (int nt = 0; nt < 8; nt++) {
            mma_bf16(acc[0][nt], ah[0], bh8[nt]);
            mma_bf16(acc[1][nt], ah[1], bh8[nt]);
        }
        uint32_t al[2][4];
#pragma unroll
        for (int mt = 0; mt < 2; mt++) {
            int bm = wm + mt * 16;
            al[mt][0] = *(const uint32_t*)&Al[(bm + fr) * 24 + fc];
            al[mt][1] = *(const uint32_t*)&Al[(bm + fr + 8) * 24 + fc];
            al[mt][2] = *(const uint32_t*)&Al[(bm + fr) * 24 + fc + 8];
            al[mt][3] = *(const uint32_t*)&Al[(bm + fr + 8) * 24 + fc + 8];
        }
#pragma unroll
        for (int nt = 0; nt < 8; nt++) {
            mma_bf16(acc[0][nt], al[0], bh8[nt]);
            mma_bf16(acc[1][nt], al[1], bh8[nt]);
        }
#pragma unroll
        for (int nt = 0; nt < 8; nt++) {
            int nb = wn + nt * 8;
            uint32_t bl[2];
            bl[0] = *(const uint32_t*)&Bl[(nb + fr) * 24 + fc];
            bl[1] = *(const uint32_t*)&Bl[(nb + fr) * 24 + fc + 8];
            mma_bf16(acc[0][nt], ah[0], bl);
            mma_bf16(acc[1][nt], ah[1], bl);
        }
    }
#undef LOAD_STAGE

    const float FINF = __int_as_float(0x7F800000);
    float rmin[2][2] = {{FINF, FINF}, {FINF, FINF}};
#pragma unroll
    for (int mt = 0; mt < 2; mt++) {
        int mrow = m0 + wm + mt * 16 + fr;
        float q0 = qn[mrow], q1 = qn[mrow + 8];
#pragma unroll
        for (int nt = 0; nt < 8; nt++) {
            int n = n0 + wn + nt * 8 + fc;
            if (n < NT) {
                float t0 = tn[n], t1 = tn[n + 1];
                float2 o;
                o.x = fmaxf(q0 + t0 - 2.f * acc[mt][nt][0], 0.f);
                o.y = fmaxf(q0 + t1 - 2.f * acc[mt][nt][1], 0.f);
                *(float2*)&out[(size_t)mrow * NT + n] = o;
                rmin[mt][0] = fminf(rmin[mt][0], fminf(o.x, o.y));
                o.x = fmaxf(q1 + t0 - 2.f * acc[mt][nt][2], 0.f);
                o.y = fmaxf(q1 + t1 - 2.f * acc[mt][nt][3], 0.f);
                *(float2*)&out[(size_t)(mrow + 8) * NT + n] = o;
                rmin[mt][1] = fminf(rmin[mt][1], fminf(o.x, o.y));
            }
        }
    }
    __syncthreads();
#pragma unroll
    for (int mt = 0; mt < 2; mt++)
#pragma unroll
        for (int rr = 0; rr < 2; rr++) {
            float m = rmin[mt][rr];
            m = fminf(m, __shfl_xor_sync(0xFFFFFFFFu, m, 1));
            m = fminf(m, __shfl_xor_sync(0xFFFFFFFFu, m, 2));
            if ((lane & 3) == 0)
                sMin[wm + mt * 16 + rr * 8 + fr][wn >> 6] = m;
        }
    __syncthreads();
    if (tid < 256)
        gmin[(size_t)(m0 + tid) * NTILES + blockIdx.x] =
            fminf(sMin[tid][0], sMin[tid][1]);
}

// ---------------------------------------------------------------------------
__global__ void __launch_bounds__(256, 2)
mma_linear_kernel(const __nv_bfloat16* __restrict__ Ahi, const __nv_bfloat16* __restrict__ Alo,
                  const __nv_bfloat16* __restrict__ Wth, const __nv_bfloat16* __restrict__ Wtl,
                  const float* __restrict__ bias,
                  __nv_bfloat16* __restrict__ Ohi, __nv_bfloat16* __restrict__ Olo,
                  float* __restrict__ nrm, float* __restrict__ Ofp, int nCh)
{
    __shared__ __align__(16) __nv_bfloat16 smem[8 * SLICE_ELEMS];
    __shared__ float snorm[128];
    __shared__ float sbias[128];
    const int tid = threadIdx.x;
    const int wid = tid >> 5, lane = tid & 31;
    const int m0 = blockIdx.x * 128;
    const int wm = (wid & 3) * 32;
    const int wn = (wid >> 2) * 64;
    const int lr = tid >> 1, lh = tid & 1;
    const int fr = lane >> 2, fc = (lane & 3) * 2;

    if (tid < 128) { sbias[tid] = bias[tid]; snorm[tid] = 0.f; }

    float acc[2][8][4];
#pragma unroll
    for (int mt = 0; mt < 2; mt++)
#pragma unroll
        for (int nt = 0; nt < 8; nt++)
#pragma unroll
            for (int j = 0; j < 4; j++) acc[mt][nt][j] = 0.f;

    gemm3_mainloop(Ahi, Alo, Wth, Wtl, smem, m0, 0, nCh,
                   wm, wn, fr, fc, lr, lh, acc);

#pragma unroll
    for (int mt = 0; mt < 2; mt++) {
        int r0 = wm + mt * 16 + fr;
        int r1 = r0 + 8;
        size_t g0 = (size_t)(m0 + r0) * 128;
        size_t g1 = (size_t)(m0 + r1) * 128;
        float ns0 = 0.f, ns1 = 0.f;
#pragma unroll
        for (int nt = 0; nt < 8; nt++) {
            int n = wn + nt * 8 + fc;
            float b0 = sbias[n], b1 = sbias[n + 1];
            float v00 = fmaxf(acc[mt][nt][0] + b0, 0.f);
            float v01 = fmaxf(acc[mt][nt][1] + b1, 0.f);
            float v10 = fmaxf(acc[mt][nt][2] + b0, 0.f);
            float v11 = fmaxf(acc[mt][nt][3] + b1, 0.f);
            ns0 += v00 * v00 + v01 * v01;
            ns1 += v10 * v10 + v11 * v11;
            __nv_bfloat162 h, l;
            h.x = __float2bfloat16_rn(v00);
            h.y = __float2bfloat16_rn(v01);
            l.x = __float2bfloat16_rn(v00 - __bfloat162float(h.x));
            l.y = __float2bfloat16_rn(v01 - __bfloat162float(h.y));
            *(__nv_bfloat162*)&Ohi[g0 + n] = h;
            *(__nv_bfloat162*)&Olo[g0 + n] = l;
            h.x = __float2bfloat16_rn(v10);
            h.y = __float2bfloat16_rn(v11);
            l.x = __float2bfloat16_rn(v10 - __bfloat162float(h.x));
            l.y = __float2bfloat16_rn(v11 - __bfloat162float(h.y));
            *(__nv_bfloat162*)&Ohi[g1 + n] = h;
            *(__nv_bfloat162*)&Olo[g1 + n] = l;
            if (Ofp) {
                *(float2*)&Ofp[g0 + n] = make_float2(v00, v01);
                *(float2*)&Ofp[g1 + n] = make_float2(v10, v11);
            }
        }
        atomicAdd(&snorm[r0], ns0);
        atomicAdd(&snorm[r1], ns1);
    }
    __syncthreads();
    if (tid < 128 && m0 + tid < NT) nrm[m0 + tid] = snorm[tid];
}

// ---------------------------------------------------------------------------
__global__ void __launch_bounds__(256)
linear_relu_kernel(const float* __restrict__ A, const float* __restrict__ W,
                   const float* __restrict__ bias, float* __restrict__ out,
                   int M, int K)
{
    __shared__ __align__(16) float As[16 * 68];
    __shared__ __align__(16) float Bs[16 * 136];
    const int tx = threadIdx.x, ty = threadIdx.y;
    const int tid = ty * 16 + tx;
    const int m0 = blockIdx.x * 64;

    float acc[4][8];
#pragma unroll
    for (int r = 0; r < 4; r++)
#pragma unroll
        for (int c = 0; c < 8; c++) acc[r][c] = 0.f;

    const int nChunks = (K + 15) / 16;
    for (int ch = 0; ch < nChunks; ch++) {
        const int k0 = ch * 16;
#pragma unroll
        for (int i = 0; i < 4; i++) {
            int e = tid + i * 256;
            int k = e & 15, m = e >> 4;
            float v = 0.f;
            if (k0 + k < K && m0 + m < M) v = A[(size_t)(m0 + m) * K + k0 + k];
            As[k * 68 + m] = v;
        }
#pragma unroll
        for (int i = 0; i < 8; i++) {
            int e = tid + i * 256;
            int h = e & 127, k = e >> 7;
            float v = 0.f;
            if (k0 + k < K) v = W[(size_t)(k0 + k) * HD + h];
            Bs[k * 136 + h] = v;
        }
        __syncthreads();
#pragma unroll
        for (int k = 0; k < 16; k++) {
            float4 a  = *(const float4*)&As[k * 68 + ty * 4];
            float4 b0 = *(const float4*)&Bs[k * 136 + tx * 4];
            float4 b1 = *(const float4*)&Bs[k * 136 + 64 + tx * 4];
            float av[4] = {a.x, a.y, a.z, a.w};
            float bv[8] = {b0.x, b0.y, b0.z, b0.w, b1.x, b1.y, b1.z, b1.w};
#pragma unroll
            for (int r = 0; r < 4; r++)
#pragma unroll
                for (int c = 0; c < 8; c++) acc[r][c] += av[r] * bv[c];
        }
        __syncthreads();
    }
#pragma unroll
    for (int r = 0; r < 4; r++) {
        int m = m0 + ty * 4 + r;
        if (m >= M) continue;
#pragma unroll
        for (int half = 0; half < 2; half++) {
#pragma unroll
            for (int c = 0; c < 4; c++) {
                int h = half * 64 + tx * 4 + c;
                float v = acc[r][half * 4 + c] + bias[h];
                out[(size_t)m * HD + h] = fmaxf(v, 0.f);
            }
        }
    }
}

// ---------------------------------------------------------------------------
__global__ void __launch_bounds__(256)
linear_softmax_kernel(const float* __restrict__ A, const float* __restrict__ W,
                      const float* __restrict__ bias, float* __restrict__ out, int M)
{
    __shared__ float Ws[HD * NL];
    __shared__ float bs[NL];
    int tid = threadIdx.x;
    for (int i = tid; i < HD * NL; i += 256) Ws[i] = W[i];
    if (tid < NL) bs[tid] = bias[tid];
    __syncthreads();

    int warp = tid >> 5, lane = tid & 31;
    int m = blockIdx.x * 8 + warp;
    if (m >= M) return;

    float acc[NL];
#pragma unroll
    for (int h = 0; h < NL; h++) acc[h] = 0.f;
    for (int k = lane; k < HD; k += 32) {
        float x = A[(size_t)m * HD + k];
#pragma unroll
        for (int h = 0; h < NL; h++) acc[h] += x * Ws[k * NL + h];
    }
#pragma unroll
    for (int h = 0; h < NL; h++)
#pragma unroll
        for (int off = 16; off > 0; off >>= 1)
            acc[h] += __shfl_down_sync(0xFFFFFFFFu, acc[h], off);

    if (lane == 0) {
        float v[NL], mx = -1e30f;
#pragma unroll
        for (int h = 0; h < NL; h++) { v[h] = acc[h] + bs[h]; mx = fmaxf(mx, v[h]); }
        float s = 0.f;
#pragma unroll
        for (int h = 0; h < NL; h++) { v[h] = expf(v[h] - mx); s += v[h]; }
        float inv = 1.0f / s;
#pragma unroll
        for (int h = 0; h < NL; h++) out[(size_t)m * NL + h] = v[h] * inv;
    }
}

// ---------------------------------------------------------------------------
// Layer-4 tile minima WITHOUT materializing d2.
// ---------------------------------------------------------------------------
__global__ void __launch_bounds__(256)
min4_kernel(const float* __restrict__ q4, const float* __restrict__ t4,
            float* __restrict__ gmin)
{
    __shared__ float st[128 * 8];
    __shared__ float sq[128 * 8];
    const int t = blockIdx.x;
    const int q0 = blockIdx.y * 128;
    const int tid = threadIdx.x;
    const float FINF = __int_as_float(0x7F800000);

    for (int i = tid; i < 1024; i += 256) {
        int row = t * 128 + (i >> 3);
        st[i] = (row < NT) ? t4[(size_t)row * 8 + (i & 7)] : 0.f;
        sq[i] = q4[(size_t)(q0 + (i >> 3)) * 8 + (i & 7)];
    }
    __syncthreads();

    const int qi = tid >> 1, half = tid & 1;
    float q[8];
#pragma unroll
    for (int j = 0; j < 8; j++) q[j] = sq[qi * 8 + j];
    const float qq = l4_qq(q);

    float m = FINF;
    const int rbase = half * 64;
    for (int r = 0; r < 64; r++) {
        int row = t * 128 + rbase + r;
        if (row < NT)
            m = fminf(m, l4_d2f(&st[(rbase + r) * 8], q, qq));
    }
    m = fminf(m, __shfl_xor_sync(0xFFFFFFFFu, m, 1));
    if (half == 0)
        gmin[(size_t)(q0 + qi) * NTILES + t] = m;
}

// ---------------------------------------------------------------------------
__device__ __forceinline__ void find_kth(const unsigned* hist, int NB, unsigned kth,
                                         int tid, unsigned* s_bin, unsigned* s_kthr)
{
    if (tid < 32) {
        unsigned running = 0;
        for (int base = 0; base < NB; base += 32) {
            unsigned v = hist[base + tid];
            unsigned sc = v;
#pragma unroll
            for (int off = 1; off < 32; off <<= 1) {
                unsigned t = __shfl_up_sync(0xFFFFFFFFu, sc, off);
                if (tid >= off) sc += t;
            }
            unsigned tot = __shfl_sync(0xFFFFFFFFu, sc, 31);
            if (running + tot >= kth) {
                unsigned mask = __ballot_sync(0xFFFFFFFFu, running + sc >= kth);
                int l = __ffs(mask) - 1;
                if (tid == l) { *s_bin = (unsigned)(base + l); *s_kthr = kth - running - (sc - v); }
                break;
            }
            running += tot;
        }
    }
}

// ---------------------------------------------------------------------------
// Exact top-K select (layers 0-3): tile-min threshold + tile-subset d2 scan.
// ---------------------------------------------------------------------------
#define SEL_THREADS 512
#define SEL_CAP 2048
#define OFF_CAND  16384
#define OFF_SEL   (OFF_CAND + SEL_CAP * 8)
#define OFF_TIES  (OFF_SEL + 1024)
#define OFF_TLAB  (OFF_TIES + 1024)
#define OFF_MINS  (OFF_TLAB + 512)
#define OFF_TLIST (OFF_MINS + 392 * 4)
#define SEL_SMEM  (OFF_TLIST + 392 * 4)

__global__ void __launch_bounds__(SEL_THREADS)
select_kernel(const float* __restrict__ d2mat, const float* __restrict__ gmin,
              const int* __restrict__ labels, float* __restrict__ total, int init)
{
    extern __shared__ __align__(16) char sms[];
    unsigned* hist = (unsigned*)sms;
    u64* cand  = (u64*)(sms + OFF_CAND);
    u64* sel   = (u64*)(sms + OFF_SEL);
    u64* ties  = (u64*)(sms + OFF_TIES);
    int* tlab  = (int*)(sms + OFF_TLAB);
    float* mins = (float*)(sms + OFF_MINS);
    int* tlist = (int*)(sms + OFF_TLIST);

    __shared__ unsigned s_M75, s_bin, s_kthr, s_candcnt, s_selcnt, s_tiecnt, s_ntiles;
    __shared__ float s_w[80];
    __shared__ int s_lab[80];

    const int b = blockIdx.x, tid = threadIdx.x, lane = tid & 31;
    const uint4* usrc = (const uint4*)(d2mat + (size_t)b * NT);
    const int NH = NT / 4;

    for (int i = tid; i < NTILES; i += SEL_THREADS)
        mins[i] = gmin[(size_t)b * NTILES + i];
    if (tid == 0) { s_candcnt = 0; s_selcnt = 0; s_tiecnt = 0; s_ntiles = 0; }
    __syncthreads();

    if (tid < NTILES) {
        unsigned key = __float_as_uint(mins[tid]);
        int c = 0;
        for (int j = 0; j < NTILES; j++) {
            unsigned kj = __float_as_uint(mins[j]);
            c += (kj < key) || (kj == key && j < tid);
        }
        if (c == KNN - 1) s_M75 = key;
    }
    __syncthreads();
    const unsigned Mkey = s_M75;

    if (tid < NTILES) {
        if (__float_as_uint(mins[tid]) <= Mkey) {
            unsigned s = atomicAdd(&s_ntiles, 1u);
            tlist[s] = tid;
        }
    }
    __syncthreads();
    const int ntl = (int)s_ntiles;

    for (int w = tid; w < ntl * 32; w += SEL_THREADS) {
        int t = tlist[w >> 5];
        int i4 = t * 32 + (w & 31);
        if (i4 < NH) {
            uint4 a = usrc[i4];
            unsigned k[4] = {a.x, a.y, a.z, a.w};
#pragma unroll
            for (int j = 0; j < 4; j++) {
                if (k[j] <= Mkey) {
                    unsigned s = atomicAdd(&s_candcnt, 1u);
                    if (s < SEL_CAP) cand[s] = ((u64)k[j] << 32) | (unsigned)(i4 * 4 + j);
                }
            }
        }
    }
    __syncthreads();

    unsigned Tkey;
    const unsigned candTotal = s_candcnt;

    if (candTotal <= SEL_CAP) {
        const int cc = (int)candTotal;
        for (int i = tid; i < 4096; i += SEL_THREADS) hist[i] = 0;
        __syncthreads();
        for (int i = tid; i < cc; i += SEL_THREADS)
            atomicAdd(&hist[(unsigned)(cand[i] >> 52)], 1u);
        __syncthreads();
        find_kth(hist, 4096, KNN, tid, &s_bin, &s_kthr);
        __syncthreads();
        const unsigned pfx = s_bin;
        const unsigned k1v = s_kthr;
        for (int i = tid; i < 4096; i += SEL_THREADS) hist[i] = 0;
        __syncthreads();
        for (int i = tid; i < cc; i += SEL_THREADS) {
            unsigned key = (unsigned)(cand[i] >> 32);
            if ((key >> 20) == pfx) atomicAdd(&hist[(key >> 8) & 0xFFFu], 1u);
        }
        __syncthreads();
        find_kth(hist, 4096, k1v, tid, &s_bin, &s_kthr);
        __syncthreads();
        const unsigned pfx20 = (pfx << 12) | s_bin;
        const unsigned k2v = s_kthr;
        for (int i = tid; i < 256; i += SEL_THREADS) hist[i] = 0;
        __syncthreads();
        for (int i = tid; i < cc; i += SEL_THREADS) {
            unsigned key = (unsigned)(cand[i] >> 32);
            if ((key >> 8) == pfx20) atomicAdd(&hist[key & 0xFFu], 1u);
        }
        __syncthreads();
        find_kth(hist, 256, k2v, tid, &s_bin, &s_kthr);
        __syncthreads();
        Tkey = (pfx20 << 8) | s_bin;
        for (int i = tid; i < cc; i += SEL_THREADS) {
            u64 cv = cand[i];
            unsigned key = (unsigned)(cv >> 32);
            if (key < Tkey) {
                unsigned s = atomicAdd(&s_selcnt, 1u);
                if (s < 128) sel[s] = cv;
            } else if (key == Tkey) {
                unsigned s = atomicAdd(&s_tiecnt, 1u);
                if (s < 128) ties[s] = cv;
            }
        }
        __syncthreads();
    } else {
        for (int i = tid; i < 4096; i += SEL_THREADS) hist[i] = 0;
        __syncthreads();
        for (int w = tid; w < ntl * 32; w += SEL_THREADS) {
            int t = tlist[w >> 5];
            int i4 = t * 32 + (w & 31);
            uint4 a = (i4 < NH) ? usrc[i4] : make_uint4(~0u, ~0u, ~0u, ~0u);
            unsigned k[4] = {a.x, a.y, a.z, a.w};
#pragma unroll
            for (int j = 0; j < 4; j++) {
                unsigned bin = (k[j] <= Mkey) ? (k[j] >> 20) : 0xFFFFFFFFu;
                unsigned grp = __match_any_sync(0xFFFFFFFFu, bin);
                if (bin != 0xFFFFFFFFu && lane == __ffs(grp) - 1)
                    atomicAdd(&hist[bin], (unsigned)__popc(grp));
            }
        }
        __syncthreads();
        find_kth(hist, 4096, KNN, tid, &s_bin, &s_kthr);
        __syncthreads();
        const unsigned pfx = s_bin;
        const unsigned k1v = s_kthr;

        for (int i = tid; i < 4096; i += SEL_THREADS) hist[i] = 0;
        __syncthreads();
        for (int w = tid; w < ntl * 32; w += SEL_THREADS) {
            int t = tlist[w >> 5];
            int i4 = t * 32 + (w & 31);
            uint4 a = (i4 < NH) ? usrc[i4] : make_uint4(~0u, ~0u, ~0u, ~0u);
            unsigned k[4] = {a.x, a.y, a.z, a.w};
#pragma unroll
            for (int j = 0; j < 4; j++) {
                unsigned bin = (k[j] <= Mkey && (k[j] >> 20) == pfx)
                               ? ((k[j] >> 8) & 0xFFFu) : 0xFFFFFFFFu;
                unsigned grp = __match_any_sync(0xFFFFFFFFu, bin);
                if (bin != 0xFFFFFFFFu && lane == __ffs(grp) - 1)
                    atomicAdd(&hist[bin], (unsigned)__popc(grp));
            }
        }
        __syncthreads();
        find_kth(hist, 4096, k1v, tid, &s_bin, &s_kthr);
        __syncthreads();
        const unsigned pfx20 = (pfx << 12) | s_bin;
        const unsigned k2v = s_kthr;

        for (int i = tid; i < 256; i += SEL_THREADS) hist[i] = 0;
        __syncthreads();
        for (int w = tid; w < ntl * 32; w += SEL_THREADS) {
            int t = tlist[w >> 5];
            int i4 = t * 32 + (w & 31);
            uint4 a = (i4 < NH) ? usrc[i4] : make_uint4(~0u, ~0u, ~0u, ~0u);
            unsigned k[4] = {a.x, a.y, a.z, a.w};
#pragma unroll
            for (int j = 0; j < 4; j++) {
                unsigned bin = (k[j] <= Mkey && (k[j] >> 8) == pfx20)
                               ? (k[j] & 0xFFu) : 0xFFFFFFFFu;
                unsigned grp = __match_any_sync(0xFFFFFFFFu, bin);
                if (bin != 0xFFFFFFFFu && lane == __ffs(grp) - 1)
                    atomicAdd(&hist[bin], (unsigned)__popc(grp));
            }
        }
        __syncthreads();
        find_kth(hist, 256, k2v, tid, &s_bin, &s_kthr);
        __syncthreads();
        Tkey = (pfx20 << 8) | s_bin;

        for (int w = tid; w < ntl * 32; w += SEL_THREADS) {
            int t = tlist[w >> 5];
            int i4 = t * 32 + (w & 31);
            if (i4 < NH) {
                uint4 a = usrc[i4];
                unsigned k[4] = {a.x, a.y, a.z, a.w};
#pragma unroll
                for (int j = 0; j < 4; j++) {
                    if (k[j] < Tkey) {
                        unsigned s = atomicAdd(&s_selcnt, 1u);
                        if (s < 128) sel[s] = ((u64)k[j] << 32) | (unsigned)(i4 * 4 + j);
                    } else if (k[j] == Tkey) {
                        unsigned s = atomicAdd(&s_tiecnt, 1u);
                        if (s < 128) ties[s] = ((u64)k[j] << 32) | (unsigned)(i4 * 4 + j);
                    }
                }
            }
        }
        __syncthreads();
    }

    const int ns = min((int)s_selcnt, 128);
    const int ne = min((int)s_tiecnt, 128);

    if (tid < ns) {
        u64 mine = sel[tid];
        unsigned my_idx = (unsigned)(mine & 0xFFFFFFFFu);
        int rank = 0;
        for (int j = 0; j < ns; j++) rank += ((unsigned)(sel[j] & 0xFFFFFFFFu) < my_idx);
        float d2 = __uint_as_float((unsigned)(mine >> 32));
        s_w[rank] = (d2 > 0.f) ? __fdiv_rn(1.0f, __fsqrt_rn(d2)) : 0.f;
        s_lab[rank] = labels[my_idx];
    }
    if (tid >= 128 && tid - 128 < ne) {
        int t = tid - 128;
        unsigned my_idx = (unsigned)(ties[t] & 0xFFFFFFFFu);
        int rank = 0;
        for (int j = 0; j < ne; j++) rank += ((unsigned)(ties[j] & 0xFFFFFFFFu) < my_idx);
        tlab[rank] = labels[my_idx];
    }
    __syncthreads();

    if (tid == 0) {
        float cls[NL];
#pragma unroll
        for (int l = 0; l < NL; l++) cls[l] = 0.f;
        float stot = 0.f;
        for (int j = 0; j < ns; j++) { stot += s_w[j]; cls[s_lab[j]] += s_w[j]; }
        int need = KNN - ns;
        float d2T = __uint_as_float(Tkey);
        float wT = (d2T > 0.f) ? __fdiv_rn(1.0f, __fsqrt_rn(d2T)) : 0.f;
        int m = (need < ne) ? need : ne;
        for (int j = 0; j < m; j++) { stot += wT; cls[tlab[j]] += wT; }
#pragma unroll
        for (int l = 0; l < NL; l++) {
            float val = stot - cls[l];
            size_t o = (size_t)b * NL + l;
            if (init) total[o] = val; else total[o] += val;
        }
    }
}

// ---------------------------------------------------------------------------
// Layer-4 select: d2 recomputed inline from t4 (no d2 matrix).
// ---------------------------------------------------------------------------
__global__ void __launch_bounds__(SEL_THREADS)
select4_kernel(const float* __restrict__ q4, const float* __restrict__ t4,
               const float* __restrict__ gmin, const int* __restrict__ labels,
               float* __restrict__ total)
{
    extern __shared__ __align__(16) char sms[];
    unsigned* hist = (unsigned*)sms;
    u64* cand  = (u64*)(sms + OFF_CAND);
    u64* sel   = (u64*)(sms + OFF_SEL);
    u64* ties  = (u64*)(sms + OFF_TIES);
    int* tlab  = (int*)(sms + OFF_TLAB);
    float* mins = (float*)(sms + OFF_MINS);
    int* tlist = (int*)(sms + OFF_TLIST);

    __shared__ unsigned s_M75, s_bin, s_kthr, s_candcnt, s_selcnt, s_tiecnt, s_ntiles;
    __shared__ float s_w[80];
    __shared__ int s_lab[80];
    __shared__ float s_q[8];

    const int b = blockIdx.x, tid = threadIdx.x, lane = tid & 31;

    if (tid < 8) s_q[tid] = q4[(size_t)b * 8 + tid];
    for (int i = tid; i < NTILES; i += SEL_THREADS)
        mins[i] = gmin[(size_t)b * NTILES + i];
    if (tid == 0) { s_candcnt = 0; s_selcnt = 0; s_tiecnt = 0; s_ntiles = 0; }
    __syncthreads();

    float q[8];
#pragma unroll
    for (int j = 0; j < 8; j++) q[j] = s_q[j];
    const float qq = l4_qq(q);

    if (tid < NTILES) {
        unsigned key = __float_as_uint(mins[tid]);
        int c = 0;
        for (int j = 0; j < NTILES; j++) {
            unsigned kj = __float_as_uint(mins[j]);
            c += (kj < key) || (kj == key && j < tid);
        }
        if (c == KNN - 1) s_M75 = key;
    }
    __syncthreads();
    unsigned Mkey = s_M75;

    if (tid < NTILES) {
        if (__float_as_uint(mins[tid]) <= Mkey) {
            unsigned s = atomicAdd(&s_ntiles, 1u);
            tlist[s] = tid;
        }
    }
    __syncthreads();
    int ntl = (int)s_ntiles;

    for (int w = tid; w < ntl * 128; w += SEL_THREADS) {
        int row = tlist[w >> 7] * 128 + (w & 127);
        if (row < NT) {
            unsigned key = __float_as_uint(l4_d2f(t4 + (size_t)row * 8, q, qq));
            if (key <= Mkey) {
                unsigned s = atomicAdd(&s_candcnt, 1u);
                if (s < SEL_CAP) cand[s] = ((u64)key << 32) | (unsigned)row;
            }
        }
    }
    __syncthreads();

    unsigned candTotal = s_candcnt;
    if (candTotal < KNN) {
        __syncthreads();
        if (tid < NTILES) tlist[tid] = tid;
        if (tid == 0) s_ntiles = NTILES;
        __syncthreads();
        ntl = NTILES;
        Mkey = 0xFFFFFFFFu;
        candTotal = SEL_CAP + 1;
    }

    unsigned Tkey;
    if (candTotal <= SEL_CAP) {
        const int cc = (int)candTotal;
        for (int i = tid; i < 4096; i += SEL_THREADS) hist[i] = 0;
        __syncthreads();
        for (int i = tid; i < cc; i += SEL_THREADS)
            atomicAdd(&hist[(unsigned)(cand[i] >> 52)], 1u);
        __syncthreads();
        find_kth(hist, 4096, KNN, tid, &s_bin, &s_kthr);
        __syncthreads();
        const unsigned pfx = s_bin;
        const unsigned k1v = s_kthr;
        for (int i = tid; i < 4096; i += SEL_THREADS) hist[i] = 0;
        __syncthreads();
        for (int i = tid; i < cc; i += SEL_THREADS) {
            unsigned key = (unsigned)(cand[i] >> 32);
            if ((key >> 20) == pfx) atomicAdd(&hist[(key >> 8) & 0xFFFu], 1u);
        }
        __syncthreads();
        find_kth(hist, 4096, k1v, tid, &s_bin, &s_kthr);
        __syncthreads();
        const unsigned pfx20 = (pfx << 12) | s_bin;
        const unsigned k2v = s_kthr;
        for (int i = tid; i < 256; i += SEL_THREADS) hist[i] = 0;
        __syncthreads();
        for (int i = tid; i < cc; i += SEL_THREADS) {
            unsigned key = (unsigned)(cand[i] >> 32);
            if ((key >> 8) == pfx20) atomicAdd(&hist[key & 0xFFu], 1u);
        }
        __syncthreads();
        find_kth(hist, 256, k2v, tid, &s_bin, &s_kthr);
        __syncthreads();
        Tkey = (pfx20 << 8) | s_bin;
        for (int i = tid; i < cc; i += SEL_THREADS) {
            u64 cv = cand[i];
            unsigned key = (unsigned)(cv >> 32);
            if (key < Tkey) {
                unsigned s = atomicAdd(&s_selcnt, 1u);
                if (s < 128) sel[s] = cv;
            } else if (key == Tkey) {
                unsigned s = atomicAdd(&s_tiecnt, 1u);
                if (s < 128) ties[s] = cv;
            }
        }
        __syncthreads();
    } else {
        for (int i = tid; i < 4096; i += SEL_THREADS) hist[i] = 0;
        __syncthreads();
        for (int w = tid; w < ntl * 128; w += SEL_THREADS) {
            int row = tlist[w >> 7] * 128 + (w & 127);
            unsigned bin = 0xFFFFFFFFu;
            if (row < NT) {
                unsigned key = __float_as_uint(l4_d2f(t4 + (size_t)row * 8, q, qq));
                if (key <= Mkey) bin = key >> 20;
            }
            unsigned grp = __match_any_sync(0xFFFFFFFFu, bin);
            if (bin != 0xFFFFFFFFu && lane == __ffs(grp) - 1)
                atomicAdd(&hist[bin], (unsigned)__popc(grp));
        }
        __syncthreads();
        find_kth(hist, 4096, KNN, tid, &s_bin, &s_kthr);
        __syncthreads();
        const unsigned pfx = s_bin;
        const unsigned k1v = s_kthr;

        for (int i = tid; i < 4096; i += SEL_THREADS) hist[i] = 0;
        __syncthreads();
        for (int w = tid; w < ntl * 128; w += SEL_THREADS) {
            int row = tlist[w >> 7] * 128 + (w & 127);
            unsigned bin = 0xFFFFFFFFu;
            if (row < NT) {
                unsigned key = __float_as_uint(l4_d2f(t4 + (size_t)row * 8, q, qq));
                if (key <= Mkey && (key >> 20) == pfx) bin = (key >> 8) & 0xFFFu;
            }
            unsigned grp = __match_any_sync(0xFFFFFFFFu, bin);
            if (bin != 0xFFFFFFFFu && lane == __ffs(grp) - 1)
                atomicAdd(&hist[bin], (unsigned)__popc(grp));
        }
        __syncthreads();
        find_kth(hist, 4096, k1v, tid, &s_bin, &s_kthr);
        __syncthreads();
        const unsigned pfx20 = (pfx << 12) | s_bin;
        const unsigned k2v = s_kthr;

        for (int i = tid; i < 256; i += SEL_THREADS) hist[i] = 0;
        __syncthreads();
        for (int w = tid; w < ntl * 128; w += SEL_THREADS) {
            int row = tlist[w >> 7] * 128 + (w & 127);
            unsigned bin = 0xFFFFFFFFu;
            if (row < NT) {
                unsigned key = __float_as_uint(l4_d2f(t4 + (size_t)row * 8, q, qq));
                if (key <= Mkey && (key >> 8) == pfx20) bin = key & 0xFFu;
            }
            unsigned grp = __match_any_sync(0xFFFFFFFFu, bin);
            if (bin != 0xFFFFFFFFu && lane == __ffs(grp) - 1)
                atomicAdd(&hist[bin], (unsigned)__popc(grp));
        }
        __syncthreads();
        find_kth(hist, 256, k2v, tid, &s_bin, &s_kthr);
        __syncthreads();
        Tkey = (pfx20 << 8) | s_bin;

        for (int w = tid; w < ntl * 128; w += SEL_THREADS) {
            int row = tlist[w >> 7] * 128 + (w & 127);
            if (row < NT) {
                unsigned key = __float_as_uint(l4_d2f(t4 + (size_t)row * 8, q, qq));
                if (key < Tkey) {
                    unsigned s = atomicAdd(&s_selcnt, 1u);
                    if (s < 128) sel[s] = ((u64)key << 32) | (unsigned)row;
                } else if (key == Tkey) {
                    unsigned s = atomicAdd(&s_tiecnt, 1u);
                    if (s < 128) ties[s] = ((u64)key << 32) | (unsigned)row;
                }
            }
        }
        __syncthreads();
    }

    const int ns = min((int)s_selcnt, 128);
    const int ne = min((int)s_tiecnt, 128);

    if (tid < ns) {
        u64 mine = sel[tid];
        unsigned my_idx = (unsigned)(mine & 0xFFFFFFFFu);
        int rank = 0;
        for (int j = 0; j < ns; j++) rank += ((unsigned)(sel[j] & 0xFFFFFFFFu) < my_idx);
        float d2 = __uint_as_float((unsigned)(mine >> 32));
        s_w[rank] = (d2 > 0.f) ? __fdiv_rn(1.0f, __fsqrt_rn(d2)) : 0.f;
        s_lab[rank] = labels[my_idx];
    }
    if (tid >= 128 && tid - 128 < ne) {
        int t = tid - 128;
        unsigned my_idx = (unsigned)(ties[t] & 0xFFFFFFFFu);
        int rank = 0;
        for (int j = 0; j < ne; j++) rank += ((unsigned)(ties[j] & 0xFFFFFFFFu) < my_idx);
        tlab[rank] = labels[my_idx];
    }
    __syncthreads();

    if (tid == 0) {
        float cls[NL];
#pragma unroll
        for (int l = 0; l < NL; l++) cls[l] = 0.f;
        float stot = 0.f;
        for (int j = 0; j < ns; j++) { stot += s_w[j]; cls[s_lab[j]] += s_w[j]; }
        int need = KNN - ns;
        float d2T = __uint_as_float(Tkey);
        float wT = (d2T > 0.f) ? __fdiv_rn(1.0f, __fsqrt_rn(d2T)) : 0.f;
        int m = (need < ne) ? need : ne;
        for (int j = 0; j < m; j++) { stot += wT; cls[tlab[j]] += wT; }
#pragma unroll
        for (int l = 0; l < NL; l++)
            total[(size_t)b * NL + l] += stot - cls[l];
    }
}

// ---------------------------------------------------------------------------
__global__ void __launch_bounds__(256)
pvalue_kernel(const float* __restrict__ total, const float* __restrict__ cali,
              float* __restrict__ out)
{
    const int b = blockIdx.x, tid = threadIdx.x;
    float t[NL];
#pragma unroll
    for (int l = 0; l < NL; l++) t[l] = total[(size_t)b * NL + l];
    int cnt[NL];
#pragma unroll
    for (int l = 0; l < NL; l++) cnt[l] = 0;
    for (int i = tid; i < NC; i += 256) {
        float c = cali[i];
#pragma unroll
        for (int l = 0; l < NL; l++) cnt[l] += (c >= t[l]) ? 1 : 0;
    }
    __shared__ int sc[NL];
    if (tid < NL) sc[tid] = 0;
    __syncthreads();
#pragma unroll
    for (int l = 0; l < NL; l++) atomicAdd(&sc[l], cnt[l]);
    __syncthreads();
    if (tid < NL) out[(size_t)b * NL + tid] = (float)sc[tid] * (1.0f / NC);
}

// ---------------------------------------------------------------------------
extern "C" void kernel_launch(void* const* d_in, const int* in_sizes, int n_in,
                              void* d_out, int out_size)
{
    const float* x        = (const float*)d_in[0];
    const float* train_x  = (const float*)d_in[1];
    const int*   lab      = (const int*)  d_in[2];
    const float* cali     = (const float*)d_in[3];
    const float* W1 = (const float*)d_in[4];  const float* b1 = (const float*)d_in[5];
    const float* W2 = (const float*)d_in[6];  const float* b2 = (const float*)d_in[7];
    const float* W3 = (const float*)d_in[8];  const float* b3 = (const float*)d_in[9];
    const float* W4 = (const float*)d_in[10]; const float* b4 = (const float*)d_in[11];
    float* out = (float*)d_out;

    float *h1p, *h2p, *h3p, *q4p, *t3p, *t4p, *d2ap, *d2bp, *qnp, *tnp, *totp, *minall;
    __nv_bfloat16 *qhip, *qlop, *thip, *tlop, *thi2p, *tlo2p;
    __nv_bfloat16 *w1th, *w1tl, *w2th, *w2tl, *w3th, *w3tl;
    cudaGetSymbolAddress((void**)&h1p, g_h1);
    cudaGetSymbolAddress((void**)&h2p, g_h2);
    cudaGetSymbolAddress((void**)&h3p, g_h3);
    cudaGetSymbolAddress((void**)&q4p, g_q4);
    cudaGetSymbolAddress((void**)&t3p, g_t3);
    cudaGetSymbolAddress((void**)&t4p, g_t4);
    cudaGetSymbolAddress((void**)&d2ap, g_d2a);
    cudaGetSymbolAddress((void**)&d2bp, g_d2b);
    cudaGetSymbolAddress((void**)&minall, g_minall);
    cudaGetSymbolAddress((void**)&qnp, g_qn);
    cudaGetSymbolAddress((void**)&tnp, g_tn);
    cudaGetSymbolAddress((void**)&totp, g_tot);
    cudaGetSymbolAddress((void**)&qhip, g_qhi);
    cudaGetSymbolAddress((void**)&qlop, g_qlo);
    cudaGetSymbolAddress((void**)&thip, g_thi);
    cudaGetSymbolAddress((void**)&tlop, g_tlo);
    cudaGetSymbolAddress((void**)&thi2p, g_thi2);
    cudaGetSymbolAddress((void**)&tlo2p, g_tlo2);
    cudaGetSymbolAddress((void**)&w1th, g_w1th);
    cudaGetSymbolAddress((void**)&w1tl, g_w1tl);
    cudaGetSymbolAddress((void**)&w2th, g_w2th);
    cudaGetSymbolAddress((void**)&w2tl, g_w2tl);
    cudaGetSymbolAddress((void**)&w3th, g_w3th);
    cudaGetSymbolAddress((void**)&w3tl, g_w3tl);

    float* minL[5];
    for (int i = 0; i < 5; i++) minL[i] = minall + (size_t)i * BQ * NTILES;

    cudaFuncSetAttribute(select_kernel,
                         cudaFuncAttributeMaxDynamicSharedMemorySize, SEL_SMEM);
    cudaFuncSetAttribute(select4_kernel,
                         cudaFuncAttributeMaxDynamicSharedMemorySize, SEL_SMEM);
    cudaFuncSetAttribute(mma_dist_kernel,
                         cudaFuncAttributeMaxDynamicSharedMemorySize, MD_SMEM);

    cudaStream_t s2 = g_ok ? g_s2 : (cudaStream_t)0;
#define FORK(i)  do { if (g_ok) { cudaEventRecord(g_evF[i], 0); cudaStreamWaitEvent(s2, g_evF[i], 0); } } while (0)
#define JOIN(i)  do { if (g_ok) { cudaEventRecord(g_evJ[i], s2); } } while (0)
#define WAITJ(i) do { if (g_ok) { cudaStreamWaitEvent(0, g_evJ[i], 0); } } while (0)

    dim3 tb(16, 16);
    const int D0 = 83;
    const dim3 mgrid(NTILES, BQ / 256);

    conv_norm_kernel<<<BQ / 8, 256>>>(x, qhip, qlop, qnp, BQ, D0);
    conv_norm_kernel<<<NTP / 8, 256>>>(train_x, thip, tlop, tnp, NT, D0);
    wt_convert_kernel<<<(3 * 128 * 128 + 255) / 256, 256>>>(W1, W2, W3);

    // query-side MLP (independent of dist/select chain)
    linear_relu_kernel<<<BQ / 64, tb>>>(x,   W1, b1, h1p, BQ, D0);
    linear_relu_kernel<<<BQ / 64, tb>>>(h1p, W2, b2, h2p, BQ, HD);
    linear_relu_kernel<<<BQ / 64, tb>>>(h2p, W3, b3, h3p, BQ, HD);
    linear_softmax_kernel<<<(BQ + 7) / 8, 256>>>(h3p, W4, b4, q4p, BQ);

    // layer 0 -> d2A
    mma_dist_kernel<<<mgrid, 512, MD_SMEM>>>(qhip, qlop, thip, tlop, qnp, tnp,
                                             d2ap, minL[0], 6);
    FORK(0);
    select_kernel<<<BQ, SEL_THREADS, SEL_SMEM, s2>>>(d2ap, minL[0], lab, totp, 1);
    JOIN(0);

    // layer 1 -> d2B (overlaps with select L0 on s2)
    mma_linear_kernel<<<NTILES, 256>>>(thip, tlop, w1th, w1tl, b1,
                                       thi2p, tlo2p, tnp, (float*)0, 6);
    conv_norm_kernel<<<BQ / 8, 256>>>(h1p, qhip, qlop, qnp, BQ, HD);
    mma_dist_kernel<<<mgrid, 512, MD_SMEM>>>(qhip, qlop, thi2p, tlo2p, qnp, tnp,
                                             d2bp, minL[1], 8);
    FORK(1);
    select_kernel<<<BQ, SEL_THREADS, SEL_SMEM, s2>>>(d2bp, minL[1], lab, totp, 0);
    JOIN(1);

    // layer 2 -> d2A (must wait select L0)
    mma_linear_kernel<<<NTILES, 256>>>(thi2p, tlo2p, w2th, w2tl, b2,
                                       thip, tlop, tnp, (float*)0, 8);
    conv_norm_kernel<<<BQ / 8, 256>>>(h2p, qhip, qlop, qnp, BQ, HD);
    WAITJ(0);
    mma_dist_kernel<<<mgrid, 512, MD_SMEM>>>(qhip, qlop, thip, tlop, qnp, tnp,
                                             d2ap, minL[2], 8);
    FORK(2);
    select_kernel<<<BQ, SEL_THREADS, SEL_SMEM, s2>>>(d2ap, minL[2], lab, totp, 0);
    JOIN(2);

    // layer 3 -> d2B (must wait select L1)
    mma_linear_kernel<<<NTILES, 256>>>(thip, tlop, w3th, w3tl, b3,
                                       thi2p, tlo2p, tnp, t3p, 8);
    conv_norm_kernel<<<BQ / 8, 256>>>(h3p, qhip, qlop, qnp, BQ, HD);
    WAITJ(1);
    mma_dist_kernel<<<mgrid, 512, MD_SMEM>>>(qhip, qlop, thi2p, tlo2p, qnp, tnp,
                                             d2bp, minL[3], 8);
    FORK(3);
    select_kernel<<<BQ, SEL_THREADS, SEL_SMEM, s2>>>(d2bp, minL[3], lab, totp, 0);
    JOIN(3);

    // layer 4 (d2-free) — overlaps with select L3
    linear_softmax_kernel<<<(NT + 7) / 8, 256>>>(t3p, W4, b4, t4p, NT);
    min4_kernel<<<dim3(NTILES, BQ / 128), 256>>>(q4p, t4p, minL[4]);
    FORK(4);
    select4_kernel<<<BQ, SEL_THREADS, SEL_SMEM, s2>>>(q4p, t4p, minL[4], lab, totp);
    JOIN(4);

    WAITJ(4);   // s2 is in-order: J4 implies all selects done
    pvalue_kernel<<<BQ, 256>>>(totp, cali, out);

#undef FORK
#undef JOIN
#undef WAITJ
}

// round 16
// speedup vs baseline: 1.1908x; 1.0841x over previous
#include <cuda_runtime.h>
#include <cuda_bf16.h>
#include <math.h>
#include <stdint.h>

#define BQ   1024
#define NT   50000
#define NTP  50048
#define NL   8
#define KNN  75
#define HD   128
#define NC   10000
#define NTILES 391          // NTP/128

typedef unsigned long long u64;

// ---------------- device scratch ----------------
__device__ float g_h1[BQ * HD];
__device__ float g_h2[BQ * HD];
__device__ float g_h3[BQ * HD];
__device__ float g_q4[BQ * NL];
__device__ float g_t3[(size_t)NT * HD];
__device__ float g_t4[(size_t)NT * NL];
__device__ float g_d2a[(size_t)BQ * NT];
__device__ float g_d2b[(size_t)BQ * NT];
__device__ float g_minall[(size_t)5 * BQ * NTILES];
__device__ float g_qnA[BQ], g_qnB[BQ];
__device__ float g_tnA[NT], g_tnB[NT];
__device__ float g_tot[BQ * NL];
__device__ __nv_bfloat16 g_qhiA[(size_t)BQ * 128], g_qloA[(size_t)BQ * 128];
__device__ __nv_bfloat16 g_qhiB[(size_t)BQ * 128], g_qloB[(size_t)BQ * 128];
__device__ __nv_bfloat16 g_thi[(size_t)NTP * 128];    // bank A
__device__ __nv_bfloat16 g_tlo[(size_t)NTP * 128];
__device__ __nv_bfloat16 g_thi2[(size_t)NTP * 128];   // bank B
__device__ __nv_bfloat16 g_tlo2[(size_t)NTP * 128];
__device__ __nv_bfloat16 g_w1th[128 * 128], g_w1tl[128 * 128];
__device__ __nv_bfloat16 g_w2th[128 * 128], g_w2tl[128 * 128];
__device__ __nv_bfloat16 g_w3th[128 * 128], g_w3tl[128 * 128];

// ---------------- overlap machinery (created once at load; no device mem) ----
static cudaStream_t g_s2 = 0, g_s3 = 0;
static cudaEvent_t g_ev[16];
static bool g_ok = false;
namespace {
enum { EV_PREP = 0, EV_D0, EV_D1, EV_D2, EV_D3,
       EV_S3A, EV_S3B, EV_S3C, EV_S3D,
       EV_J0, EV_J1, EV_J4, EV_COUNT };
struct StreamInit {
    StreamInit() {
        if (cudaStreamCreateWithFlags(&g_s2, cudaStreamNonBlocking) != cudaSuccess) return;
        if (cudaStreamCreateWithFlags(&g_s3, cudaStreamNonBlocking) != cudaSuccess) return;
        bool ok = true;
        for (int i = 0; i < EV_COUNT; i++)
            ok = ok && (cudaEventCreateWithFlags(&g_ev[i], cudaEventDisableTiming) == cudaSuccess);
        g_ok = ok;
    }
};
StreamInit g_si;
}

// ---------------------------------------------------------------------------
__device__ __forceinline__ void mma_bf16(float* d, const uint32_t* a, const uint32_t* b)
{
    asm volatile(
        "mma.sync.aligned.m16n8k16.row.col.f32.bf16.bf16.f32 "
        "{%0,%1,%2,%3}, {%4,%5,%6,%7}, {%8,%9}, {%0,%1,%2,%3};"
        : "+f"(d[0]), "+f"(d[1]), "+f"(d[2]), "+f"(d[3])
        : "r"(a[0]), "r"(a[1]), "r"(a[2]), "r"(a[3]), "r"(b[0]), "r"(b[1]));
}

#define SLICE_ELEMS (128 * 24)

__device__ __forceinline__ void slice_load_async(
    const __nv_bfloat16* __restrict__ Gp, __nv_bfloat16* Ss,
    int row0, int k0, int lr, int lh)
{
    uint32_t sa = (uint32_t)__cvta_generic_to_shared(Ss + lr * 24 + lh * 8);
    const void* ga = Gp + (size_t)(row0 + lr) * 128 + k0 + lh * 8;
    asm volatile("cp.async.cg.shared.global [%0], [%1], 16;\n" :: "r"(sa), "l"(ga));
}

// ---------------------------------------------------------------------------
// Layer-4 exact d2 helpers (fixed op order, shared by min4 / select4).
// ---------------------------------------------------------------------------
__device__ __forceinline__ float l4_qq(const float* q)
{
    float s = __fmul_rn(q[0], q[0]);
    s = __fmaf_rn(q[1], q[1], s); s = __fmaf_rn(q[2], q[2], s);
    s = __fmaf_rn(q[3], q[3], s); s = __fmaf_rn(q[4], q[4], s);
    s = __fmaf_rn(q[5], q[5], s); s = __fmaf_rn(q[6], q[6], s);
    s = __fmaf_rn(q[7], q[7], s);
    return s;
}
__device__ __forceinline__ float l4_d2f(const float* __restrict__ tr,
                                        const float* q, float qq)
{
    float tt = __fmul_rn(tr[0], tr[0]);
    tt = __fmaf_rn(tr[1], tr[1], tt); tt = __fmaf_rn(tr[2], tr[2], tt);
    tt = __fmaf_rn(tr[3], tr[3], tt); tt = __fmaf_rn(tr[4], tr[4], tt);
    tt = __fmaf_rn(tr[5], tr[5], tt); tt = __fmaf_rn(tr[6], tr[6], tt);
    tt = __fmaf_rn(tr[7], tr[7], tt);
    float dt = __fmul_rn(q[0], tr[0]);
    dt = __fmaf_rn(q[1], tr[1], dt); dt = __fmaf_rn(q[2], tr[2], dt);
    dt = __fmaf_rn(q[3], tr[3], dt); dt = __fmaf_rn(q[4], tr[4], dt);
    dt = __fmaf_rn(q[5], tr[5], dt); dt = __fmaf_rn(q[6], tr[6], dt);
    dt = __fmaf_rn(q[7], tr[7], dt);
    return fmaxf(__fmaf_rn(-2.f, dt, __fadd_rn(qq, tt)), 0.f);
}

// ---------------------------------------------------------------------------
__global__ void __launch_bounds__(256)
conv_norm_kernel(const float* __restrict__ A, __nv_bfloat16* __restrict__ hi,
                 __nv_bfloat16* __restrict__ lo, float* __restrict__ nrm,
                 int Mreal, int D)
{
    int warp = threadIdx.x >> 5, lane = threadIdx.x & 31;
    int row = blockIdx.x * 8 + warp;
    int base = lane * 4;

    float ss = 0.f;
    __nv_bfloat16 hb[4], lb[4];
#pragma unroll
    for (int j = 0; j < 4; j++) {
        int col = base + j;
        float v = (row < Mreal && col < D) ? A[(size_t)row * D + col] : 0.f;
        ss += v * v;
        hb[j] = __float2bfloat16_rn(v);
        lb[j] = __float2bfloat16_rn(v - __bfloat162float(hb[j]));
    }
    __nv_bfloat162 h01, h23, l01, l23;
    h01.x = hb[0]; h01.y = hb[1]; h23.x = hb[2]; h23.y = hb[3];
    l01.x = lb[0]; l01.y = lb[1]; l23.x = lb[2]; l23.y = lb[3];
    *(__nv_bfloat162*)&hi[(size_t)row * 128 + base]     = h01;
    *(__nv_bfloat162*)&hi[(size_t)row * 128 + base + 2] = h23;
    *(__nv_bfloat162*)&lo[(size_t)row * 128 + base]     = l01;
    *(__nv_bfloat162*)&lo[(size_t)row * 128 + base + 2] = l23;

#pragma unroll
    for (int off = 16; off > 0; off >>= 1) ss += __shfl_down_sync(0xFFFFFFFFu, ss, off);
    if (lane == 0 && row < Mreal) nrm[row] = ss;
}

// ---------------------------------------------------------------------------
__global__ void __launch_bounds__(256)
wt_convert_kernel(const float* __restrict__ W1, const float* __restrict__ W2,
                  const float* __restrict__ W3)
{
    int idx = blockIdx.x * 256 + threadIdx.x;
    if (idx >= 3 * 128 * 128) return;
    int which = idx >> 14;
    int e = idx & 16383;
    int n = e & 127, k = e >> 7;
    const float* W = (which == 0) ? W1 : (which == 1) ? W2 : W3;
    int K = (which == 0) ? 83 : 128;
    float v = (k < K) ? W[(size_t)k * 128 + n] : 0.f;
    __nv_bfloat16 h = __float2bfloat16_rn(v);
    __nv_bfloat16 l = __float2bfloat16_rn(v - __bfloat162float(h));
    __nv_bfloat16* dh = (which == 0) ? g_w1th : (which == 1) ? g_w2th : g_w3th;
    __nv_bfloat16* dl = (which == 0) ? g_w1tl : (which == 1) ? g_w2tl : g_w3tl;
    dh[e] = h;
    dl[e] = l;
}

// ---------------------------------------------------------------------------
// bf16x3 GEMM mainloop (128-row tiles) - used by mma_linear_kernel.
// ---------------------------------------------------------------------------
__device__ __forceinline__ void gemm3_mainloop(
    const __nv_bfloat16* Ahi, const __nv_bfloat16* Alo,
    const __nv_bfloat16* Bhi, const __nv_bfloat16* Blo,
    __nv_bfloat16* smem, int m0, int n0, int nCh,
    int wm, int wn, int fr, int fc, int lr, int lh,
    float acc[2][8][4])
{
    __nv_bfloat16* AhiS[2] = {smem,                   smem + 4 * SLICE_ELEMS};
    __nv_bfloat16* AloS[2] = {smem + 1 * SLICE_ELEMS, smem + 5 * SLICE_ELEMS};
    __nv_bfloat16* BhiS[2] = {smem + 2 * SLICE_ELEMS, smem + 6 * SLICE_ELEMS};
    __nv_bfloat16* BloS[2] = {smem + 3 * SLICE_ELEMS, smem + 7 * SLICE_ELEMS};

    slice_load_async(Ahi, AhiS[0], m0, 0, lr, lh);
    slice_load_async(Alo, AloS[0], m0, 0, lr, lh);
    slice_load_async(Bhi, BhiS[0], n0, 0, lr, lh);
    slice_load_async(Blo, BloS[0], n0, 0, lr, lh);
    asm volatile("cp.async.commit_group;\n" ::: "memory");

    for (int c = 0; c < nCh; c++) {
        int buf = c & 1;
        if (c + 1 < nCh) {
            int k0 = (c + 1) * 16;
            slice_load_async(Ahi, AhiS[buf ^ 1], m0, k0, lr, lh);
            slice_load_async(Alo, AloS[buf ^ 1], m0, k0, lr, lh);
            slice_load_async(Bhi, BhiS[buf ^ 1], n0, k0, lr, lh);
            slice_load_async(Blo, BloS[buf ^ 1], n0, k0, lr, lh);
            asm volatile("cp.async.commit_group;\n" ::: "memory");
            asm volatile("cp.async.wait_group 1;" ::: "memory");
        } else {
            asm volatile("cp.async.wait_group 0;" ::: "memory");
        }
        __syncthreads();

        const __nv_bfloat16* Ah = AhiS[buf];
        const __nv_bfloat16* Al = AloS[buf];
        const __nv_bfloat16* Bh = BhiS[buf];
        const __nv_bfloat16* Bl = BloS[buf];

        uint32_t ah[2][4];
#pragma unroll
        for (int mt = 0; mt < 2; mt++) {
            int bm = wm + mt * 16;
            ah[mt][0] = *(const uint32_t*)&Ah[(bm + fr) * 24 + fc];
            ah[mt][1] = *(const uint32_t*)&Ah[(bm + fr + 8) * 24 + fc];
            ah[mt][2] = *(const uint32_t*)&Ah[(bm + fr) * 24 + fc + 8];
            ah[mt][3] = *(const uint32_t*)&Ah[(bm + fr + 8) * 24 + fc + 8];
        }
        uint32_t bh8[8][2];
#pragma unroll
        for (int nt = 0; nt < 8; nt++) {
            int nb = wn + nt * 8;
            bh8[nt][0] = *(const uint32_t*)&Bh[(nb + fr) * 24 + fc];
            bh8[nt][1] = *(const uint32_t*)&Bh[(nb + fr) * 24 + fc + 8];
        }
#pragma unroll
        for (int nt = 0; nt < 8; nt++) {
            mma_bf16(acc[0][nt], ah[0], bh8[nt]);
            mma_bf16(acc[1][nt], ah[1], bh8[nt]);
        }
        uint32_t al[2][4];
#pragma unroll
        for (int mt = 0; mt < 2; mt++) {
            int bm = wm + mt * 16;
            al[mt][0] = *(const uint32_t*)&Al[(bm + fr) * 24 + fc];
            al[mt][1] = *(const uint32_t*)&Al[(bm + fr + 8) * 24 + fc];
            al[mt][2] = *(const uint32_t*)&Al[(bm + fr) * 24 + fc + 8];
            al[mt][3] = *(const uint32_t*)&Al[(bm + fr + 8) * 24 + fc + 8];
        }
#pragma unroll
        for (int nt = 0; nt < 8; nt++) {
            mma_bf16(acc[0][nt], al[0], bh8[nt]);
            mma_bf16(acc[1][nt], al[1], bh8[nt]);
        }
#pragma unroll
        for (int nt = 0; nt < 8; nt++) {
            int nb = wn + nt * 8;
            uint32_t bl[2];
            bl[0] = *(const uint32_t*)&Bl[(nb + fr) * 24 + fc];
            bl[1] = *(const uint32_t*)&Bl[(nb + fr) * 24 + fc + 8];
            mma_bf16(acc[0][nt], ah[0], bl);
            mma_bf16(acc[1][nt], ah[1], bl);
        }
        __syncthreads();
    }
}

// ---------------------------------------------------------------------------
// 256x128 distance GEMM, 512 threads, 3-stage pipeline, 1 sync per chunk.
// ---------------------------------------------------------------------------
#define ASL (256 * 24)
#define BSL (128 * 24)
#define STAGE_ELEMS (2 * ASL + 2 * BSL)
#define MD_SMEM (3 * STAGE_ELEMS * 2)

__global__ void __launch_bounds__(512, 1)
mma_dist_kernel(const __nv_bfloat16* __restrict__ Qhi, const __nv_bfloat16* __restrict__ Qlo,
                const __nv_bfloat16* __restrict__ Thi, const __nv_bfloat16* __restrict__ Tlo,
                const float* __restrict__ qn, const float* __restrict__ tn,
                float* __restrict__ out, float* __restrict__ gmin, int nCh)
{
    extern __shared__ __align__(16) __nv_bfloat16 dsm[];
    __shared__ float sMin[256][2];
    const int tid = threadIdx.x;
    const int wid = tid >> 5, lane = tid & 31;
    const int n0 = blockIdx.x * 128;
    const int m0 = blockIdx.y * 256;
    const int wm = (wid & 7) * 32;
    const int wn = (wid >> 3) * 64;
    const int fr = lane >> 2, fc = (lane & 3) * 2;
    const int ar = tid >> 1, ah2 = tid & 1;
    const int br = (tid & 255) >> 1, bh2 = tid & 1;

    float acc[2][8][4];
#pragma unroll
    for (int mt = 0; mt < 2; mt++)
#pragma unroll
        for (int nt = 0; nt < 8; nt++)
#pragma unroll
            for (int j = 0; j < 4; j++) acc[mt][nt][j] = 0.f;

#define LOAD_STAGE(s, k0) do {                                                  \
        __nv_bfloat16* sb_ = dsm + (s) * STAGE_ELEMS;                           \
        slice_load_async(Qhi, sb_,            m0, (k0), ar, ah2);               \
        slice_load_async(Qlo, sb_ + ASL,      m0, (k0), ar, ah2);               \
        if (tid < 256) slice_load_async(Thi, sb_ + 2 * ASL,      n0, (k0), br, bh2); \
        else           slice_load_async(Tlo, sb_ + 2 * ASL + BSL, n0, (k0), br, bh2); \
        asm volatile("cp.async.commit_group;\n" ::: "memory");                  \
    } while (0)

    LOAD_STAGE(0, 0);
    if (nCh > 1) LOAD_STAGE(1, 16);

    for (int c = 0; c < nCh; c++) {
        if (c + 1 < nCh) asm volatile("cp.async.wait_group 1;" ::: "memory");
        else             asm volatile("cp.async.wait_group 0;" ::: "memory");
        __syncthreads();
        if (c + 2 < nCh) LOAD_STAGE((c + 2) % 3, (c + 2) * 16);

        const __nv_bfloat16* sb = dsm + (c % 3) * STAGE_ELEMS;
        const __nv_bfloat16* Ah = sb;
        const __nv_bfloat16* Al = sb + ASL;
        const __nv_bfloat16* Bh = sb + 2 * ASL;
        const __nv_bfloat16* Bl = sb + 2 * ASL + BSL;

        uint32_t ah[2][4];
#pragma unroll
        for (int mt = 0; mt < 2; mt++) {
            int bm = wm + mt * 16;
            ah[mt][0] = *(const uint32_t*)&Ah[(bm + fr) * 24 + fc];
            ah[mt][1] = *(const uint32_t*)&Ah[(bm + fr + 8) * 24 + fc];
            ah[mt][2] = *(const uint32_t*)&Ah[(bm + fr) * 24 + fc + 8];
            ah[mt][3] = *(const uint32_t*)&Ah[(bm + fr + 8) * 24 + fc + 8];
        }
        uint32_t bh8[8][2];
#pragma unroll
        for (int nt = 0; nt < 8; nt++) {
            int nb = wn + nt * 8;
            bh8[nt][0] = *(const uint32_t*)&Bh[(nb + fr) * 24 + fc];
            bh8[nt][1] = *(const uint32_t*)&Bh[(nb + fr) * 24 + fc + 8];
        }
#pragma unroll
        for (int nt = 0; nt < 8; nt++) {
            mma_bf16(acc[0][nt], ah[0], bh8[nt]);
            mma_bf16(acc[1][nt], ah[1], bh8[nt]);
        }
        uint32_t al[2][4];
#pragma unroll
        for (int mt = 0; mt < 2; mt++) {
            int bm = wm + mt * 16;
            al[mt][0] = *(const uint32_t*)&Al[(bm + fr) * 24 + fc];
            al[mt][1] = *(const uint32_t*)&Al[(bm + fr + 8) * 24 + fc];
            al[mt][2] = *(const uint32_t*)&Al[(bm + fr) * 24 + fc + 8];
            al[mt][3] = *(const uint32_t*)&Al[(bm + fr + 8) * 24 + fc + 8];
        }
#pragma unroll
        for (int nt = 0; nt < 8; nt++) {
            mma_bf16(acc[0][nt], al[0], bh8[nt]);
            mma_bf16(acc[1][nt], al[1], bh8[nt]);
        }
#pragma unroll
        for (int nt = 0; nt < 8; nt++) {
            int nb = wn + nt * 8;
            uint32_t bl[2];
            bl[0] = *(const uint32_t*)&Bl[(nb + fr) * 24 + fc];
            bl[1] = *(const uint32_t*)&Bl[(nb + fr) * 24 + fc + 8];
            mma_bf16(acc[0][nt], ah[0], bl);
            mma_bf16(acc[1][nt], ah[1], bl);
        }
    }
#undef LOAD_STAGE

    const float FINF = __int_as_float(0x7F800000);
    float rmin[2][2] = {{FINF, FINF}, {FINF, FINF}};
#pragma unroll
    for (int mt = 0; mt < 2; mt++) {
        int mrow = m0 + wm + mt * 16 + fr;
        float q0 = qn[mrow], q1 = qn[mrow + 8];
#pragma unroll
        for (int nt = 0; nt < 8; nt++) {
            int n = n0 + wn + nt * 8 + fc;
            if (n < NT) {
                float t0 = tn[n], t1 = tn[n + 1];
                float2 o;
                o.x = fmaxf(q0 + t0 - 2.f * acc[mt][nt][0], 0.f);
                o.y = fmaxf(q0 + t1 - 2.f * acc[mt][nt][1], 0.f);
                *(float2*)&out[(size_t)mrow * NT + n] = o;
                rmin[mt][0] = fminf(rmin[mt][0], fminf(o.x, o.y));
                o.x = fmaxf(q1 + t0 - 2.f * acc[mt][nt][2], 0.f);
                o.y = fmaxf(q1 + t1 - 2.f * acc[mt][nt][3], 0.f);
                *(float2*)&out[(size_t)(mrow + 8) * NT + n] = o;
                rmin[mt][1] = fminf(rmin[mt][1], fminf(o.x, o.y));
            }
        }
    }
    __syncthreads();
#pragma unroll
    for (int mt = 0; mt < 2; mt++)
#pragma unroll
        for (int rr = 0; rr < 2; rr++) {
            float m = rmin[mt][rr];
            m = fminf(m, __shfl_xor_sync(0xFFFFFFFFu, m, 1));
            m = fminf(m, __shfl_xor_sync(0xFFFFFFFFu, m, 2));
            if ((lane & 3) == 0)
                sMin[wm + mt * 16 + rr * 8 + fr][wn >> 6] = m;
        }
    __syncthreads();
    if (tid < 256)
        gmin[(size_t)(m0 + tid) * NTILES + blockIdx.x] =
            fminf(sMin[tid][0], sMin[tid][1]);
}

// ---------------------------------------------------------------------------
__global__ void __launch_bounds__(256, 2)
mma_linear_kernel(const __nv_bfloat16* __restrict__ Ahi, const __nv_bfloat16* __restrict__ Alo,
                  const __nv_bfloat16* __restrict__ Wth, const __nv_bfloat16* __restrict__ Wtl,
                  const float* __restrict__ bias,
                  __nv_bfloat16* __restrict__ Ohi, __nv_bfloat16* __restrict__ Olo,
                  float* __restrict__ nrm, float* __restrict__ Ofp, int nCh)
{
    __shared__ __align__(16) __nv_bfloat16 smem[8 * SLICE_ELEMS];
    __shared__ float snorm[128];
    __shared__ float sbias[128];
    const int tid = threadIdx.x;
    const int wid = tid >> 5, lane = tid & 31;
    const int m0 = blockIdx.x * 128;
    const int wm = (wid & 3) * 32;
    const int wn = (wid >> 2) * 64;
    const int lr = tid >> 1, lh = tid & 1;
    const int fr = lane >> 2, fc = (lane & 3) * 2;

    if (tid < 128) { sbias[tid] = bias[tid]; snorm[tid] = 0.f; }

    float acc[2][8][4];
#pragma unroll
    for (int mt = 0; mt < 2; mt++)
#pragma unroll
        for (int nt = 0; nt < 8; nt++)
#pragma unroll
            for (int j = 0; j < 4; j++) acc[mt][nt][j] = 0.f;

    gemm3_mainloop(Ahi, Alo, Wth, Wtl, smem, m0, 0, nCh,
                   wm, wn, fr, fc, lr, lh, acc);

#pragma unroll
    for (int mt = 0; mt < 2; mt++) {
        int r0 = wm + mt * 16 + fr;
        int r1 = r0 + 8;
        size_t g0 = (size_t)(m0 + r0) * 128;
        size_t g1 = (size_t)(m0 + r1) * 128;
        float ns0 = 0.f, ns1 = 0.f;
#pragma unroll
        for (int nt = 0; nt < 8; nt++) {
            int n = wn + nt * 8 + fc;
            float b0 = sbias[n], b1 = sbias[n + 1];
            float v00 = fmaxf(acc[mt][nt][0] + b0, 0.f);
            float v01 = fmaxf(acc[mt][nt][1] + b1, 0.f);
            float v10 = fmaxf(acc[mt][nt][2] + b0, 0.f);
            float v11 = fmaxf(acc[mt][nt][3] + b1, 0.f);
            ns0 += v00 * v00 + v01 * v01;
            ns1 += v10 * v10 + v11 * v11;
            __nv_bfloat162 h, l;
            h.x = __float2bfloat16_rn(v00);
            h.y = __float2bfloat16_rn(v01);
            l.x = __float2bfloat16_rn(v00 - __bfloat162float(h.x));
            l.y = __float2bfloat16_rn(v01 - __bfloat162float(h.y));
            *(__nv_bfloat162*)&Ohi[g0 + n] = h;
            *(__nv_bfloat162*)&Olo[g0 + n] = l;
            h.x = __float2bfloat16_rn(v10);
            h.y = __float2bfloat16_rn(v11);
            l.x = __float2bfloat16_rn(v10 - __bfloat162float(h.x));
            l.y = __float2bfloat16_rn(v11 - __bfloat162float(h.y));
            *(__nv_bfloat162*)&Ohi[g1 + n] = h;
            *(__nv_bfloat162*)&Olo[g1 + n] = l;
            if (Ofp) {
                *(float2*)&Ofp[g0 + n] = make_float2(v00, v01);
                *(float2*)&Ofp[g1 + n] = make_float2(v10, v11);
            }
        }
        atomicAdd(&snorm[r0], ns0);
        atomicAdd(&snorm[r1], ns1);
    }
    __syncthreads();
    if (tid < 128 && m0 + tid < NT) nrm[m0 + tid] = snorm[tid];
}

// ---------------------------------------------------------------------------
__global__ void __launch_bounds__(256)
linear_relu_kernel(const float* __restrict__ A, const float* __restrict__ W,
                   const float* __restrict__ bias, float* __restrict__ out,
                   int M, int K)
{
    __shared__ __align__(16) float As[16 * 68];
    __shared__ __align__(16) float Bs[16 * 136];
    const int tx = threadIdx.x, ty = threadIdx.y;
    const int tid = ty * 16 + tx;
    const int m0 = blockIdx.x * 64;

    float acc[4][8];
#pragma unroll
    for (int r = 0; r < 4; r++)
#pragma unroll
        for (int c = 0; c < 8; c++) acc[r][c] = 0.f;

    const int nChunks = (K + 15) / 16;
    for (int ch = 0; ch < nChunks; ch++) {
        const int k0 = ch * 16;
#pragma unroll
        for (int i = 0; i < 4; i++) {
            int e = tid + i * 256;
            int k = e & 15, m = e >> 4;
            float v = 0.f;
            if (k0 + k < K && m0 + m < M) v = A[(size_t)(m0 + m) * K + k0 + k];
            As[k * 68 + m] = v;
        }
#pragma unroll
        for (int i = 0; i < 8; i++) {
            int e = tid + i * 256;
            int h = e & 127, k = e >> 7;
            float v = 0.f;
            if (k0 + k < K) v = W[(size_t)(k0 + k) * HD + h];
            Bs[k * 136 + h] = v;
        }
        __syncthreads();
#pragma unroll
        for (int k = 0; k < 16; k++) {
            float4 a  = *(const float4*)&As[k * 68 + ty * 4];
            float4 b0 = *(const float4*)&Bs[k * 136 + tx * 4];
            float4 b1 = *(const float4*)&Bs[k * 136 + 64 + tx * 4];
            float av[4] = {a.x, a.y, a.z, a.w};
            float bv[8] = {b0.x, b0.y, b0.z, b0.w, b1.x, b1.y, b1.z, b1.w};
#pragma unroll
            for (int r = 0; r < 4; r++)
#pragma unroll
                for (int c = 0; c < 8; c++) acc[r][c] += av[r] * bv[c];
        }
        __syncthreads();
    }
#pragma unroll
    for (int r = 0; r < 4; r++) {
        int m = m0 + ty * 4 + r;
        if (m >= M) continue;
#pragma unroll
        for (int half = 0; half < 2; half++) {
#pragma unroll
            for (int c = 0; c < 4; c++) {
                int h = half * 64 + tx * 4 + c;
                float v = acc[r][half * 4 + c] + bias[h];
                out[(size_t)m * HD + h] = fmaxf(v, 0.f);
            }
        }
    }
}

// ---------------------------------------------------------------------------
__global__ void __launch_bounds__(256)
linear_softmax_kernel(const float* __restrict__ A, const float* __restrict__ W,
                      const float* __restrict__ bias, float* __restrict__ out, int M)
{
    __shared__ float Ws[HD * NL];
    __shared__ float bs[NL];
    int tid = threadIdx.x;
    for (int i = tid; i < HD * NL; i += 256) Ws[i] = W[i];
    if (tid < NL) bs[tid] = bias[tid];
    __syncthreads();

    int warp = tid >> 5, lane = tid & 31;
    int m = blockIdx.x * 8 + warp;
    if (m >= M) return;

    float acc[NL];
#pragma unroll
    for (int h = 0; h < NL; h++) acc[h] = 0.f;
    for (int k = lane; k < HD; k += 32) {
        float x = A[(size_t)m * HD + k];
#pragma unroll
        for (int h = 0; h < NL; h++) acc[h] += x * Ws[k * NL + h];
    }
#pragma unroll
    for (int h = 0; h < NL; h++)
#pragma unroll
        for (int off = 16; off > 0; off >>= 1)
            acc[h] += __shfl_down_sync(0xFFFFFFFFu, acc[h], off);

    if (lane == 0) {
        float v[NL], mx = -1e30f;
#pragma unroll
        for (int h = 0; h < NL; h++) { v[h] = acc[h] + bs[h]; mx = fmaxf(mx, v[h]); }
        float s = 0.f;
#pragma unroll
        for (int h = 0; h < NL; h++) { v[h] = expf(v[h] - mx); s += v[h]; }
        float inv = 1.0f / s;
#pragma unroll
        for (int h = 0; h < NL; h++) out[(size_t)m * NL + h] = v[h] * inv;
    }
}

// ---------------------------------------------------------------------------
// Layer-4 tile minima WITHOUT materializing d2.
// ---------------------------------------------------------------------------
__global__ void __launch_bounds__(256)
min4_kernel(const float* __restrict__ q4, const float* __restrict__ t4,
            float* __restrict__ gmin)
{
    __shared__ float st[128 * 8];
    __shared__ float sq[128 * 8];
    const int t = blockIdx.x;
    const int q0 = blockIdx.y * 128;
    const int tid = threadIdx.x;
    const float FINF = __int_as_float(0x7F800000);

    for (int i = tid; i < 1024; i += 256) {
        int row = t * 128 + (i >> 3);
        st[i] = (row < NT) ? t4[(size_t)row * 8 + (i & 7)] : 0.f;
        sq[i] = q4[(size_t)(q0 + (i >> 3)) * 8 + (i & 7)];
    }
    __syncthreads();

    const int qi = tid >> 1, half = tid & 1;
    float q[8];
#pragma unroll
    for (int j = 0; j < 8; j++) q[j] = sq[qi * 8 + j];
    const float qq = l4_qq(q);

    float m = FINF;
    const int rbase = half * 64;
    for (int r = 0; r < 64; r++) {
        int row = t * 128 + rbase + r;
        if (row < NT)
            m = fminf(m, l4_d2f(&st[(rbase + r) * 8], q, qq));
    }
    m = fminf(m, __shfl_xor_sync(0xFFFFFFFFu, m, 1));
    if (half == 0)
        gmin[(size_t)(q0 + qi) * NTILES + t] = m;
}

// ---------------------------------------------------------------------------
__device__ __forceinline__ void find_kth(const unsigned* hist, int NB, unsigned kth,
                                         int tid, unsigned* s_bin, unsigned* s_kthr)
{
    if (tid < 32) {
        unsigned running = 0;
        for (int base = 0; base < NB; base += 32) {
            unsigned v = hist[base + tid];
            unsigned sc = v;
#pragma unroll
            for (int off = 1; off < 32; off <<= 1) {
                unsigned t = __shfl_up_sync(0xFFFFFFFFu, sc, off);
                if (tid >= off) sc += t;
            }
            unsigned tot = __shfl_sync(0xFFFFFFFFu, sc, 31);
            if (running + tot >= kth) {
                unsigned mask = __ballot_sync(0xFFFFFFFFu, running + sc >= kth);
                int l = __ffs(mask) - 1;
                if (tid == l) { *s_bin = (unsigned)(base + l); *s_kthr = kth - running - (sc - v); }
                break;
            }
            running += tot;
        }
    }
}

// ---------------------------------------------------------------------------
// Exact top-K select (layers 0-3): tile-min threshold + tile-subset d2 scan.
// ---------------------------------------------------------------------------
#define SEL_THREADS 512
#define SEL_CAP 2048
#define OFF_CAND  16384
#define OFF_SEL   (OFF_CAND + SEL_CAP * 8)
#define OFF_TIES  (OFF_SEL + 1024)
#define OFF_TLAB  (OFF_TIES + 1024)
#define OFF_MINS  (OFF_TLAB + 512)
#define OFF_TLIST (OFF_MINS + 392 * 4)
#define SEL_SMEM  (OFF_TLIST + 392 * 4)

__global__ void __launch_bounds__(SEL_THREADS)
select_kernel(const float* __restrict__ d2mat, const float* __restrict__ gmin,
              const int* __restrict__ labels, float* __restrict__ total, int init)
{
    extern __shared__ __align__(16) char sms[];
    unsigned* hist = (unsigned*)sms;
    u64* cand  = (u64*)(sms + OFF_CAND);
    u64* sel   = (u64*)(sms + OFF_SEL);
    u64* ties  = (u64*)(sms + OFF_TIES);
    int* tlab  = (int*)(sms + OFF_TLAB);
    float* mins = (float*)(sms + OFF_MINS);
    int* tlist = (int*)(sms + OFF_TLIST);

    __shared__ unsigned s_M75, s_bin, s_kthr, s_candcnt, s_selcnt, s_tiecnt, s_ntiles;
    __shared__ float s_w[80];
    __shared__ int s_lab[80];

    const int b = blockIdx.x, tid = threadIdx.x, lane = tid & 31;
    const uint4* usrc = (const uint4*)(d2mat + (size_t)b * NT);
    const int NH = NT / 4;

    for (int i = tid; i < NTILES; i += SEL_THREADS)
        mins[i] = gmin[(size_t)b * NTILES + i];
    if (tid == 0) { s_candcnt = 0; s_selcnt = 0; s_tiecnt = 0; s_ntiles = 0; }
    __syncthreads();

    if (tid < NTILES) {
        unsigned key = __float_as_uint(mins[tid]);
        int c = 0;
        for (int j = 0; j < NTILES; j++) {
            unsigned kj = __float_as_uint(mins[j]);
            c += (kj < key) || (kj == key && j < tid);
        }
        if (c == KNN - 1) s_M75 = key;
    }
    __syncthreads();
    const unsigned Mkey = s_M75;

    if (tid < NTILES) {
        if (__float_as_uint(mins[tid]) <= Mkey) {
            unsigned s = atomicAdd(&s_ntiles, 1u);
            tlist[s] = tid;
        }
    }
    __syncthreads();
    const int ntl = (int)s_ntiles;

    for (int w = tid; w < ntl * 32; w += SEL_THREADS) {
        int t = tlist[w >> 5];
        int i4 = t * 32 + (w & 31);
        if (i4 < NH) {
            uint4 a = usrc[i4];
            unsigned k[4] = {a.x, a.y, a.z, a.w};
#pragma unroll
            for (int j = 0; j < 4; j++) {
                if (k[j] <= Mkey) {
                    unsigned s = atomicAdd(&s_candcnt, 1u);
                    if (s < SEL_CAP) cand[s] = ((u64)k[j] << 32) | (unsigned)(i4 * 4 + j);
                }
            }
        }
    }
    __syncthreads();

    unsigned Tkey;
    const unsigned candTotal = s_candcnt;

    if (candTotal <= SEL_CAP) {
        const int cc = (int)candTotal;
        for (int i = tid; i < 4096; i += SEL_THREADS) hist[i] = 0;
        __syncthreads();
        for (int i = tid; i < cc; i += SEL_THREADS)
            atomicAdd(&hist[(unsigned)(cand[i] >> 52)], 1u);
        __syncthreads();
        find_kth(hist, 4096, KNN, tid, &s_bin, &s_kthr);
        __syncthreads();
        const unsigned pfx = s_bin;
        const unsigned k1v = s_kthr;
        for (int i = tid; i < 4096; i += SEL_THREADS) hist[i] = 0;
        __syncthreads();
        for (int i = tid; i < cc; i += SEL_THREADS) {
            unsigned key = (unsigned)(cand[i] >> 32);
            if ((key >> 20) == pfx) atomicAdd(&hist[(key >> 8) & 0xFFFu], 1u);
        }
        __syncthreads();
        find_kth(hist, 4096, k1v, tid, &s_bin, &s_kthr);
        __syncthreads();
        const unsigned pfx20 = (pfx << 12) | s_bin;
        const unsigned k2v = s_kthr;
        for (int i = tid; i < 256; i += SEL_THREADS) hist[i] = 0;
        __syncthreads();
        for (int i = tid; i < cc; i += SEL_THREADS) {
            unsigned key = (unsigned)(cand[i] >> 32);
            if ((key >> 8) == pfx20) atomicAdd(&hist[key & 0xFFu], 1u);
        }
        __syncthreads();
        find_kth(hist, 256, k2v, tid, &s_bin, &s_kthr);
        __syncthreads();
        Tkey = (pfx20 << 8) | s_bin;
        for (int i = tid; i < cc; i += SEL_THREADS) {
            u64 cv = cand[i];
            unsigned key = (unsigned)(cv >> 32);
            if (key < Tkey) {
                unsigned s = atomicAdd(&s_selcnt, 1u);
                if (s < 128) sel[s] = cv;
            } else if (key == Tkey) {
                unsigned s = atomicAdd(&s_tiecnt, 1u);
                if (s < 128) ties[s] = cv;
            }
        }
        __syncthreads();
    } else {
        for (int i = tid; i < 4096; i += SEL_THREADS) hist[i] = 0;
        __syncthreads();
        for (int w = tid; w < ntl * 32; w += SEL_THREADS) {
            int t = tlist[w >> 5];
            int i4 = t * 32 + (w & 31);
            uint4 a = (i4 < NH) ? usrc[i4] : make_uint4(~0u, ~0u, ~0u, ~0u);
            unsigned k[4] = {a.x, a.y, a.z, a.w};
#pragma unroll
            for (int j = 0; j < 4; j++) {
                unsigned bin = (k[j] <= Mkey) ? (k[j] >> 20) : 0xFFFFFFFFu;
                unsigned grp = __match_any_sync(0xFFFFFFFFu, bin);
                if (bin != 0xFFFFFFFFu && lane == __ffs(grp) - 1)
                    atomicAdd(&hist[bin], (unsigned)__popc(grp));
            }
        }
        __syncthreads();
        find_kth(hist, 4096, KNN, tid, &s_bin, &s_kthr);
        __syncthreads();
        const unsigned pfx = s_bin;
        const unsigned k1v = s_kthr;

        for (int i = tid; i < 4096; i += SEL_THREADS) hist[i] = 0;
        __syncthreads();
        for (int w = tid; w < ntl * 32; w += SEL_THREADS) {
            int t = tlist[w >> 5];
            int i4 = t * 32 + (w & 31);
            uint4 a = (i4 < NH) ? usrc[i4] : make_uint4(~0u, ~0u, ~0u, ~0u);
            unsigned k[4] = {a.x, a.y, a.z, a.w};
#pragma unroll
            for (int j = 0; j < 4; j++) {
                unsigned bin = (k[j] <= Mkey && (k[j] >> 20) == pfx)
                               ? ((k[j] >> 8) & 0xFFFu) : 0xFFFFFFFFu;
                unsigned grp = __match_any_sync(0xFFFFFFFFu, bin);
                if (bin != 0xFFFFFFFFu && lane == __ffs(grp) - 1)
                    atomicAdd(&hist[bin], (unsigned)__popc(grp));
            }
        }
        __syncthreads();
        find_kth(hist, 4096, k1v, tid, &s_bin, &s_kthr);
        __syncthreads();
        const unsigned pfx20 = (pfx << 12) | s_bin;
        const unsigned k2v = s_kthr;

        for (int i = tid; i < 256; i += SEL_THREADS) hist[i] = 0;
        __syncthreads();
        for (int w = tid; w < ntl * 32; w += SEL_THREADS) {
            int t = tlist[w >> 5];
            int i4 = t * 32 + (w & 31);
            uint4 a = (i4 < NH) ? usrc[i4] : make_uint4(~0u, ~0u, ~0u, ~0u);
            unsigned k[4] = {a.x, a.y, a.z, a.w};
#pragma unroll
            for (int j = 0; j < 4; j++) {
                unsigned bin = (k[j] <= Mkey && (k[j] >> 8) == pfx20)
                               ? (k[j] & 0xFFu) : 0xFFFFFFFFu;
                unsigned grp = __match_any_sync(0xFFFFFFFFu, bin);
                if (bin != 0xFFFFFFFFu && lane == __ffs(grp) - 1)
                    atomicAdd(&hist[bin], (unsigned)__popc(grp));
            }
        }
        __syncthreads();
        find_kth(hist, 256, k2v, tid, &s_bin, &s_kthr);
        __syncthreads();
        Tkey = (pfx20 << 8) | s_bin;

        for (int w = tid; w < ntl * 32; w += SEL_THREADS) {
            int t = tlist[w >> 5];
            int i4 = t * 32 + (w & 31);
            if (i4 < NH) {
                uint4 a = usrc[i4];
                unsigned k[4] = {a.x, a.y, a.z, a.w};
#pragma unroll
                for (int j = 0; j < 4; j++) {
                    if (k[j] < Tkey) {
                        unsigned s = atomicAdd(&s_selcnt, 1u);
                        if (s < 128) sel[s] = ((u64)k[j] << 32) | (unsigned)(i4 * 4 + j);
                    } else if (k[j] == Tkey) {
                        unsigned s = atomicAdd(&s_tiecnt, 1u);
                        if (s < 128) ties[s] = ((u64)k[j] << 32) | (unsigned)(i4 * 4 + j);
                    }
                }
            }
        }
        __syncthreads();
    }

    const int ns = min((int)s_selcnt, 128);
    const int ne = min((int)s_tiecnt, 128);

    if (tid < ns) {
        u64 mine = sel[tid];
        unsigned my_idx = (unsigned)(mine & 0xFFFFFFFFu);
        int rank = 0;
        for (int j = 0; j < ns; j++) rank += ((unsigned)(sel[j] & 0xFFFFFFFFu) < my_idx);
        float d2 = __uint_as_float((unsigned)(mine >> 32));
        s_w[rank] = (d2 > 0.f) ? __fdiv_rn(1.0f, __fsqrt_rn(d2)) : 0.f;
        s_lab[rank] = labels[my_idx];
    }
    if (tid >= 128 && tid - 128 < ne) {
        int t = tid - 128;
        unsigned my_idx = (unsigned)(ties[t] & 0xFFFFFFFFu);
        int rank = 0;
        for (int j = 0; j < ne; j++) rank += ((unsigned)(ties[j] & 0xFFFFFFFFu) < my_idx);
        tlab[rank] = labels[my_idx];
    }
    __syncthreads();

    if (tid == 0) {
        float cls[NL];
#pragma unroll
        for (int l = 0; l < NL; l++) cls[l] = 0.f;
        float stot = 0.f;
        for (int j = 0; j < ns; j++) { stot += s_w[j]; cls[s_lab[j]] += s_w[j]; }
        int need = KNN - ns;
        float d2T = __uint_as_float(Tkey);
        float wT = (d2T > 0.f) ? __fdiv_rn(1.0f, __fsqrt_rn(d2T)) : 0.f;
        int m = (need < ne) ? need : ne;
        for (int j = 0; j < m; j++) { stot += wT; cls[tlab[j]] += wT; }
#pragma unroll
        for (int l = 0; l < NL; l++) {
            float val = stot - cls[l];
            size_t o = (size_t)b * NL + l;
            if (init) total[o] = val; else total[o] += val;
        }
    }
}

// ---------------------------------------------------------------------------
// Layer-4 select: d2 recomputed inline from t4 (no d2 matrix).
// ---------------------------------------------------------------------------
__global__ void __launch_bounds__(SEL_THREADS)
select4_kernel(const float* __restrict__ q4, const float* __restrict__ t4,
               const float* __restrict__ gmin, const int* __restrict__ labels,
               float* __restrict__ total)
{
    extern __shared__ __align__(16) char sms[];
    unsigned* hist = (unsigned*)sms;
    u64* cand  = (u64*)(sms + OFF_CAND);
    u64* sel   = (u64*)(sms + OFF_SEL);
    u64* ties  = (u64*)(sms + OFF_TIES);
    int* tlab  = (int*)(sms + OFF_TLAB);
    float* mins = (float*)(sms + OFF_MINS);
    int* tlist = (int*)(sms + OFF_TLIST);

    __shared__ unsigned s_M75, s_bin, s_kthr, s_candcnt, s_selcnt, s_tiecnt, s_ntiles;
    __shared__ float s_w[80];
    __shared__ int s_lab[80];
    __shared__ float s_q[8];

    const int b = blockIdx.x, tid = threadIdx.x, lane = tid & 31;

    if (tid < 8) s_q[tid] = q4[(size_t)b * 8 + tid];
    for (int i = tid; i < NTILES; i += SEL_THREADS)
        mins[i] = gmin[(size_t)b * NTILES + i];
    if (tid == 0) { s_candcnt = 0; s_selcnt = 0; s_tiecnt = 0; s_ntiles = 0; }
    __syncthreads();

    float q[8];
#pragma unroll
    for (int j = 0; j < 8; j++) q[j] = s_q[j];
    const float qq = l4_qq(q);

    if (tid < NTILES) {
        unsigned key = __float_as_uint(mins[tid]);
        int c = 0;
        for (int j = 0; j < NTILES; j++) {
            unsigned kj = __float_as_uint(mins[j]);
            c += (kj < key) || (kj == key && j < tid);
        }
        if (c == KNN - 1) s_M75 = key;
    }
    __syncthreads();
    unsigned Mkey = s_M75;

    if (tid < NTILES) {
        if (__float_as_uint(mins[tid]) <= Mkey) {
            unsigned s = atomicAdd(&s_ntiles, 1u);
            tlist[s] = tid;
        }
    }
    __syncthreads();
    int ntl = (int)s_ntiles;

    for (int w = tid; w < ntl * 128; w += SEL_THREADS) {
        int row = tlist[w >> 7] * 128 + (w & 127);
        if (row < NT) {
            unsigned key = __float_as_uint(l4_d2f(t4 + (size_t)row * 8, q, qq));
            if (key <= Mkey) {
                unsigned s = atomicAdd(&s_candcnt, 1u);
                if (s < SEL_CAP) cand[s] = ((u64)key << 32) | (unsigned)row;
            }
        }
    }
    __syncthreads();

    unsigned candTotal = s_candcnt;
    if (candTotal < KNN) {
        __syncthreads();
        if (tid < NTILES) tlist[tid] = tid;
        if (tid == 0) s_ntiles = NTILES;
        __syncthreads();
        ntl = NTILES;
        Mkey = 0xFFFFFFFFu;
        candTotal = SEL_CAP + 1;
    }

    unsigned Tkey;
    if (candTotal <= SEL_CAP) {
        const int cc = (int)candTotal;
        for (int i = tid; i < 4096; i += SEL_THREADS) hist[i] = 0;
        __syncthreads();
        for (int i = tid; i < cc; i += SEL_THREADS)
            atomicAdd(&hist[(unsigned)(cand[i] >> 52)], 1u);
        __syncthreads();
        find_kth(hist, 4096, KNN, tid, &s_bin, &s_kthr);
        __syncthreads();
        const unsigned pfx = s_bin;
        const unsigned k1v = s_kthr;
        for (int i = tid; i < 4096; i += SEL_THREADS) hist[i] = 0;
        __syncthreads();
        for (int i = tid; i < cc; i += SEL_THREADS) {
            unsigned key = (unsigned)(cand[i] >> 32);
            if ((key >> 20) == pfx) atomicAdd(&hist[(key >> 8) & 0xFFFu], 1u);
        }
        __syncthreads();
        find_kth(hist, 4096, k1v, tid, &s_bin, &s_kthr);
        __syncthreads();
        const unsigned pfx20 = (pfx << 12) | s_bin;
        const unsigned k2v = s_kthr;
        for (int i = tid; i < 256; i += SEL_THREADS) hist[i] = 0;
        __syncthreads();
        for (int i = tid; i < cc; i += SEL_THREADS) {
            unsigned key = (unsigned)(cand[i] >> 32);
            if ((key >> 8) == pfx20) atomicAdd(&hist[key & 0xFFu], 1u);
        }
        __syncthreads();
        find_kth(hist, 256, k2v, tid, &s_bin, &s_kthr);
        __syncthreads();
        Tkey = (pfx20 << 8) | s_bin;
        for (int i = tid; i < cc; i += SEL_THREADS) {
            u64 cv = cand[i];
            unsigned key = (unsigned)(cv >> 32);
            if (key < Tkey) {
                unsigned s = atomicAdd(&s_selcnt, 1u);
                if (s < 128) sel[s] = cv;
            } else if (key == Tkey) {
                unsigned s = atomicAdd(&s_tiecnt, 1u);
                if (s < 128) ties[s] = cv;
            }
        }
        __syncthreads();
    } else {
        for (int i = tid; i < 4096; i += SEL_THREADS) hist[i] = 0;
        __syncthreads();
        for (int w = tid; w < ntl * 128; w += SEL_THREADS) {
            int row = tlist[w >> 7] * 128 + (w & 127);
            unsigned bin = 0xFFFFFFFFu;
            if (row < NT) {
                unsigned key = __float_as_uint(l4_d2f(t4 + (size_t)row * 8, q, qq));
                if (key <= Mkey) bin = key >> 20;
            }
            unsigned grp = __match_any_sync(0xFFFFFFFFu, bin);
            if (bin != 0xFFFFFFFFu && lane == __ffs(grp) - 1)
                atomicAdd(&hist[bin], (unsigned)__popc(grp));
        }
        __syncthreads();
        find_kth(hist, 4096, KNN, tid, &s_bin, &s_kthr);
        __syncthreads();
        const unsigned pfx = s_bin;
        const unsigned k1v = s_kthr;

        for (int i = tid; i < 4096; i += SEL_THREADS) hist[i] = 0;
        __syncthreads();
        for (int w = tid; w < ntl * 128; w += SEL_THREADS) {
            int row = tlist[w >> 7] * 128 + (w & 127);
            unsigned bin = 0xFFFFFFFFu;
            if (row < NT) {
                unsigned key = __float_as_uint(l4_d2f(t4 + (size_t)row * 8, q, qq));
                if (key <= Mkey && (key >> 20) == pfx) bin = (key >> 8) & 0xFFFu;
            }
            unsigned grp = __match_any_sync(0xFFFFFFFFu, bin);
            if (bin != 0xFFFFFFFFu && lane == __ffs(grp) - 1)
                atomicAdd(&hist[bin], (unsigned)__popc(grp));
        }
        __syncthreads();
        find_kth(hist, 4096, k1v, tid, &s_bin, &s_kthr);
        __syncthreads();
        const unsigned pfx20 = (pfx << 12) | s_bin;
        const unsigned k2v = s_kthr;

        for (int i = tid; i < 256; i += SEL_THREADS) hist[i] = 0;
        __syncthreads();
        for (int w = tid; w < ntl * 128; w += SEL_THREADS) {
            int row = tlist[w >> 7] * 128 + (w & 127);
            unsigned bin = 0xFFFFFFFFu;
            if (row < NT) {
                unsigned key = __float_as_uint(l4_d2f(t4 + (size_t)row * 8, q, qq));
                if (key <= Mkey && (key >> 8) == pfx20) bin = key & 0xFFu;
            }
            unsigned grp = __match_any_sync(0xFFFFFFFFu, bin);
            if (bin != 0xFFFFFFFFu && lane == __ffs(grp) - 1)
                atomicAdd(&hist[bin], (unsigned)__popc(grp));
        }
        __syncthreads();
        find_kth(hist, 256, k2v, tid, &s_bin, &s_kthr);
        __syncthreads();
        Tkey = (pfx20 << 8) | s_bin;

        for (int w = tid; w < ntl * 128; w += SEL_THREADS) {
            int row = tlist[w >> 7] * 128 + (w & 127);
            if (row < NT) {
                unsigned key = __float_as_uint(l4_d2f(t4 + (size_t)row * 8, q, qq));
                if (key < Tkey) {
                    unsigned s = atomicAdd(&s_selcnt, 1u);
                    if (s < 128) sel[s] = ((u64)key << 32) | (unsigned)row;
                } else if (key == Tkey) {
                    unsigned s = atomicAdd(&s_tiecnt, 1u);
                    if (s < 128) ties[s] = ((u64)key << 32) | (unsigned)row;
                }
            }
        }
        __syncthreads();
    }

    const int ns = min((int)s_selcnt, 128);
    const int ne = min((int)s_tiecnt, 128);

    if (tid < ns) {
        u64 mine = sel[tid];
        unsigned my_idx = (unsigned)(mine & 0xFFFFFFFFu);
        int rank = 0;
        for (int j = 0; j < ns; j++) rank += ((unsigned)(sel[j] & 0xFFFFFFFFu) < my_idx);
        float d2 = __uint_as_float((unsigned)(mine >> 32));
        s_w[rank] = (d2 > 0.f) ? __fdiv_rn(1.0f, __fsqrt_rn(d2)) : 0.f;
        s_lab[rank] = labels[my_idx];
    }
    if (tid >= 128 && tid - 128 < ne) {
        int t = tid - 128;
        unsigned my_idx = (unsigned)(ties[t] & 0xFFFFFFFFu);
        int rank = 0;
        for (int j = 0; j < ne; j++) rank += ((unsigned)(ties[j] & 0xFFFFFFFFu) < my_idx);
        tlab[rank] = labels[my_idx];
    }
    __syncthreads();

    if (tid == 0) {
        float cls[NL];
#pragma unroll
        for (int l = 0; l < NL; l++) cls[l] = 0.f;
        float stot = 0.f;
        for (int j = 0; j < ns; j++) { stot += s_w[j]; cls[s_lab[j]] += s_w[j]; }
        int need = KNN - ns;
        float d2T = __uint_as_float(Tkey);
        float wT = (d2T > 0.f) ? __fdiv_rn(1.0f, __fsqrt_rn(d2T)) : 0.f;
        int m = (need < ne) ? need : ne;
        for (int j = 0; j < m; j++) { stot += wT; cls[tlab[j]] += wT; }
#pragma unroll
        for (int l = 0; l < NL; l++)
            total[(size_t)b * NL + l] += stot - cls[l];
    }
}

// ---------------------------------------------------------------------------
__global__ void __launch_bounds__(256)
pvalue_kernel(const float* __restrict__ total, const float* __restrict__ cali,
              float* __restrict__ out)
{
    const int b = blockIdx.x, tid = threadIdx.x;
    float t[NL];
#pragma unroll
    for (int l = 0; l < NL; l++) t[l] = total[(size_t)b * NL + l];
    int cnt[NL];
#pragma unroll
    for (int l = 0; l < NL; l++) cnt[l] = 0;
    for (int i = tid; i < NC; i += 256) {
        float c = cali[i];
#pragma unroll
        for (int l = 0; l < NL; l++) cnt[l] += (c >= t[l]) ? 1 : 0;
    }
    __shared__ int sc[NL];
    if (tid < NL) sc[tid] = 0;
    __syncthreads();
#pragma unroll
    for (int l = 0; l < NL; l++) atomicAdd(&sc[l], cnt[l]);
    __syncthreads();
    if (tid < NL) out[(size_t)b * NL + tid] = (float)sc[tid] * (1.0f / NC);
}

// ---------------------------------------------------------------------------
extern "C" void kernel_launch(void* const* d_in, const int* in_sizes, int n_in,
                              void* d_out, int out_size)
{
    const float* x        = (const float*)d_in[0];
    const float* train_x  = (const float*)d_in[1];
    const int*   lab      = (const int*)  d_in[2];
    const float* cali     = (const float*)d_in[3];
    const float* W1 = (const float*)d_in[4];  const float* b1 = (const float*)d_in[5];
    const float* W2 = (const float*)d_in[6];  const float* b2 = (const float*)d_in[7];
    const float* W3 = (const float*)d_in[8];  const float* b3 = (const float*)d_in[9];
    const float* W4 = (const float*)d_in[10]; const float* b4 = (const float*)d_in[11];
    float* out = (float*)d_out;

    float *h1p, *h2p, *h3p, *q4p, *t3p, *t4p, *d2ap, *d2bp, *totp, *minall;
    float *qnAp, *qnBp, *tnAp, *tnBp;
    __nv_bfloat16 *qhiAp, *qloAp, *qhiBp, *qloBp, *thip, *tlop, *thi2p, *tlo2p;
    __nv_bfloat16 *w1th, *w1tl, *w2th, *w2tl, *w3th, *w3tl;
    cudaGetSymbolAddress((void**)&h1p, g_h1);
    cudaGetSymbolAddress((void**)&h2p, g_h2);
    cudaGetSymbolAddress((void**)&h3p, g_h3);
    cudaGetSymbolAddress((void**)&q4p, g_q4);
    cudaGetSymbolAddress((void**)&t3p, g_t3);
    cudaGetSymbolAddress((void**)&t4p, g_t4);
    cudaGetSymbolAddress((void**)&d2ap, g_d2a);
    cudaGetSymbolAddress((void**)&d2bp, g_d2b);
    cudaGetSymbolAddress((void**)&minall, g_minall);
    cudaGetSymbolAddress((void**)&qnAp, g_qnA);
    cudaGetSymbolAddress((void**)&qnBp, g_qnB);
    cudaGetSymbolAddress((void**)&tnAp, g_tnA);
    cudaGetSymbolAddress((void**)&tnBp, g_tnB);
    cudaGetSymbolAddress((void**)&totp, g_tot);
    cudaGetSymbolAddress((void**)&qhiAp, g_qhiA);
    cudaGetSymbolAddress((void**)&qloAp, g_qloA);
    cudaGetSymbolAddress((void**)&qhiBp, g_qhiB);
    cudaGetSymbolAddress((void**)&qloBp, g_qloB);
    cudaGetSymbolAddress((void**)&thip, g_thi);
    cudaGetSymbolAddress((void**)&tlop, g_tlo);
    cudaGetSymbolAddress((void**)&thi2p, g_thi2);
    cudaGetSymbolAddress((void**)&tlo2p, g_tlo2);
    cudaGetSymbolAddress((void**)&w1th, g_w1th);
    cudaGetSymbolAddress((void**)&w1tl, g_w1tl);
    cudaGetSymbolAddress((void**)&w2th, g_w2th);
    cudaGetSymbolAddress((void**)&w2tl, g_w2tl);
    cudaGetSymbolAddress((void**)&w3th, g_w3th);
    cudaGetSymbolAddress((void**)&w3tl, g_w3tl);

    float* minL[5];
    for (int i = 0; i < 5; i++) minL[i] = minall + (size_t)i * BQ * NTILES;

    cudaFuncSetAttribute(select_kernel,
                         cudaFuncAttributeMaxDynamicSharedMemorySize, SEL_SMEM);
    cudaFuncSetAttribute(select4_kernel,
                         cudaFuncAttributeMaxDynamicSharedMemorySize, SEL_SMEM);
    cudaFuncSetAttribute(mma_dist_kernel,
                         cudaFuncAttributeMaxDynamicSharedMemorySize, MD_SMEM);

    cudaStream_t s2 = g_ok ? g_s2 : (cudaStream_t)0;
    cudaStream_t s3 = g_ok ? g_s3 : (cudaStream_t)0;
#define REC(ev, st)  do { if (g_ok) cudaEventRecord(g_ev[ev], st); } while (0)
#define WAIT(st, ev) do { if (g_ok) cudaStreamWaitEvent(st, g_ev[ev], 0); } while (0)

    dim3 tb(16, 16);
    const int D0 = 83;
    const dim3 mgrid(NTILES, BQ / 256);

    // ---- main: prep ----
    conv_norm_kernel<<<BQ / 8, 256>>>(x, qhiAp, qloAp, qnAp, BQ, D0);
    conv_norm_kernel<<<NTP / 8, 256>>>(train_x, thip, tlop, tnAp, NT, D0);
    wt_convert_kernel<<<(3 * 128 * 128 + 255) / 256, 256>>>(W1, W2, W3);
    REC(EV_PREP, 0);

    // ---- s3: query MLP (depends only on x/W) ----
    linear_relu_kernel<<<BQ / 64, tb, 0, s3>>>(x,   W1, b1, h1p, BQ, D0);
    linear_relu_kernel<<<BQ / 64, tb, 0, s3>>>(h1p, W2, b2, h2p, BQ, HD);
    linear_relu_kernel<<<BQ / 64, tb, 0, s3>>>(h2p, W3, b3, h3p, BQ, HD);
    linear_softmax_kernel<<<(BQ + 7) / 8, 256, 0, s3>>>(h3p, W4, b4, q4p, BQ);

    // ---- main: dist L0 (A banks) ----
    mma_dist_kernel<<<mgrid, 512, MD_SMEM>>>(qhiAp, qloAp, thip, tlop, qnAp, tnAp,
                                             d2ap, minL[0], 6);
    REC(EV_D0, 0);

    // ---- s2: select L0 ----
    WAIT(s2, EV_D0);
    select_kernel<<<BQ, SEL_THREADS, SEL_SMEM, s2>>>(d2ap, minL[0], lab, totp, 1);
    REC(EV_J0, s2);

    // ---- s3: linear L1 (tA->tB) + conv h1 (->qB), overlap dist L0 ----
    WAIT(s3, EV_PREP);
    mma_linear_kernel<<<NTILES, 256, 0, s3>>>(thip, tlop, w1th, w1tl, b1,
                                              thi2p, tlo2p, tnBp, (float*)0, 6);
    conv_norm_kernel<<<BQ / 8, 256, 0, s3>>>(h1p, qhiBp, qloBp, qnBp, BQ, HD);
    REC(EV_S3A, s3);

    // ---- main: dist L1 (B banks) ----
    WAIT(0, EV_S3A);
    mma_dist_kernel<<<mgrid, 512, MD_SMEM>>>(qhiBp, qloBp, thi2p, tlo2p, qnBp, tnBp,
                                             d2bp, minL[1], 8);
    REC(EV_D1, 0);

    // ---- s2: select L1 ----
    WAIT(s2, EV_D1);
    select_kernel<<<BQ, SEL_THREADS, SEL_SMEM, s2>>>(d2bp, minL[1], lab, totp, 0);
    REC(EV_J1, s2);

    // ---- s3: linear L2 (tB->tA) + conv h2 (->qA); must wait dist L0 (reads tA,qA) ----
    WAIT(s3, EV_D0);
    mma_linear_kernel<<<NTILES, 256, 0, s3>>>(thi2p, tlo2p, w2th, w2tl, b2,
                                              thip, tlop, tnAp, (float*)0, 8);
    conv_norm_kernel<<<BQ / 8, 256, 0, s3>>>(h2p, qhiAp, qloAp, qnAp, BQ, HD);
    REC(EV_S3B, s3);

    // ---- main: dist L2 (A banks, d2A reuse after select L0) ----
    WAIT(0, EV_S3B);
    WAIT(0, EV_J0);
    mma_dist_kernel<<<mgrid, 512, MD_SMEM>>>(qhiAp, qloAp, thip, tlop, qnAp, tnAp,
                                             d2ap, minL[2], 8);
    REC(EV_D2, 0);

    // ---- s2: select L2 ----
    WAIT(s2, EV_D2);
    select_kernel<<<BQ, SEL_THREADS, SEL_SMEM, s2>>>(d2ap, minL[2], lab, totp, 0);

    // ---- s3: linear L3 (tA->tB, t3) + conv h3 (->qB); must wait dist L1 ----
    WAIT(s3, EV_D1);
    mma_linear_kernel<<<NTILES, 256, 0, s3>>>(thip, tlop, w3th, w3tl, b3,
                                              thi2p, tlo2p, tnBp, t3p, 8);
    conv_norm_kernel<<<BQ / 8, 256, 0, s3>>>(h3p, qhiBp, qloBp, qnBp, BQ, HD);
    REC(EV_S3C, s3);
    // s3 continues with layer-4 prep (overlaps dist L3)
    linear_softmax_kernel<<<(NT + 7) / 8, 256, 0, s3>>>(t3p, W4, b4, t4p, NT);
    min4_kernel<<<dim3(NTILES, BQ / 128), 256, 0, s3>>>(q4p, t4p, minL[4]);
    REC(EV_S3D, s3);

    // ---- main: dist L3 (B banks, d2B reuse after select L1) ----
    WAIT(0, EV_S3C);
    WAIT(0, EV_J1);
    mma_dist_kernel<<<mgrid, 512, MD_SMEM>>>(qhiBp, qloBp, thi2p, tlo2p, qnBp, tnBp,
                                             d2bp, minL[3], 8);
    REC(EV_D3, 0);

    // ---- s2: select L3, then select4 ----
    WAIT(s2, EV_D3);
    select_kernel<<<BQ, SEL_THREADS, SEL_SMEM, s2>>>(d2bp, minL[3], lab, totp, 0);
    WAIT(s2, EV_S3D);
    select4_kernel<<<BQ, SEL_THREADS, SEL_SMEM, s2>>>(q4p, t4p, minL[4], lab, totp);
    REC(EV_J4, s2);

    // ---- main: p-values ----
    WAIT(0, EV_J4);
    pvalue_kernel<<<BQ, 256>>>(totp, cali, out);

#undef REC
#undef WAIT
}

// round 17
// speedup vs baseline: 1.2017x; 1.0091x over previous
#include <cuda_runtime.h>
#include <cuda_bf16.h>
#include <math.h>
#include <stdint.h>

#define BQ   1024
#define NT   50000
#define NTP  50048
#define NL   8
#define KNN  75
#define HD   128
#define NC   10000
#define NTILES 391          // NTP/128

typedef unsigned long long u64;

// ---------------- device scratch ----------------
__device__ float g_q4[BQ * NL];
__device__ float g_t3[(size_t)NT * HD];
__device__ float g_t4[(size_t)NT * NL];
__device__ float g_d2a[(size_t)BQ * NT];
__device__ float g_d2b[(size_t)BQ * NT];
__device__ float g_minall[(size_t)5 * BQ * NTILES];
__device__ float g_qnX[4 * BQ];
__device__ float g_tnA[NT], g_tnB[NT];
__device__ float g_tot[BQ * NL];
__device__ float g_tot4[BQ * NL];
__device__ __nv_bfloat16 g_qhiX[(size_t)4 * BQ * 128];
__device__ __nv_bfloat16 g_qloX[(size_t)4 * BQ * 128];
__device__ __nv_bfloat16 g_thi[(size_t)NTP * 128];    // bank A
__device__ __nv_bfloat16 g_tlo[(size_t)NTP * 128];
__device__ __nv_bfloat16 g_thi2[(size_t)NTP * 128];   // bank B
__device__ __nv_bfloat16 g_tlo2[(size_t)NTP * 128];
__device__ __nv_bfloat16 g_w1th[128 * 128], g_w1tl[128 * 128];
__device__ __nv_bfloat16 g_w2th[128 * 128], g_w2tl[128 * 128];
__device__ __nv_bfloat16 g_w3th[128 * 128], g_w3tl[128 * 128];

// ---------------- overlap machinery (created once at load; no device mem) ----
static cudaStream_t g_s2 = 0, g_s3 = 0;
static cudaEvent_t g_ev[16];
static bool g_ok = false;
namespace {
enum { EV_PREP = 0, EV_D0, EV_D1, EV_D2, EV_D3,
       EV_S3A, EV_S3B, EV_S3C, EV_S3D,
       EV_J0, EV_J1, EV_J3, EV_COUNT };
struct StreamInit {
    StreamInit() {
        if (cudaStreamCreateWithFlags(&g_s2, cudaStreamNonBlocking) != cudaSuccess) return;
        if (cudaStreamCreateWithFlags(&g_s3, cudaStreamNonBlocking) != cudaSuccess) return;
        bool ok = true;
        for (int i = 0; i < EV_COUNT; i++)
            ok = ok && (cudaEventCreateWithFlags(&g_ev[i], cudaEventDisableTiming) == cudaSuccess);
        g_ok = ok;
    }
};
StreamInit g_si;
}

// ---------------------------------------------------------------------------
__device__ __forceinline__ void mma_bf16(float* d, const uint32_t* a, const uint32_t* b)
{
    asm volatile(
        "mma.sync.aligned.m16n8k16.row.col.f32.bf16.bf16.f32 "
        "{%0,%1,%2,%3}, {%4,%5,%6,%7}, {%8,%9}, {%0,%1,%2,%3};"
        : "+f"(d[0]), "+f"(d[1]), "+f"(d[2]), "+f"(d[3])
        : "r"(a[0]), "r"(a[1]), "r"(a[2]), "r"(a[3]), "r"(b[0]), "r"(b[1]));
}

#define SLICE_ELEMS (128 * 24)

__device__ __forceinline__ void slice_load_async(
    const __nv_bfloat16* __restrict__ Gp, __nv_bfloat16* Ss,
    int row0, int k0, int lr, int lh)
{
    uint32_t sa = (uint32_t)__cvta_generic_to_shared(Ss + lr * 24 + lh * 8);
    const void* ga = Gp + (size_t)(row0 + lr) * 128 + k0 + lh * 8;
    asm volatile("cp.async.cg.shared.global [%0], [%1], 16;\n" :: "r"(sa), "l"(ga));
}

// ---------------------------------------------------------------------------
// Layer-4 exact d2 helpers (fixed op order, shared by min4 / select4).
// ---------------------------------------------------------------------------
__device__ __forceinline__ float l4_qq(const float* q)
{
    float s = __fmul_rn(q[0], q[0]);
    s = __fmaf_rn(q[1], q[1], s); s = __fmaf_rn(q[2], q[2], s);
    s = __fmaf_rn(q[3], q[3], s); s = __fmaf_rn(q[4], q[4], s);
    s = __fmaf_rn(q[5], q[5], s); s = __fmaf_rn(q[6], q[6], s);
    s = __fmaf_rn(q[7], q[7], s);
    return s;
}
__device__ __forceinline__ float l4_d2f(const float* __restrict__ tr,
                                        const float* q, float qq)
{
    float tt = __fmul_rn(tr[0], tr[0]);
    tt = __fmaf_rn(tr[1], tr[1], tt); tt = __fmaf_rn(tr[2], tr[2], tt);
    tt = __fmaf_rn(tr[3], tr[3], tt); tt = __fmaf_rn(tr[4], tr[4], tt);
    tt = __fmaf_rn(tr[5], tr[5], tt); tt = __fmaf_rn(tr[6], tr[6], tt);
    tt = __fmaf_rn(tr[7], tr[7], tt);
    float dt = __fmul_rn(q[0], tr[0]);
    dt = __fmaf_rn(q[1], tr[1], dt); dt = __fmaf_rn(q[2], tr[2], dt);
    dt = __fmaf_rn(q[3], tr[3], dt); dt = __fmaf_rn(q[4], tr[4], dt);
    dt = __fmaf_rn(q[5], tr[5], dt); dt = __fmaf_rn(q[6], tr[6], dt);
    dt = __fmaf_rn(q[7], tr[7], dt);
    return fmaxf(__fmaf_rn(-2.f, dt, __fadd_rn(qq, tt)), 0.f);
}

// ---------------------------------------------------------------------------
__global__ void __launch_bounds__(256)
conv_norm_kernel(const float* __restrict__ A, __nv_bfloat16* __restrict__ hi,
                 __nv_bfloat16* __restrict__ lo, float* __restrict__ nrm,
                 int Mreal, int D)
{
    int warp = threadIdx.x >> 5, lane = threadIdx.x & 31;
    int row = blockIdx.x * 8 + warp;
    int base = lane * 4;

    float ss = 0.f;
    __nv_bfloat16 hb[4], lb[4];
#pragma unroll
    for (int j = 0; j < 4; j++) {
        int col = base + j;
        float v = (row < Mreal && col < D) ? A[(size_t)row * D + col] : 0.f;
        ss += v * v;
        hb[j] = __float2bfloat16_rn(v);
        lb[j] = __float2bfloat16_rn(v - __bfloat162float(hb[j]));
    }
    __nv_bfloat162 h01, h23, l01, l23;
    h01.x = hb[0]; h01.y = hb[1]; h23.x = hb[2]; h23.y = hb[3];
    l01.x = lb[0]; l01.y = lb[1]; l23.x = lb[2]; l23.y = lb[3];
    *(__nv_bfloat162*)&hi[(size_t)row * 128 + base]     = h01;
    *(__nv_bfloat162*)&hi[(size_t)row * 128 + base + 2] = h23;
    *(__nv_bfloat162*)&lo[(size_t)row * 128 + base]     = l01;
    *(__nv_bfloat162*)&lo[(size_t)row * 128 + base + 2] = l23;

#pragma unroll
    for (int off = 16; off > 0; off >>= 1) ss += __shfl_down_sync(0xFFFFFFFFu, ss, off);
    if (lane == 0 && row < Mreal) nrm[row] = ss;
}

// ---------------------------------------------------------------------------
__global__ void __launch_bounds__(256)
wt_convert_kernel(const float* __restrict__ W1, const float* __restrict__ W2,
                  const float* __restrict__ W3)
{
    int idx = blockIdx.x * 256 + threadIdx.x;
    if (idx >= 3 * 128 * 128) return;
    int which = idx >> 14;
    int e = idx & 16383;
    int n = e & 127, k = e >> 7;
    const float* W = (which == 0) ? W1 : (which == 1) ? W2 : W3;
    int K = (which == 0) ? 83 : 128;
    float v = (k < K) ? W[(size_t)k * 128 + n] : 0.f;
    __nv_bfloat16 h = __float2bfloat16_rn(v);
    __nv_bfloat16 l = __float2bfloat16_rn(v - __bfloat162float(h));
    __nv_bfloat16* dh = (which == 0) ? g_w1th : (which == 1) ? g_w2th : g_w3th;
    __nv_bfloat16* dl = (which == 0) ? g_w1tl : (which == 1) ? g_w2tl : g_w3tl;
    dh[e] = h;
    dl[e] = l;
}

// ---------------------------------------------------------------------------
// Fused query MLP: one kernel computes h1,h2,h3 (smem), emits per-layer
// qhi/qlo/qn banks and q4 (softmax). All math replicates the old kernels'
// operation order exactly -> bit-identical results.
// Dyn smem: As[1088] | Bs[2176] | hA[64*132] | hB[64*132]  (~80.6 KB)
// ---------------------------------------------------------------------------
#define QMLP_SMEM ((1088 + 2176 + 2 * 64 * 132) * 4)

__device__ void qmlp_stage(const float* __restrict__ gA, const float* sA, int K,
                           const float* __restrict__ W, const float* __restrict__ bias,
                           float* hOut, float* As, float* Bs,
                           int tx, int ty, int tid, int m0)
{
    float acc[4][8];
#pragma unroll
    for (int r = 0; r < 4; r++)
#pragma unroll
        for (int c = 0; c < 8; c++) acc[r][c] = 0.f;

    const int nChunks = (K + 15) / 16;
    for (int ch = 0; ch < nChunks; ch++) {
        const int k0 = ch * 16;
#pragma unroll
        for (int i = 0; i < 4; i++) {
            int e = tid + i * 256;
            int k = e & 15, m = e >> 4;
            float v = 0.f;
            if (k0 + k < K)
                v = gA ? gA[(size_t)(m0 + m) * K + k0 + k] : sA[m * 132 + k0 + k];
            As[k * 68 + m] = v;
        }
#pragma unroll
        for (int i = 0; i < 8; i++) {
            int e = tid + i * 256;
            int h = e & 127, k = e >> 7;
            float v = 0.f;
            if (k0 + k < K) v = W[(size_t)(k0 + k) * HD + h];
            Bs[k * 136 + h] = v;
        }
        __syncthreads();
#pragma unroll
        for (int k = 0; k < 16; k++) {
            float4 a  = *(const float4*)&As[k * 68 + ty * 4];
            float4 b0 = *(const float4*)&Bs[k * 136 + tx * 4];
            float4 b1 = *(const float4*)&Bs[k * 136 + 64 + tx * 4];
            float av[4] = {a.x, a.y, a.z, a.w};
            float bv[8] = {b0.x, b0.y, b0.z, b0.w, b1.x, b1.y, b1.z, b1.w};
#pragma unroll
            for (int r = 0; r < 4; r++)
#pragma unroll
                for (int c = 0; c < 8; c++) acc[r][c] += av[r] * bv[c];
        }
        __syncthreads();
    }
#pragma unroll
    for (int r = 0; r < 4; r++) {
        int m = ty * 4 + r;
#pragma unroll
        for (int half = 0; half < 2; half++) {
#pragma unroll
            for (int c = 0; c < 4; c++) {
                int h = half * 64 + tx * 4 + c;
                float v = acc[r][half * 4 + c] + bias[h];
                hOut[m * 132 + h] = fmaxf(v, 0.f);
            }
        }
    }
    __syncthreads();
}

// conv pass over a 64-row smem buffer; replicates conv_norm_kernel exactly.
__device__ void qmlp_conv(const float* hsm, __nv_bfloat16* __restrict__ hi,
                          __nv_bfloat16* __restrict__ lo, float* __restrict__ nrm,
                          int m0, int tid)
{
    int warp = tid >> 5, lane = tid & 31;
    int base = lane * 4;
    for (int rr = warp; rr < 64; rr += 8) {
        int row = m0 + rr;
        float ss = 0.f;
        __nv_bfloat16 hb[4], lb[4];
#pragma unroll
        for (int j = 0; j < 4; j++) {
            float v = hsm[rr * 132 + base + j];
            ss += v * v;
            hb[j] = __float2bfloat16_rn(v);
            lb[j] = __float2bfloat16_rn(v - __bfloat162float(hb[j]));
        }
        __nv_bfloat162 h01, h23, l01, l23;
        h01.x = hb[0]; h01.y = hb[1]; h23.x = hb[2]; h23.y = hb[3];
        l01.x = lb[0]; l01.y = lb[1]; l23.x = lb[2]; l23.y = lb[3];
        *(__nv_bfloat162*)&hi[(size_t)row * 128 + base]     = h01;
        *(__nv_bfloat162*)&hi[(size_t)row * 128 + base + 2] = h23;
        *(__nv_bfloat162*)&lo[(size_t)row * 128 + base]     = l01;
        *(__nv_bfloat162*)&lo[(size_t)row * 128 + base + 2] = l23;
#pragma unroll
        for (int off = 16; off > 0; off >>= 1)
            ss += __shfl_down_sync(0xFFFFFFFFu, ss, off);
        if (lane == 0) nrm[row] = ss;
    }
    __syncthreads();
}

__global__ void __launch_bounds__(256)
fused_qmlp_kernel(const float* __restrict__ x,
                  const float* __restrict__ W1, const float* __restrict__ b1,
                  const float* __restrict__ W2, const float* __restrict__ b2,
                  const float* __restrict__ W3, const float* __restrict__ b3,
                  const float* __restrict__ W4, const float* __restrict__ b4,
                  __nv_bfloat16* __restrict__ qhiX, __nv_bfloat16* __restrict__ qloX,
                  float* __restrict__ qnX, float* __restrict__ q4)
{
    extern __shared__ float fsm[];
    float* As = fsm;
    float* Bs = fsm + 1088;
    float* hA = fsm + 1088 + 2176;
    float* hB = hA + 64 * 132;
    const int tx = threadIdx.x, ty = threadIdx.y;
    const int tid = ty * 16 + tx;
    const int m0 = blockIdx.x * 64;

    // layer 1: x -> hA, emit bank 1
    qmlp_stage(x, (const float*)0, 83, W1, b1, hA, As, Bs, tx, ty, tid, m0);
    qmlp_conv(hA, qhiX + (size_t)1 * BQ * 128, qloX + (size_t)1 * BQ * 128,
              qnX + 1 * BQ, m0, tid);
    // layer 2: hA -> hB, emit bank 2
    qmlp_stage((const float*)0, hA, 128, W2, b2, hB, As, Bs, tx, ty, tid, m0);
    qmlp_conv(hB, qhiX + (size_t)2 * BQ * 128, qloX + (size_t)2 * BQ * 128,
              qnX + 2 * BQ, m0, tid);
    // layer 3: hB -> hA, emit bank 3
    qmlp_stage((const float*)0, hB, 128, W3, b3, hA, As, Bs, tx, ty, tid, m0);
    qmlp_conv(hA, qhiX + (size_t)3 * BQ * 128, qloX + (size_t)3 * BQ * 128,
              qnX + 3 * BQ, m0, tid);

    // softmax: hA -> q4 (replicates linear_softmax_kernel math)
    float* Ws = As;       // 1024 floats
    float* bs = Bs;       // 8 floats
    for (int i = tid; i < HD * NL; i += 256) Ws[i] = W4[i];
    if (tid < NL) bs[tid] = b4[tid];
    __syncthreads();

    int warp = tid >> 5, lane = tid & 31;
    for (int rr = warp; rr < 64; rr += 8) {
        int m = m0 + rr;
        float acc[NL];
#pragma unroll
        for (int h = 0; h < NL; h++) acc[h] = 0.f;
        for (int k = lane; k < HD; k += 32) {
            float xv = hA[rr * 132 + k];
#pragma unroll
            for (int h = 0; h < NL; h++) acc[h] += xv * Ws[k * NL + h];
        }
#pragma unroll
        for (int h = 0; h < NL; h++)
#pragma unroll
            for (int off = 16; off > 0; off >>= 1)
                acc[h] += __shfl_down_sync(0xFFFFFFFFu, acc[h], off);
        if (lane == 0) {
            float v[NL], mx = -1e30f;
#pragma unroll
            for (int h = 0; h < NL; h++) { v[h] = acc[h] + bs[h]; mx = fmaxf(mx, v[h]); }
            float s = 0.f;
#pragma unroll
            for (int h = 0; h < NL; h++) { v[h] = expf(v[h] - mx); s += v[h]; }
            float inv = 1.0f / s;
#pragma unroll
            for (int h = 0; h < NL; h++) q4[(size_t)m * NL + h] = v[h] * inv;
        }
    }
}

// ---------------------------------------------------------------------------
// bf16x3 GEMM mainloop (128-row tiles) - used by mma_linear_kernel.
// ---------------------------------------------------------------------------
__device__ __forceinline__ void gemm3_mainloop(
    const __nv_bfloat16* Ahi, const __nv_bfloat16* Alo,
    const __nv_bfloat16* Bhi, const __nv_bfloat16* Blo,
    __nv_bfloat16* smem, int m0, int n0, int nCh,
    int wm, int wn, int fr, int fc, int lr, int lh,
    float acc[2][8][4])
{
    __nv_bfloat16* AhiS[2] = {smem,                   smem + 4 * SLICE_ELEMS};
    __nv_bfloat16* AloS[2] = {smem + 1 * SLICE_ELEMS, smem + 5 * SLICE_ELEMS};
    __nv_bfloat16* BhiS[2] = {smem + 2 * SLICE_ELEMS, smem + 6 * SLICE_ELEMS};
    __nv_bfloat16* BloS[2] = {smem + 3 * SLICE_ELEMS, smem + 7 * SLICE_ELEMS};

    slice_load_async(Ahi, AhiS[0], m0, 0, lr, lh);
    slice_load_async(Alo, AloS[0], m0, 0, lr, lh);
    slice_load_async(Bhi, BhiS[0], n0, 0, lr, lh);
    slice_load_async(Blo, BloS[0], n0, 0, lr, lh);
    asm volatile("cp.async.commit_group;\n" ::: "memory");

    for (int c = 0; c < nCh; c++) {
        int buf = c & 1;
        if (c + 1 < nCh) {
            int k0 = (c + 1) * 16;
            slice_load_async(Ahi, AhiS[buf ^ 1], m0, k0, lr, lh);
            slice_load_async(Alo, AloS[buf ^ 1], m0, k0, lr, lh);
            slice_load_async(Bhi, BhiS[buf ^ 1], n0, k0, lr, lh);
            slice_load_async(Blo, BloS[buf ^ 1], n0, k0, lr, lh);
            asm volatile("cp.async.commit_group;\n" ::: "memory");
            asm volatile("cp.async.wait_group 1;" ::: "memory");
        } else {
            asm volatile("cp.async.wait_group 0;" ::: "memory");
        }
        __syncthreads();

        const __nv_bfloat16* Ah = AhiS[buf];
        const __nv_bfloat16* Al = AloS[buf];
        const __nv_bfloat16* Bh = BhiS[buf];
        const __nv_bfloat16* Bl = BloS[buf];

        uint32_t ah[2][4];
#pragma unroll
        for (int mt = 0; mt < 2; mt++) {
            int bm = wm + mt * 16;
            ah[mt][0] = *(const uint32_t*)&Ah[(bm + fr) * 24 + fc];
            ah[mt][1] = *(const uint32_t*)&Ah[(bm + fr + 8) * 24 + fc];
            ah[mt][2] = *(const uint32_t*)&Ah[(bm + fr) * 24 + fc + 8];
            ah[mt][3] = *(const uint32_t*)&Ah[(bm + fr + 8) * 24 + fc + 8];
        }
        uint32_t bh8[8][2];
#pragma unroll
        for (int nt = 0; nt < 8; nt++) {
            int nb = wn + nt * 8;
            bh8[nt][0] = *(const uint32_t*)&Bh[(nb + fr) * 24 + fc];
            bh8[nt][1] = *(const uint32_t*)&Bh[(nb + fr) * 24 + fc + 8];
        }
#pragma unroll
        for (int nt = 0; nt < 8; nt++) {
            mma_bf16(acc[0][nt], ah[0], bh8[nt]);
            mma_bf16(acc[1][nt], ah[1], bh8[nt]);
        }
        uint32_t al[2][4];
#pragma unroll
        for (int mt = 0; mt < 2; mt++) {
            int bm = wm + mt * 16;
            al[mt][0] = *(const uint32_t*)&Al[(bm + fr) * 24 + fc];
            al[mt][1] = *(const uint32_t*)&Al[(bm + fr + 8) * 24 + fc];
            al[mt][2] = *(const uint32_t*)&Al[(bm + fr) * 24 + fc + 8];
            al[mt][3] = *(const uint32_t*)&Al[(bm + fr + 8) * 24 + fc + 8];
        }
#pragma unroll
        for (int nt = 0; nt < 8; nt++) {
            mma_bf16(acc[0][nt], al[0], bh8[nt]);
            mma_bf16(acc[1][nt], al[1], bh8[nt]);
        }
#pragma unroll
        for (int nt = 0; nt < 8; nt++) {
            int nb = wn + nt * 8;
            uint32_t bl[2];
            bl[0] = *(const uint32_t*)&Bl[(nb + fr) * 24 + fc];
            bl[1] = *(const uint32_t*)&Bl[(nb + fr) * 24 + fc + 8];
            mma_bf16(acc[0][nt], ah[0], bl);
            mma_bf16(acc[1][nt], ah[1], bl);
        }
        __syncthreads();
    }
}

// ---------------------------------------------------------------------------
// 256x128 distance GEMM, 512 threads, 3-stage pipeline, 1 sync per chunk.
// ---------------------------------------------------------------------------
#define ASL (256 * 24)
#define BSL (128 * 24)
#define STAGE_ELEMS (2 * ASL + 2 * BSL)
#define MD_SMEM (3 * STAGE_ELEMS * 2)

__global__ void __launch_bounds__(512, 1)
mma_dist_kernel(const __nv_bfloat16* __restrict__ Qhi, const __nv_bfloat16* __restrict__ Qlo,
                const __nv_bfloat16* __restrict__ Thi, const __nv_bfloat16* __restrict__ Tlo,
                const float* __restrict__ qn, const float* __restrict__ tn,
                float* __restrict__ out, float* __restrict__ gmin, int nCh)
{
    extern __shared__ __align__(16) __nv_bfloat16 dsm[];
    __shared__ float sMin[256][2];
    const int tid = threadIdx.x;
    const int wid = tid >> 5, lane = tid & 31;
    const int n0 = blockIdx.x * 128;
    const int m0 = blockIdx.y * 256;
    const int wm = (wid & 7) * 32;
    const int wn = (wid >> 3) * 64;
    const int fr = lane >> 2, fc = (lane & 3) * 2;
    const int ar = tid >> 1, ah2 = tid & 1;
    const int br = (tid & 255) >> 1, bh2 = tid & 1;

    float acc[2][8][4];
#pragma unroll
    for (int mt = 0; mt < 2; mt++)
#pragma unroll
        for (int nt = 0; nt < 8; nt++)
#pragma unroll
            for (int j = 0; j < 4; j++) acc[mt][nt][j] = 0.f;

#define LOAD_STAGE(s, k0) do {                                                  \
        __nv_bfloat16* sb_ = dsm + (s) * STAGE_ELEMS;                           \
        slice_load_async(Qhi, sb_,            m0, (k0), ar, ah2);               \
        slice_load_async(Qlo, sb_ + ASL,      m0, (k0), ar, ah2);               \
        if (tid < 256) slice_load_async(Thi, sb_ + 2 * ASL,      n0, (k0), br, bh2); \
        else           slice_load_async(Tlo, sb_ + 2 * ASL + BSL, n0, (k0), br, bh2); \
        asm volatile("cp.async.commit_group;\n" ::: "memory");                  \
    } while (0)

    LOAD_STAGE(0, 0);
    if (nCh > 1) LOAD_STAGE(1, 16);

    for (int c = 0; c < nCh; c++) {
        if (c + 1 < nCh) asm volatile("cp.async.wait_group 1;" ::: "memory");
        else             asm volatile("cp.async.wait_group 0;" ::: "memory");
        __syncthreads();
        if (c + 2 < nCh) LOAD_STAGE((c + 2) % 3, (c + 2) * 16);

        const __nv_bfloat16* sb = dsm + (c % 3) * STAGE_ELEMS;
        const __nv_bfloat16* Ah = sb;
        const __nv_bfloat16* Al = sb + ASL;
        const __nv_bfloat16* Bh = sb + 2 * ASL;
        const __nv_bfloat16* Bl = sb + 2 * ASL + BSL;

        uint32_t ah[2][4];
#pragma unroll
        for (int mt = 0; mt < 2; mt++) {
            int bm = wm + mt * 16;
            ah[mt][0] = *(const uint32_t*)&Ah[(bm + fr) * 24 + fc];
            ah[mt][1] = *(const uint32_t*)&Ah[(bm + fr + 8) * 24 + fc];
            ah[mt][2] = *(const uint32_t*)&Ah[(bm + fr) * 24 + fc + 8];
            ah[mt][3] = *(const uint32_t*)&Ah[(bm + fr + 8) * 24 + fc + 8];
        }
        uint32_t bh8[8][2];
#pragma unroll
        for (int nt = 0; nt < 8; nt++) {
            int nb = wn + nt * 8;
            bh8[nt][0] = *(const uint32_t*)&Bh[(nb + fr) * 24 + fc];
            bh8[nt][1] = *(const uint32_t*)&Bh[(nb + fr) * 24 + fc + 8];
        }
#pragma unroll
        for (int nt = 0; nt < 8; nt++) {
            mma_bf16(acc[0][nt], ah[0], bh8[nt]);
            mma_bf16(acc[1][nt], ah[1], bh8[nt]);
        }
        uint32_t al[2][4];
#pragma unroll
        for (int mt = 0; mt < 2; mt++) {
            int bm = wm + mt * 16;
            al[mt][0] = *(const uint32_t*)&Al[(bm + fr) * 24 + fc];
            al[mt][1] = *(const uint32_t*)&Al[(bm + fr + 8) * 24 + fc];
            al[mt][2] = *(const uint32_t*)&Al[(bm + fr) * 24 + fc + 8];
            al[mt][3] = *(const uint32_t*)&Al[(bm + fr + 8) * 24 + fc + 8];
        }
#pragma unroll
        for (int nt = 0; nt < 8; nt++) {
            mma_bf16(acc[0][nt], al[0], bh8[nt]);
            mma_bf16(acc[1][nt], al[1], bh8[nt]);
        }
#pragma unroll
        for (int nt = 0; nt < 8; nt++) {
            int nb = wn + nt * 8;
            uint32_t bl[2];
            bl[0] = *(const uint32_t*)&Bl[(nb + fr) * 24 + fc];
            bl[1] = *(const uint32_t*)&Bl[(nb + fr) * 24 + fc + 8];
            mma_bf16(acc[0][nt], ah[0], bl);
            mma_bf16(acc[1][nt], ah[1], bl);
        }
    }
#undef LOAD_STAGE

    const float FINF = __int_as_float(0x7F800000);
    float rmin[2][2] = {{FINF, FINF}, {FINF, FINF}};
#pragma unroll
    for (int mt = 0; mt < 2; mt++) {
        int mrow = m0 + wm + mt * 16 + fr;
        float q0 = qn[mrow], q1 = qn[mrow + 8];
#pragma unroll
        for (int nt = 0; nt < 8; nt++) {
            int n = n0 + wn + nt * 8 + fc;
            if (n < NT) {
                float t0 = tn[n], t1 = tn[n + 1];
                float2 o;
                o.x = fmaxf(q0 + t0 - 2.f * acc[mt][nt][0], 0.f);
                o.y = fmaxf(q0 + t1 - 2.f * acc[mt][nt][1], 0.f);
                *(float2*)&out[(size_t)mrow * NT + n] = o;
                rmin[mt][0] = fminf(rmin[mt][0], fminf(o.x, o.y));
                o.x = fmaxf(q1 + t0 - 2.f * acc[mt][nt][2], 0.f);
                o.y = fmaxf(q1 + t1 - 2.f * acc[mt][nt][3], 0.f);
                *(float2*)&out[(size_t)(mrow + 8) * NT + n] = o;
                rmin[mt][1] = fminf(rmin[mt][1], fminf(o.x, o.y));
            }
        }
    }
    __syncthreads();
#pragma unroll
    for (int mt = 0; mt < 2; mt++)
#pragma unroll
        for (int rr = 0; rr < 2; rr++) {
            float m = rmin[mt][rr];
            m = fminf(m, __shfl_xor_sync(0xFFFFFFFFu, m, 1));
            m = fminf(m, __shfl_xor_sync(0xFFFFFFFFu, m, 2));
            if ((lane & 3) == 0)
                sMin[wm + mt * 16 + rr * 8 + fr][wn >> 6] = m;
        }
    __syncthreads();
    if (tid < 256)
        gmin[(size_t)(m0 + tid) * NTILES + blockIdx.x] =
            fminf(sMin[tid][0], sMin[tid][1]);
}

// ---------------------------------------------------------------------------
__global__ void __launch_bounds__(256, 2)
mma_linear_kernel(const __nv_bfloat16* __restrict__ Ahi, const __nv_bfloat16* __restrict__ Alo,
                  const __nv_bfloat16* __restrict__ Wth, const __nv_bfloat16* __restrict__ Wtl,
                  const float* __restrict__ bias,
                  __nv_bfloat16* __restrict__ Ohi, __nv_bfloat16* __restrict__ Olo,
                  float* __restrict__ nrm, float* __restrict__ Ofp, int nCh)
{
    __shared__ __align__(16) __nv_bfloat16 smem[8 * SLICE_ELEMS];
    __shared__ float snorm[128];
    __shared__ float sbias[128];
    const int tid = threadIdx.x;
    const int wid = tid >> 5, lane = tid & 31;
    const int m0 = blockIdx.x * 128;
    const int wm = (wid & 3) * 32;
    const int wn = (wid >> 2) * 64;
    const int lr = tid >> 1, lh = tid & 1;
    const int fr = lane >> 2, fc = (lane & 3) * 2;

    if (tid < 128) { sbias[tid] = bias[tid]; snorm[tid] = 0.f; }

    float acc[2][8][4];
#pragma unroll
    for (int mt = 0; mt < 2; mt++)
#pragma unroll
        for (int nt = 0; nt < 8; nt++)
#pragma unroll
            for (int j = 0; j < 4; j++) acc[mt][nt][j] = 0.f;

    gemm3_mainloop(Ahi, Alo, Wth, Wtl, smem, m0, 0, nCh,
                   wm, wn, fr, fc, lr, lh, acc);

#pragma unroll
    for (int mt = 0; mt < 2; mt++) {
        int r0 = wm + mt * 16 + fr;
        int r1 = r0 + 8;
        size_t g0 = (size_t)(m0 + r0) * 128;
        size_t g1 = (size_t)(m0 + r1) * 128;
        float ns0 = 0.f, ns1 = 0.f;
#pragma unroll
        for (int nt = 0; nt < 8; nt++) {
            int n = wn + nt * 8 + fc;
            float b0 = sbias[n], b1 = sbias[n + 1];
            float v00 = fmaxf(acc[mt][nt][0] + b0, 0.f);
            float v01 = fmaxf(acc[mt][nt][1] + b1, 0.f);
            float v10 = fmaxf(acc[mt][nt][2] + b0, 0.f);
            float v11 = fmaxf(acc[mt][nt][3] + b1, 0.f);
            ns0 += v00 * v00 + v01 * v01;
            ns1 += v10 * v10 + v11 * v11;
            __nv_bfloat162 h, l;
            h.x = __float2bfloat16_rn(v00);
            h.y = __float2bfloat16_rn(v01);
            l.x = __float2bfloat16_rn(v00 - __bfloat162float(h.x));
            l.y = __float2bfloat16_rn(v01 - __bfloat162float(h.y));
            *(__nv_bfloat162*)&Ohi[g0 + n] = h;
            *(__nv_bfloat162*)&Olo[g0 + n] = l;
            h.x = __float2bfloat16_rn(v10);
            h.y = __float2bfloat16_rn(v11);
            l.x = __float2bfloat16_rn(v10 - __bfloat162float(h.x));
            l.y = __float2bfloat16_rn(v11 - __bfloat162float(h.y));
            *(__nv_bfloat162*)&Ohi[g1 + n] = h;
            *(__nv_bfloat162*)&Olo[g1 + n] = l;
            if (Ofp) {
                *(float2*)&Ofp[g0 + n] = make_float2(v00, v01);
                *(float2*)&Ofp[g1 + n] = make_float2(v10, v11);
            }
        }
        atomicAdd(&snorm[r0], ns0);
        atomicAdd(&snorm[r1], ns1);
    }
    __syncthreads();
    if (tid < 128 && m0 + tid < NT) nrm[m0 + tid] = snorm[tid];
}

// ---------------------------------------------------------------------------
__global__ void __launch_bounds__(256)
linear_softmax_kernel(const float* __restrict__ A, const float* __restrict__ W,
                      const float* __restrict__ bias, float* __restrict__ out, int M)
{
    __shared__ float Ws[HD * NL];
    __shared__ float bs[NL];
    int tid = threadIdx.x;
    for (int i = tid; i < HD * NL; i += 256) Ws[i] = W[i];
    if (tid < NL) bs[tid] = bias[tid];
    __syncthreads();

    int warp = tid >> 5, lane = tid & 31;
    int m = blockIdx.x * 8 + warp;
    if (m >= M) return;

    float acc[NL];
#pragma unroll
    for (int h = 0; h < NL; h++) acc[h] = 0.f;
    for (int k = lane; k < HD; k += 32) {
        float x = A[(size_t)m * HD + k];
#pragma unroll
        for (int h = 0; h < NL; h++) acc[h] += x * Ws[k * NL + h];
    }
#pragma unroll
    for (int h = 0; h < NL; h++)
#pragma unroll
        for (int off = 16; off > 0; off >>= 1)
            acc[h] += __shfl_down_sync(0xFFFFFFFFu, acc[h], off);

    if (lane == 0) {
        float v[NL], mx = -1e30f;
#pragma unroll
        for (int h = 0; h < NL; h++) { v[h] = acc[h] + bs[h]; mx = fmaxf(mx, v[h]); }
        float s = 0.f;
#pragma unroll
        for (int h = 0; h < NL; h++) { v[h] = expf(v[h] - mx); s += v[h]; }
        float inv = 1.0f / s;
#pragma unroll
        for (int h = 0; h < NL; h++) out[(size_t)m * NL + h] = v[h] * inv;
    }
}

// ---------------------------------------------------------------------------
// Layer-4 tile minima WITHOUT materializing d2.
// ---------------------------------------------------------------------------
__global__ void __launch_bounds__(256)
min4_kernel(const float* __restrict__ q4, const float* __restrict__ t4,
            float* __restrict__ gmin)
{
    __shared__ float st[128 * 8];
    __shared__ float sq[128 * 8];
    const int t = blockIdx.x;
    const int q0 = blockIdx.y * 128;
    const int tid = threadIdx.x;
    const float FINF = __int_as_float(0x7F800000);

    for (int i = tid; i < 1024; i += 256) {
        int row = t * 128 + (i >> 3);
        st[i] = (row < NT) ? t4[(size_t)row * 8 + (i & 7)] : 0.f;
        sq[i] = q4[(size_t)(q0 + (i >> 3)) * 8 + (i & 7)];
    }
    __syncthreads();

    const int qi = tid >> 1, half = tid & 1;
    float q[8];
#pragma unroll
    for (int j = 0; j < 8; j++) q[j] = sq[qi * 8 + j];
    const float qq = l4_qq(q);

    float m = FINF;
    const int rbase = half * 64;
    for (int r = 0; r < 64; r++) {
        int row = t * 128 + rbase + r;
        if (row < NT)
            m = fminf(m, l4_d2f(&st[(rbase + r) * 8], q, qq));
    }
    m = fminf(m, __shfl_xor_sync(0xFFFFFFFFu, m, 1));
    if (half == 0)
        gmin[(size_t)(q0 + qi) * NTILES + t] = m;
}

// ---------------------------------------------------------------------------
__device__ __forceinline__ void find_kth(const unsigned* hist, int NB, unsigned kth,
                                         int tid, unsigned* s_bin, unsigned* s_kthr)
{
    if (tid < 32) {
        unsigned running = 0;
        for (int base = 0; base < NB; base += 32) {
            unsigned v = hist[base + tid];
            unsigned sc = v;
#pragma unroll
            for (int off = 1; off < 32; off <<= 1) {
                unsigned t = __shfl_up_sync(0xFFFFFFFFu, sc, off);
                if (tid >= off) sc += t;
            }
            unsigned tot = __shfl_sync(0xFFFFFFFFu, sc, 31);
            if (running + tot >= kth) {
                unsigned mask = __ballot_sync(0xFFFFFFFFu, running + sc >= kth);
                int l = __ffs(mask) - 1;
                if (tid == l) { *s_bin = (unsigned)(base + l); *s_kthr = kth - running - (sc - v); }
                break;
            }
            running += tot;
        }
    }
}

// ---------------------------------------------------------------------------
// Exact top-K select (layers 0-3): tile-min threshold + tile-subset d2 scan.
// ---------------------------------------------------------------------------
#define SEL_THREADS 512
#define SEL_CAP 2048
#define OFF_CAND  16384
#define OFF_SEL   (OFF_CAND + SEL_CAP * 8)
#define OFF_TIES  (OFF_SEL + 1024)
#define OFF_TLAB  (OFF_TIES + 1024)
#define OFF_MINS  (OFF_TLAB + 512)
#define OFF_TLIST (OFF_MINS + 392 * 4)
#define SEL_SMEM  (OFF_TLIST + 392 * 4)

__global__ void __launch_bounds__(SEL_THREADS)
select_kernel(const float* __restrict__ d2mat, const float* __restrict__ gmin,
              const int* __restrict__ labels, float* __restrict__ total, int init)
{
    extern __shared__ __align__(16) char sms[];
    unsigned* hist = (unsigned*)sms;
    u64* cand  = (u64*)(sms + OFF_CAND);
    u64* sel   = (u64*)(sms + OFF_SEL);
    u64* ties  = (u64*)(sms + OFF_TIES);
    int* tlab  = (int*)(sms + OFF_TLAB);
    float* mins = (float*)(sms + OFF_MINS);
    int* tlist = (int*)(sms + OFF_TLIST);

    __shared__ unsigned s_M75, s_bin, s_kthr, s_candcnt, s_selcnt, s_tiecnt, s_ntiles;
    __shared__ float s_w[80];
    __shared__ int s_lab[80];

    const int b = blockIdx.x, tid = threadIdx.x, lane = tid & 31;
    const uint4* usrc = (const uint4*)(d2mat + (size_t)b * NT);
    const int NH = NT / 4;

    for (int i = tid; i < NTILES; i += SEL_THREADS)
        mins[i] = gmin[(size_t)b * NTILES + i];
    if (tid == 0) { s_candcnt = 0; s_selcnt = 0; s_tiecnt = 0; s_ntiles = 0; }
    __syncthreads();

    if (tid < NTILES) {
        unsigned key = __float_as_uint(mins[tid]);
        int c = 0;
        for (int j = 0; j < NTILES; j++) {
            unsigned kj = __float_as_uint(mins[j]);
            c += (kj < key) || (kj == key && j < tid);
        }
        if (c == KNN - 1) s_M75 = key;
    }
    __syncthreads();
    const unsigned Mkey = s_M75;

    if (tid < NTILES) {
        if (__float_as_uint(mins[tid]) <= Mkey) {
            unsigned s = atomicAdd(&s_ntiles, 1u);
            tlist[s] = tid;
        }
    }
    __syncthreads();
    const int ntl = (int)s_ntiles;

    for (int w = tid; w < ntl * 32; w += SEL_THREADS) {
        int t = tlist[w >> 5];
        int i4 = t * 32 + (w & 31);
        if (i4 < NH) {
            uint4 a = usrc[i4];
            unsigned k[4] = {a.x, a.y, a.z, a.w};
#pragma unroll
            for (int j = 0; j < 4; j++) {
                if (k[j] <= Mkey) {
                    unsigned s = atomicAdd(&s_candcnt, 1u);
                    if (s < SEL_CAP) cand[s] = ((u64)k[j] << 32) | (unsigned)(i4 * 4 + j);
                }
            }
        }
    }
    __syncthreads();

    unsigned Tkey;
    const unsigned candTotal = s_candcnt;

    if (candTotal <= SEL_CAP) {
        const int cc = (int)candTotal;
        for (int i = tid; i < 4096; i += SEL_THREADS) hist[i] = 0;
        __syncthreads();
        for (int i = tid; i < cc; i += SEL_THREADS)
            atomicAdd(&hist[(unsigned)(cand[i] >> 52)], 1u);
        __syncthreads();
        find_kth(hist, 4096, KNN, tid, &s_bin, &s_kthr);
        __syncthreads();
        const unsigned pfx = s_bin;
        const unsigned k1v = s_kthr;
        for (int i = tid; i < 4096; i += SEL_THREADS) hist[i] = 0;
        __syncthreads();
        for (int i = tid; i < cc; i += SEL_THREADS) {
            unsigned key = (unsigned)(cand[i] >> 32);
            if ((key >> 20) == pfx) atomicAdd(&hist[(key >> 8) & 0xFFFu], 1u);
        }
        __syncthreads();
        find_kth(hist, 4096, k1v, tid, &s_bin, &s_kthr);
        __syncthreads();
        const unsigned pfx20 = (pfx << 12) | s_bin;
        const unsigned k2v = s_kthr;
        for (int i = tid; i < 256; i += SEL_THREADS) hist[i] = 0;
        __syncthreads();
        for (int i = tid; i < cc; i += SEL_THREADS) {
            unsigned key = (unsigned)(cand[i] >> 32);
            if ((key >> 8) == pfx20) atomicAdd(&hist[key & 0xFFu], 1u);
        }
        __syncthreads();
        find_kth(hist, 256, k2v, tid, &s_bin, &s_kthr);
        __syncthreads();
        Tkey = (pfx20 << 8) | s_bin;
        for (int i = tid; i < cc; i += SEL_THREADS) {
            u64 cv = cand[i];
            unsigned key = (unsigned)(cv >> 32);
            if (key < Tkey) {
                unsigned s = atomicAdd(&s_selcnt, 1u);
                if (s < 128) sel[s] = cv;
            } else if (key == Tkey) {
                unsigned s = atomicAdd(&s_tiecnt, 1u);
                if (s < 128) ties[s] = cv;
            }
        }
        __syncthreads();
    } else {
        for (int i = tid; i < 4096; i += SEL_THREADS) hist[i] = 0;
        __syncthreads();
        for (int w = tid; w < ntl * 32; w += SEL_THREADS) {
            int t = tlist[w >> 5];
            int i4 = t * 32 + (w & 31);
            uint4 a = (i4 < NH) ? usrc[i4] : make_uint4(~0u, ~0u, ~0u, ~0u);
            unsigned k[4] = {a.x, a.y, a.z, a.w};
#pragma unroll
            for (int j = 0; j < 4; j++) {
                unsigned bin = (k[j] <= Mkey) ? (k[j] >> 20) : 0xFFFFFFFFu;
                unsigned grp = __match_any_sync(0xFFFFFFFFu, bin);
                if (bin != 0xFFFFFFFFu && lane == __ffs(grp) - 1)
                    atomicAdd(&hist[bin], (unsigned)__popc(grp));
            }
        }
        __syncthreads();
        find_kth(hist, 4096, KNN, tid, &s_bin, &s_kthr);
        __syncthreads();
        const unsigned pfx = s_bin;
        const unsigned k1v = s_kthr;

        for (int i = tid; i < 4096; i += SEL_THREADS) hist[i] = 0;
        __syncthreads();
        for (int w = tid; w < ntl * 32; w += SEL_THREADS) {
            int t = tlist[w >> 5];
            int i4 = t * 32 + (w & 31);
            uint4 a = (i4 < NH) ? usrc[i4] : make_uint4(~0u, ~0u, ~0u, ~0u);
            unsigned k[4] = {a.x, a.y, a.z, a.w};
#pragma unroll
            for (int j = 0; j < 4; j++) {
                unsigned bin = (k[j] <= Mkey && (k[j] >> 20) == pfx)
                               ? ((k[j] >> 8) & 0xFFFu) : 0xFFFFFFFFu;
                unsigned grp = __match_any_sync(0xFFFFFFFFu, bin);
                if (bin != 0xFFFFFFFFu && lane == __ffs(grp) - 1)
                    atomicAdd(&hist[bin], (unsigned)__popc(grp));
            }
        }
        __syncthreads();
        find_kth(hist, 4096, k1v, tid, &s_bin, &s_kthr);
        __syncthreads();
        const unsigned pfx20 = (pfx << 12) | s_bin;
        const unsigned k2v = s_kthr;

        for (int i = tid; i < 256; i += SEL_THREADS) hist[i] = 0;
        __syncthreads();
        for (int w = tid; w < ntl * 32; w += SEL_THREADS) {
            int t = tlist[w >> 5];
            int i4 = t * 32 + (w & 31);
            uint4 a = (i4 < NH) ? usrc[i4] : make_uint4(~0u, ~0u, ~0u, ~0u);
            unsigned k[4] = {a.x, a.y, a.z, a.w};
#pragma unroll
            for (int j = 0; j < 4; j++) {
                unsigned bin = (k[j] <= Mkey && (k[j] >> 8) == pfx20)
                               ? (k[j] & 0xFFu) : 0xFFFFFFFFu;
                unsigned grp = __match_any_sync(0xFFFFFFFFu, bin);
                if (bin != 0xFFFFFFFFu && lane == __ffs(grp) - 1)
                    atomicAdd(&hist[bin], (unsigned)__popc(grp));
            }
        }
        __syncthreads();
        find_kth(hist, 256, k2v, tid, &s_bin, &s_kthr);
        __syncthreads();
        Tkey = (pfx20 << 8) | s_bin;

        for (int w = tid; w < ntl * 32; w += SEL_THREADS) {
            int t = tlist[w >> 5];
            int i4 = t * 32 + (w & 31);
            if (i4 < NH) {
                uint4 a = usrc[i4];
                unsigned k[4] = {a.x, a.y, a.z, a.w};
#pragma unroll
                for (int j = 0; j < 4; j++) {
                    if (k[j] < Tkey) {
                        unsigned s = atomicAdd(&s_selcnt, 1u);
                        if (s < 128) sel[s] = ((u64)k[j] << 32) | (unsigned)(i4 * 4 + j);
                    } else if (k[j] == Tkey) {
                        unsigned s = atomicAdd(&s_tiecnt, 1u);
                        if (s < 128) ties[s] = ((u64)k[j] << 32) | (unsigned)(i4 * 4 + j);
                    }
                }
            }
        }
        __syncthreads();
    }

    const int ns = min((int)s_selcnt, 128);
    const int ne = min((int)s_tiecnt, 128);

    if (tid < ns) {
        u64 mine = sel[tid];
        unsigned my_idx = (unsigned)(mine & 0xFFFFFFFFu);
        int rank = 0;
        for (int j = 0; j < ns; j++) rank += ((unsigned)(sel[j] & 0xFFFFFFFFu) < my_idx);
        float d2 = __uint_as_float((unsigned)(mine >> 32));
        s_w[rank] = (d2 > 0.f) ? __fdiv_rn(1.0f, __fsqrt_rn(d2)) : 0.f;
        s_lab[rank] = labels[my_idx];
    }
    if (tid >= 128 && tid - 128 < ne) {
        int t = tid - 128;
        unsigned my_idx = (unsigned)(ties[t] & 0xFFFFFFFFu);
        int rank = 0;
        for (int j = 0; j < ne; j++) rank += ((unsigned)(ties[j] & 0xFFFFFFFFu) < my_idx);
        tlab[rank] = labels[my_idx];
    }
    __syncthreads();

    if (tid == 0) {
        float cls[NL];
#pragma unroll
        for (int l = 0; l < NL; l++) cls[l] = 0.f;
        float stot = 0.f;
        for (int j = 0; j < ns; j++) { stot += s_w[j]; cls[s_lab[j]] += s_w[j]; }
        int need = KNN - ns;
        float d2T = __uint_as_float(Tkey);
        float wT = (d2T > 0.f) ? __fdiv_rn(1.0f, __fsqrt_rn(d2T)) : 0.f;
        int m = (need < ne) ? need : ne;
        for (int j = 0; j < m; j++) { stot += wT; cls[tlab[j]] += wT; }
#pragma unroll
        for (int l = 0; l < NL; l++) {
            float val = stot - cls[l];
            size_t o = (size_t)b * NL + l;
            if (init) total[o] = val; else total[o] += val;
        }
    }
}

// ---------------------------------------------------------------------------
// Layer-4 select: d2 recomputed inline from t4; writes its OWN tot4 buffer.
// ---------------------------------------------------------------------------
__global__ void __launch_bounds__(SEL_THREADS)
select4_kernel(const float* __restrict__ q4, const float* __restrict__ t4,
               const float* __restrict__ gmin, const int* __restrict__ labels,
               float* __restrict__ tot4)
{
    extern __shared__ __align__(16) char sms[];
    unsigned* hist = (unsigned*)sms;
    u64* cand  = (u64*)(sms + OFF_CAND);
    u64* sel   = (u64*)(sms + OFF_SEL);
    u64* ties  = (u64*)(sms + OFF_TIES);
    int* tlab  = (int*)(sms + OFF_TLAB);
    float* mins = (float*)(sms + OFF_MINS);
    int* tlist = (int*)(sms + OFF_TLIST);

    __shared__ unsigned s_M75, s_bin, s_kthr, s_candcnt, s_selcnt, s_tiecnt, s_ntiles;
    __shared__ float s_w[80];
    __shared__ int s_lab[80];
    __shared__ float s_q[8];

    const int b = blockIdx.x, tid = threadIdx.x, lane = tid & 31;

    if (tid < 8) s_q[tid] = q4[(size_t)b * 8 + tid];
    for (int i = tid; i < NTILES; i += SEL_THREADS)
        mins[i] = gmin[(size_t)b * NTILES + i];
    if (tid == 0) { s_candcnt = 0; s_selcnt = 0; s_tiecnt = 0; s_ntiles = 0; }
    __syncthreads();

    float q[8];
#pragma unroll
    for (int j = 0; j < 8; j++) q[j] = s_q[j];
    const float qq = l4_qq(q);

    if (tid < NTILES) {
        unsigned key = __float_as_uint(mins[tid]);
        int c = 0;
        for (int j = 0; j < NTILES; j++) {
            unsigned kj = __float_as_uint(mins[j]);
            c += (kj < key) || (kj == key && j < tid);
        }
        if (c == KNN - 1) s_M75 = key;
    }
    __syncthreads();
    unsigned Mkey = s_M75;

    if (tid < NTILES) {
        if (__float_as_uint(mins[tid]) <= Mkey) {
            unsigned s = atomicAdd(&s_ntiles, 1u);
            tlist[s] = tid;
        }
    }
    __syncthreads();
    int ntl = (int)s_ntiles;

    for (int w = tid; w < ntl * 128; w += SEL_THREADS) {
        int row = tlist[w >> 7] * 128 + (w & 127);
        if (row < NT) {
            unsigned key = __float_as_uint(l4_d2f(t4 + (size_t)row * 8, q, qq));
            if (key <= Mkey) {
                unsigned s = atomicAdd(&s_candcnt, 1u);
                if (s < SEL_CAP) cand[s] = ((u64)key << 32) | (unsigned)row;
            }
        }
    }
    __syncthreads();

    unsigned candTotal = s_candcnt;
    if (candTotal < KNN) {
        __syncthreads();
        if (tid < NTILES) tlist[tid] = tid;
        if (tid == 0) s_ntiles = NTILES;
        __syncthreads();
        ntl = NTILES;
        Mkey = 0xFFFFFFFFu;
        candTotal = SEL_CAP + 1;
    }

    unsigned Tkey;
    if (candTotal <= SEL_CAP) {
        const int cc = (int)candTotal;
        for (int i = tid; i < 4096; i += SEL_THREADS) hist[i] = 0;
        __syncthreads();
        for (int i = tid; i < cc; i += SEL_THREADS)
            atomicAdd(&hist[(unsigned)(cand[i] >> 52)], 1u);
        __syncthreads();
        find_kth(hist, 4096, KNN, tid, &s_bin, &s_kthr);
        __syncthreads();
        const unsigned pfx = s_bin;
        const unsigned k1v = s_kthr;
        for (int i = tid; i < 4096; i += SEL_THREADS) hist[i] = 0;
        __syncthreads();
        for (int i = tid; i < cc; i += SEL_THREADS) {
            unsigned key = (unsigned)(cand[i] >> 32);
            if ((key >> 20) == pfx) atomicAdd(&hist[(key >> 8) & 0xFFFu], 1u);
        }
        __syncthreads();
        find_kth(hist, 4096, k1v, tid, &s_bin, &s_kthr);
        __syncthreads();
        const unsigned pfx20 = (pfx << 12) | s_bin;
        const unsigned k2v = s_kthr;
        for (int i = tid; i < 256; i += SEL_THREADS) hist[i] = 0;
        __syncthreads();
        for (int i = tid; i < cc; i += SEL_THREADS) {
            unsigned key = (unsigned)(cand[i] >> 32);
            if ((key >> 8) == pfx20) atomicAdd(&hist[key & 0xFFu], 1u);
        }
        __syncthreads();
        find_kth(hist, 256, k2v, tid, &s_bin, &s_kthr);
        __syncthreads();
        Tkey = (pfx20 << 8) | s_bin;
        for (int i = tid; i < cc; i += SEL_THREADS) {
            u64 cv = cand[i];
            unsigned key = (unsigned)(cv >> 32);
            if (key < Tkey) {
                unsigned s = atomicAdd(&s_selcnt, 1u);
                if (s < 128) sel[s] = cv;
            } else if (key == Tkey) {
                unsigned s = atomicAdd(&s_tiecnt, 1u);
                if (s < 128) ties[s] = cv;
            }
        }
        __syncthreads();
    } else {
        for (int i = tid; i < 4096; i += SEL_THREADS) hist[i] = 0;
        __syncthreads();
        for (int w = tid; w < ntl * 128; w += SEL_THREADS) {
            int row = tlist[w >> 7] * 128 + (w & 127);
            unsigned bin = 0xFFFFFFFFu;
            if (row < NT) {
                unsigned key = __float_as_uint(l4_d2f(t4 + (size_t)row * 8, q, qq));
                if (key <= Mkey) bin = key >> 20;
            }
            unsigned grp = __match_any_sync(0xFFFFFFFFu, bin);
            if (bin != 0xFFFFFFFFu && lane == __ffs(grp) - 1)
                atomicAdd(&hist[bin], (unsigned)__popc(grp));
        }
        __syncthreads();
        find_kth(hist, 4096, KNN, tid, &s_bin, &s_kthr);
        __syncthreads();
        const unsigned pfx = s_bin;
        const unsigned k1v = s_kthr;

        for (int i = tid; i < 4096; i += SEL_THREADS) hist[i] = 0;
        __syncthreads();
        for (int w = tid; w < ntl * 128; w += SEL_THREADS) {
            int row = tlist[w >> 7] * 128 + (w & 127);
            unsigned bin = 0xFFFFFFFFu;
            if (row < NT) {
                unsigned key = __float_as_uint(l4_d2f(t4 + (size_t)row * 8, q, qq));
                if (key <= Mkey && (key >> 20) == pfx) bin = (key >> 8) & 0xFFFu;
            }
            unsigned grp = __match_any_sync(0xFFFFFFFFu, bin);
            if (bin != 0xFFFFFFFFu && lane == __ffs(grp) - 1)
                atomicAdd(&hist[bin], (unsigned)__popc(grp));
        }
        __syncthreads();
        find_kth(hist, 4096, k1v, tid, &s_bin, &s_kthr);
        __syncthreads();
        const unsigned pfx20 = (pfx << 12) | s_bin;
        const unsigned k2v = s_kthr;

        for (int i = tid; i < 256; i += SEL_THREADS) hist[i] = 0;
        __syncthreads();
        for (int w = tid; w < ntl * 128; w += SEL_THREADS) {
            int row = tlist[w >> 7] * 128 + (w & 127);
            unsigned bin = 0xFFFFFFFFu;
            if (row < NT) {
                unsigned key = __float_as_uint(l4_d2f(t4 + (size_t)row * 8, q, qq));
                if (key <= Mkey && (key >> 8) == pfx20) bin = key & 0xFFu;
            }
            unsigned grp = __match_any_sync(0xFFFFFFFFu, bin);
            if (bin != 0xFFFFFFFFu && lane == __ffs(grp) - 1)
                atomicAdd(&hist[bin], (unsigned)__popc(grp));
        }
        __syncthreads();
        find_kth(hist, 256, k2v, tid, &s_bin, &s_kthr);
        __syncthreads();
        Tkey = (pfx20 << 8) | s_bin;

        for (int w = tid; w < ntl * 128; w += SEL_THREADS) {
            int row = tlist[w >> 7] * 128 + (w & 127);
            if (row < NT) {
                unsigned key = __float_as_uint(l4_d2f(t4 + (size_t)row * 8, q, qq));
                if (key < Tkey) {
                    unsigned s = atomicAdd(&s_selcnt, 1u);
                    if (s < 128) sel[s] = ((u64)key << 32) | (unsigned)row;
                } else if (key == Tkey) {
                    unsigned s = atomicAdd(&s_tiecnt, 1u);
                    if (s < 128) ties[s] = ((u64)key << 32) | (unsigned)row;
                }
            }
        }
        __syncthreads();
    }

    const int ns = min((int)s_selcnt, 128);
    const int ne = min((int)s_tiecnt, 128);

    if (tid < ns) {
        u64 mine = sel[tid];
        unsigned my_idx = (unsigned)(mine & 0xFFFFFFFFu);
        int rank = 0;
        for (int j = 0; j < ns; j++) rank += ((unsigned)(sel[j] & 0xFFFFFFFFu) < my_idx);
        float d2 = __uint_as_float((unsigned)(mine >> 32));
        s_w[rank] = (d2 > 0.f) ? __fdiv_rn(1.0f, __fsqrt_rn(d2)) : 0.f;
        s_lab[rank] = labels[my_idx];
    }
    if (tid >= 128 && tid - 128 < ne) {
        int t = tid - 128;
        unsigned my_idx = (unsigned)(ties[t] & 0xFFFFFFFFu);
        int rank = 0;
        for (int j = 0; j < ne; j++) rank += ((unsigned)(ties[j] & 0xFFFFFFFFu) < my_idx);
        tlab[rank] = labels[my_idx];
    }
    __syncthreads();

    if (tid == 0) {
        float cls[NL];
#pragma unroll
        for (int l = 0; l < NL; l++) cls[l] = 0.f;
        float stot = 0.f;
        for (int j = 0; j < ns; j++) { stot += s_w[j]; cls[s_lab[j]] += s_w[j]; }
        int need = KNN - ns;
        float d2T = __uint_as_float(Tkey);
        float wT = (d2T > 0.f) ? __fdiv_rn(1.0f, __fsqrt_rn(d2T)) : 0.f;
        int m = (need < ne) ? need : ne;
        for (int j = 0; j < m; j++) { stot += wT; cls[tlab[j]] += wT; }
#pragma unroll
        for (int l = 0; l < NL; l++)
            tot4[(size_t)b * NL + l] = stot - cls[l];
    }
}

// ---------------------------------------------------------------------------
__global__ void __launch_bounds__(256)
pvalue_kernel(const float* __restrict__ total, const float* __restrict__ tot4,
              const float* __restrict__ cali, float* __restrict__ out)
{
    const int b = blockIdx.x, tid = threadIdx.x;
    float t[NL];
#pragma unroll
    for (int l = 0; l < NL; l++)
        t[l] = total[(size_t)b * NL + l] + tot4[(size_t)b * NL + l];
    int cnt[NL];
#pragma unroll
    for (int l = 0; l < NL; l++) cnt[l] = 0;
    for (int i = tid; i < NC; i += 256) {
        float c = cali[i];
#pragma unroll
        for (int l = 0; l < NL; l++) cnt[l] += (c >= t[l]) ? 1 : 0;
    }
    __shared__ int sc[NL];
    if (tid < NL) sc[tid] = 0;
    __syncthreads();
#pragma unroll
    for (int l = 0; l < NL; l++) atomicAdd(&sc[l], cnt[l]);
    __syncthreads();
    if (tid < NL) out[(size_t)b * NL + tid] = (float)sc[tid] * (1.0f / NC);
}

// ---------------------------------------------------------------------------
extern "C" void kernel_launch(void* const* d_in, const int* in_sizes, int n_in,
                              void* d_out, int out_size)
{
    const float* x        = (const float*)d_in[0];
    const float* train_x  = (const float*)d_in[1];
    const int*   lab      = (const int*)  d_in[2];
    const float* cali     = (const float*)d_in[3];
    const float* W1 = (const float*)d_in[4];  const float* b1 = (const float*)d_in[5];
    const float* W2 = (const float*)d_in[6];  const float* b2 = (const float*)d_in[7];
    const float* W3 = (const float*)d_in[8];  const float* b3 = (const float*)d_in[9];
    const float* W4 = (const float*)d_in[10]; const float* b4 = (const float*)d_in[11];
    float* out = (float*)d_out;

    float *q4p, *t3p, *t4p, *d2ap, *d2bp, *totp, *tot4p, *minall, *qnXp, *tnAp, *tnBp;
    __nv_bfloat16 *qhiXp, *qloXp, *thip, *tlop, *thi2p, *tlo2p;
    __nv_bfloat16 *w1th, *w1tl, *w2th, *w2tl, *w3th, *w3tl;
    cudaGetSymbolAddress((void**)&q4p, g_q4);
    cudaGetSymbolAddress((void**)&t3p, g_t3);
    cudaGetSymbolAddress((void**)&t4p, g_t4);
    cudaGetSymbolAddress((void**)&d2ap, g_d2a);
    cudaGetSymbolAddress((void**)&d2bp, g_d2b);
    cudaGetSymbolAddress((void**)&minall, g_minall);
    cudaGetSymbolAddress((void**)&qnXp, g_qnX);
    cudaGetSymbolAddress((void**)&tnAp, g_tnA);
    cudaGetSymbolAddress((void**)&tnBp, g_tnB);
    cudaGetSymbolAddress((void**)&totp, g_tot);
    cudaGetSymbolAddress((void**)&tot4p, g_tot4);
    cudaGetSymbolAddress((void**)&qhiXp, g_qhiX);
    cudaGetSymbolAddress((void**)&qloXp, g_qloX);
    cudaGetSymbolAddress((void**)&thip, g_thi);
    cudaGetSymbolAddress((void**)&tlop, g_tlo);
    cudaGetSymbolAddress((void**)&thi2p, g_thi2);
    cudaGetSymbolAddress((void**)&tlo2p, g_tlo2);
    cudaGetSymbolAddress((void**)&w1th, g_w1th);
    cudaGetSymbolAddress((void**)&w1tl, g_w1tl);
    cudaGetSymbolAddress((void**)&w2th, g_w2th);
    cudaGetSymbolAddress((void**)&w2tl, g_w2tl);
    cudaGetSymbolAddress((void**)&w3th, g_w3th);
    cudaGetSymbolAddress((void**)&w3tl, g_w3tl);

    float* minL[5];
    for (int i = 0; i < 5; i++) minL[i] = minall + (size_t)i * BQ * NTILES;
    __nv_bfloat16* qh[4];
    __nv_bfloat16* ql[4];
    float* qn[4];
    for (int i = 0; i < 4; i++) {
        qh[i] = qhiXp + (size_t)i * BQ * 128;
        ql[i] = qloXp + (size_t)i * BQ * 128;
        qn[i] = qnXp + i * BQ;
    }

    cudaFuncSetAttribute(select_kernel,
                         cudaFuncAttributeMaxDynamicSharedMemorySize, SEL_SMEM);
    cudaFuncSetAttribute(select4_kernel,
                         cudaFuncAttributeMaxDynamicSharedMemorySize, SEL_SMEM);
    cudaFuncSetAttribute(mma_dist_kernel,
                         cudaFuncAttributeMaxDynamicSharedMemorySize, MD_SMEM);
    cudaFuncSetAttribute(fused_qmlp_kernel,
                         cudaFuncAttributeMaxDynamicSharedMemorySize, QMLP_SMEM);

    cudaStream_t s2 = g_ok ? g_s2 : (cudaStream_t)0;
    cudaStream_t s3 = g_ok ? g_s3 : (cudaStream_t)0;
#define REC(ev, st)  do { if (g_ok) cudaEventRecord(g_ev[ev], st); } while (0)
#define WAIT(st, ev) do { if (g_ok) cudaStreamWaitEvent(st, g_ev[ev], 0); } while (0)

    const int D0 = 83;
    const dim3 mgrid(NTILES, BQ / 256);

    // ---- main: prep ----
    conv_norm_kernel<<<BQ / 8, 256>>>(x, qh[0], ql[0], qn[0], BQ, D0);
    conv_norm_kernel<<<NTP / 8, 256>>>(train_x, thip, tlop, tnAp, NT, D0);
    wt_convert_kernel<<<(3 * 128 * 128 + 255) / 256, 256>>>(W1, W2, W3);
    REC(EV_PREP, 0);

    // ---- s3: fused query MLP (banks 1-3 + q4), then train linear L1 ----
    fused_qmlp_kernel<<<BQ / 64, dim3(16, 16), QMLP_SMEM, s3>>>(
        x, W1, b1, W2, b2, W3, b3, W4, b4, qhiXp, qloXp, qnXp, q4p);
    WAIT(s3, EV_PREP);
    mma_linear_kernel<<<NTILES, 256, 0, s3>>>(thip, tlop, w1th, w1tl, b1,
                                              thi2p, tlo2p, tnBp, (float*)0, 6);
    REC(EV_S3A, s3);

    // ---- main: dist L0 ----
    mma_dist_kernel<<<mgrid, 512, MD_SMEM>>>(qh[0], ql[0], thip, tlop, qn[0], tnAp,
                                             d2ap, minL[0], 6);
    REC(EV_D0, 0);

    // ---- s2: select L0 ----
    WAIT(s2, EV_D0);
    select_kernel<<<BQ, SEL_THREADS, SEL_SMEM, s2>>>(d2ap, minL[0], lab, totp, 1);
    REC(EV_J0, s2);

    // ---- main: dist L1 (bank1, tB) ----
    WAIT(0, EV_S3A);
    mma_dist_kernel<<<mgrid, 512, MD_SMEM>>>(qh[1], ql[1], thi2p, tlo2p, qn[1], tnBp,
                                             d2bp, minL[1], 8);
    REC(EV_D1, 0);

    // ---- s2: select L1 ----
    WAIT(s2, EV_D1);
    select_kernel<<<BQ, SEL_THREADS, SEL_SMEM, s2>>>(d2bp, minL[1], lab, totp, 0);
    REC(EV_J1, s2);

    // ---- s3: linear L2 (tB->tA); waits dist L0 (tA/tnA read) ----
    WAIT(s3, EV_D0);
    mma_linear_kernel<<<NTILES, 256, 0, s3>>>(thi2p, tlo2p, w2th, w2tl, b2,
                                              thip, tlop, tnAp, (float*)0, 8);
    REC(EV_S3B, s3);

    // ---- main: dist L2 (bank2, tA; d2A reuse after select L0) ----
    WAIT(0, EV_S3B);
    WAIT(0, EV_J0);
    mma_dist_kernel<<<mgrid, 512, MD_SMEM>>>(qh[2], ql[2], thip, tlop, qn[2], tnAp,
                                             d2ap, minL[2], 8);
    REC(EV_D2, 0);

    // ---- s2: select L2 ----
    WAIT(s2, EV_D2);
    select_kernel<<<BQ, SEL_THREADS, SEL_SMEM, s2>>>(d2ap, minL[2], lab, totp, 0);

    // ---- s3: linear L3 (tA->tB, t3); waits dist L1 (tB read) ----
    WAIT(s3, EV_D1);
    mma_linear_kernel<<<NTILES, 256, 0, s3>>>(thip, tlop, w3th, w3tl, b3,
                                              thi2p, tlo2p, tnBp, t3p, 8);
    REC(EV_S3C, s3);
    // s3 continues: layer-4 chain incl. select4 into its own tot4
    linear_softmax_kernel<<<(NT + 7) / 8, 256, 0, s3>>>(t3p, W4, b4, t4p, NT);
    min4_kernel<<<dim3(NTILES, BQ / 128), 256, 0, s3>>>(q4p, t4p, minL[4]);
    select4_kernel<<<BQ, SEL_THREADS, SEL_SMEM, s3>>>(q4p, t4p, minL[4], lab, tot4p);
    REC(EV_S3D, s3);

    // ---- main: dist L3 (bank3, tB; d2B reuse after select L1) ----
    WAIT(0, EV_S3C);
    WAIT(0, EV_J1);
    mma_dist_kernel<<<mgrid, 512, MD_SMEM>>>(qh[3], ql[3], thi2p, tlo2p, qn[3], tnBp,
                                             d2bp, minL[3], 8);
    REC(EV_D3, 0);

    // ---- s2: select L3 ----
    WAIT(s2, EV_D3);
    select_kernel<<<BQ, SEL_THREADS, SEL_SMEM, s2>>>(d2bp, minL[3], lab, totp, 0);
    REC(EV_J3, s2);

    // ---- main: p-values (tot + tot4, fixed order -> bit-identical) ----
    WAIT(0, EV_J3);
    WAIT(0, EV_S3D);
    pvalue_kernel<<<BQ, 256>>>(totp, tot4p, cali, out);

#undef REC
#undef WAIT
}